// round 3
// baseline (speedup 1.0000x reference)
#include <cuda_runtime.h>
#include <cuda_bf16.h>
#include <math.h>

#define Bb 2
#define Tt 2048
#define Cc 1024
#define Hh 16
#define Dd 64
#define BH (Bb*Hh)      // 32
#define MTOT (Bb*Tt)    // 4096

// Scratch (allocation-free rule: __device__ globals)
__device__ float g_Q[(size_t)BH*Tt*Dd];
__device__ float g_K[(size_t)BH*Tt*Dd];
__device__ float g_V[(size_t)BH*Tt*Dd];
__device__ float g_Y[(size_t)Bb*Tt*Cc];

// ---------------------------------------------------------------------------
// GEMM1: qkv[m][n] = sum_k X[m][k] * Wattn[n][k]; scatter into Q/K/V [B,H,T,D]
// 128x128 tile, BK=16, 256 threads, 8x8 micro-tile.
// ---------------------------------------------------------------------------
__global__ __launch_bounds__(256) void gemm_qkv_kernel(
    const float* __restrict__ X, const float* __restrict__ W)
{
    __shared__ float As[16][132];
    __shared__ float Bs[16][132];
    const int bm = blockIdx.y * 128;
    const int bn = blockIdx.x * 128;
    const int tid = threadIdx.x;
    const int lr = tid >> 1;          // 0..127
    const int lc = (tid & 1) * 8;     // 0 or 8
    const int tx = tid & 15, ty = tid >> 4;
    const int r0 = ty * 8, c0 = tx * 8;

    float acc[8][8] = {};

    const float* xg = X + (size_t)(bm + lr) * Cc + lc;
    const float* wg = W + (size_t)(bn + lr) * Cc + lc;

    for (int k0 = 0; k0 < Cc; k0 += 16) {
        float4 xv0 = *(const float4*)(xg + k0);
        float4 xv1 = *(const float4*)(xg + k0 + 4);
        float4 wv0 = *(const float4*)(wg + k0);
        float4 wv1 = *(const float4*)(wg + k0 + 4);
        __syncthreads();
        As[lc+0][lr]=xv0.x; As[lc+1][lr]=xv0.y; As[lc+2][lr]=xv0.z; As[lc+3][lr]=xv0.w;
        As[lc+4][lr]=xv1.x; As[lc+5][lr]=xv1.y; As[lc+6][lr]=xv1.z; As[lc+7][lr]=xv1.w;
        Bs[lc+0][lr]=wv0.x; Bs[lc+1][lr]=wv0.y; Bs[lc+2][lr]=wv0.z; Bs[lc+3][lr]=wv0.w;
        Bs[lc+4][lr]=wv1.x; Bs[lc+5][lr]=wv1.y; Bs[lc+6][lr]=wv1.z; Bs[lc+7][lr]=wv1.w;
        __syncthreads();
        #pragma unroll
        for (int kk = 0; kk < 16; kk++) {
            float4 a0 = *(const float4*)&As[kk][r0];
            float4 a1 = *(const float4*)&As[kk][r0+4];
            float4 b0 = *(const float4*)&Bs[kk][c0];
            float4 b1 = *(const float4*)&Bs[kk][c0+4];
            float a[8] = {a0.x,a0.y,a0.z,a0.w,a1.x,a1.y,a1.z,a1.w};
            float b[8] = {b0.x,b0.y,b0.z,b0.w,b1.x,b1.y,b1.z,b1.w};
            #pragma unroll
            for (int i = 0; i < 8; i++)
                #pragma unroll
                for (int j = 0; j < 8; j++)
                    acc[i][j] += a[i] * b[j];
        }
    }

    #pragma unroll
    for (int i = 0; i < 8; i++) {
        int m = bm + r0 + i;
        int bb = m >> 11;         // / T
        int t  = m & 2047;
        #pragma unroll
        for (int j0 = 0; j0 < 8; j0 += 4) {
            int n = bn + c0 + j0;
            int which = n >> 10;          // 0=q 1=k 2=v
            int rem = n & 1023;
            int h = rem >> 6, d = rem & 63;
            float* dst = (which == 0) ? g_Q : (which == 1) ? g_K : g_V;
            size_t idx = ((size_t)(bb * Hh + h) * Tt + t) * Dd + d;
            float4 v = make_float4(acc[i][j0], acc[i][j0+1], acc[i][j0+2], acc[i][j0+3]);
            *(float4*)(dst + idx) = v;
        }
    }
}

// ---------------------------------------------------------------------------
// GEMM2: out[m][n] = sum_k Yin[m][k] * Wproj[n][k]  (plain row-major out)
// ---------------------------------------------------------------------------
__global__ __launch_bounds__(256) void gemm_proj_kernel(
    const float* __restrict__ Yin, const float* __restrict__ W, float* __restrict__ out)
{
    __shared__ float As[16][132];
    __shared__ float Bs[16][132];
    const int bm = blockIdx.y * 128;
    const int bn = blockIdx.x * 128;
    const int tid = threadIdx.x;
    const int lr = tid >> 1;
    const int lc = (tid & 1) * 8;
    const int tx = tid & 15, ty = tid >> 4;
    const int r0 = ty * 8, c0 = tx * 8;

    float acc[8][8] = {};

    const float* xg = Yin + (size_t)(bm + lr) * Cc + lc;
    const float* wg = W   + (size_t)(bn + lr) * Cc + lc;

    for (int k0 = 0; k0 < Cc; k0 += 16) {
        float4 xv0 = *(const float4*)(xg + k0);
        float4 xv1 = *(const float4*)(xg + k0 + 4);
        float4 wv0 = *(const float4*)(wg + k0);
        float4 wv1 = *(const float4*)(wg + k0 + 4);
        __syncthreads();
        As[lc+0][lr]=xv0.x; As[lc+1][lr]=xv0.y; As[lc+2][lr]=xv0.z; As[lc+3][lr]=xv0.w;
        As[lc+4][lr]=xv1.x; As[lc+5][lr]=xv1.y; As[lc+6][lr]=xv1.z; As[lc+7][lr]=xv1.w;
        Bs[lc+0][lr]=wv0.x; Bs[lc+1][lr]=wv0.y; Bs[lc+2][lr]=wv0.z; Bs[lc+3][lr]=wv0.w;
        Bs[lc+4][lr]=wv1.x; Bs[lc+5][lr]=wv1.y; Bs[lc+6][lr]=wv1.z; Bs[lc+7][lr]=wv1.w;
        __syncthreads();
        #pragma unroll
        for (int kk = 0; kk < 16; kk++) {
            float4 a0 = *(const float4*)&As[kk][r0];
            float4 a1 = *(const float4*)&As[kk][r0+4];
            float4 b0 = *(const float4*)&Bs[kk][c0];
            float4 b1 = *(const float4*)&Bs[kk][c0+4];
            float a[8] = {a0.x,a0.y,a0.z,a0.w,a1.x,a1.y,a1.z,a1.w};
            float b[8] = {b0.x,b0.y,b0.z,b0.w,b1.x,b1.y,b1.z,b1.w};
            #pragma unroll
            for (int i = 0; i < 8; i++)
                #pragma unroll
                for (int j = 0; j < 8; j++)
                    acc[i][j] += a[i] * b[j];
        }
    }

    #pragma unroll
    for (int i = 0; i < 8; i++) {
        int m = bm + r0 + i;
        #pragma unroll
        for (int j0 = 0; j0 < 8; j0 += 4) {
            float4 v = make_float4(acc[i][j0], acc[i][j0+1], acc[i][j0+2], acc[i][j0+3]);
            *(float4*)(out + (size_t)m * Cc + bn + c0 + j0) = v;
        }
    }
}

// ---------------------------------------------------------------------------
// Attention: sigmoid-penalty causal softmax, streaming K-tiles in DECREASING k
// order so the reverse cumsum becomes a running suffix carry + in-tile scan.
// Block = 64 queries of one (b,h). 256 threads, 4x4 micro-tiles.
// ---------------------------------------------------------------------------
#define SMS 68   // smem row stride (floats), multiple of 4 for float4 alignment

__global__ __launch_bounds__(256) void attn_kernel()
{
    extern __shared__ float sm[];
    float* Qs = sm;                 // [d][q], stride SMS, Q pre-scaled by 1/8
    float* Ks = sm + 64*SMS;        // [d][k]
    float* Vs = sm + 2*64*SMS;      // [k][d]
    float* WS = sm + 3*64*SMS;      // [k][q] exp-weights

    const int qt  = blockIdx.x;     // 0..31
    const int bh  = blockIdx.y;     // 0..31
    const int tid = threadIdx.x;
    const int tx = tid & 15, ty = tid >> 4;
    const int r0 = ty * 4, c0 = tx * 4;
    const int lq = tid & 63, dblk = tid >> 6;   // loader mapping

    // Load Q tile (transposed into [d][q]), scaled by 1/sqrt(D)=0.125
    {
        const float* Qg = g_Q + ((size_t)bh * Tt + (size_t)qt * 64) * Dd;
        #pragma unroll
        for (int i = 0; i < 4; i++) {
            int d = dblk * 16 + i * 4;
            float4 v = *(const float4*)(Qg + lq * Dd + d);
            Qs[(d+0)*SMS + lq] = v.x * 0.125f;
            Qs[(d+1)*SMS + lq] = v.y * 0.125f;
            Qs[(d+2)*SMS + lq] = v.z * 0.125f;
            Qs[(d+3)*SMS + lq] = v.w * 0.125f;
        }
    }

    float acc[4][4] = {};
    float mrow[4], lrow[4], zcarry[4];
    #pragma unroll
    for (int i = 0; i < 4; i++) { mrow[i] = -1e30f; lrow[i] = 0.f; zcarry[i] = 0.f; }

    for (int kt = qt; kt >= 0; --kt) {
        const float* Kg = g_K + ((size_t)bh * Tt + (size_t)kt * 64) * Dd;
        const float* Vg = g_V + ((size_t)bh * Tt + (size_t)kt * 64) * Dd;
        float4 kv[4], vv[4];
        #pragma unroll
        for (int i = 0; i < 4; i++) {
            int d = dblk * 16 + i * 4;
            kv[i] = *(const float4*)(Kg + lq * Dd + d);
            vv[i] = *(const float4*)(Vg + lq * Dd + d);
        }
        __syncthreads();   // previous tile's AV reads (and Q stores on iter 0) done
        #pragma unroll
        for (int i = 0; i < 4; i++) {
            int d = dblk * 16 + i * 4;
            Ks[(d+0)*SMS + lq] = kv[i].x;
            Ks[(d+1)*SMS + lq] = kv[i].y;
            Ks[(d+2)*SMS + lq] = kv[i].z;
            Ks[(d+3)*SMS + lq] = kv[i].w;
            *(float4*)&Vs[lq*SMS + d] = vv[i];
        }
        __syncthreads();

        // P tile: p[i][j] = (q_r0+i . k_c0+j) / 8
        float p[4][4] = {};
        #pragma unroll 16
        for (int dd = 0; dd < 64; dd++) {
            float4 aq = *(const float4*)&Qs[dd*SMS + r0];
            float4 bk = *(const float4*)&Ks[dd*SMS + c0];
            float af[4] = {aq.x, aq.y, aq.z, aq.w};
            float bf[4] = {bk.x, bk.y, bk.z, bk.w};
            #pragma unroll
            for (int i = 0; i < 4; i++)
                #pragma unroll
                for (int j = 0; j < 4; j++)
                    p[i][j] += af[i] * bf[j];
        }

        const bool diag = (kt == qt);
        float s[4][4];
        #pragma unroll
        for (int i = 0; i < 4; i++)
            #pragma unroll
            for (int j = 0; j < 4; j++) {
                bool msk = diag && ((c0 + j) > (r0 + i));
                s[i][j] = msk ? 0.f : __fdividef(1.f, 1.f + __expf(-p[i][j]));
            }

        float w[4][4];
        #pragma unroll
        for (int i = 0; i < 4; i++) {
            // in-thread suffix (inclusive) over 4 cols
            float z3 = s[i][3];
            float z2 = s[i][2] + z3;
            float z1 = s[i][1] + z2;
            float z0 = s[i][0] + z1;
            // cross-lane inclusive suffix over 16 lanes (Hillis-Steele)
            float x = z0;
            #pragma unroll
            for (int o = 1; o < 16; o <<= 1) {
                float y = __shfl_down_sync(0xffffffffu, x, o, 16);
                if (tx + o < 16) x += y;
            }
            float carry_in = x - z0;                                // exclusive
            float rowS = __shfl_sync(0xffffffffu, x, 0, 16);        // full tile row-sum of S
            float zt[4] = {z0, z1, z2, z3};

            float e[4];
            float tmax = -1e30f;
            #pragma unroll
            for (int j = 0; j < 4; j++) {
                bool msk = diag && ((c0 + j) > (r0 + i));
                e[j] = msk ? -1e30f : (p[i][j] - (zcarry[i] + carry_in + zt[j]));
                tmax = fmaxf(tmax, e[j]);
            }
            #pragma unroll
            for (int o = 1; o < 16; o <<= 1)
                tmax = fmaxf(tmax, __shfl_xor_sync(0xffffffffu, tmax, o, 16));

            float mn = fmaxf(mrow[i], tmax);
            float sc = __expf(mrow[i] - mn);
            float ws = 0.f;
            #pragma unroll
            for (int j = 0; j < 4; j++) { w[i][j] = __expf(e[j] - mn); ws += w[i][j]; }
            #pragma unroll
            for (int o = 1; o < 16; o <<= 1)
                ws += __shfl_xor_sync(0xffffffffu, ws, o, 16);

            lrow[i] = lrow[i] * sc + ws;
            mrow[i] = mn;
            #pragma unroll
            for (int j = 0; j < 4; j++) acc[i][j] *= sc;
            zcarry[i] += rowS;
        }

        // exp-weights -> WS[k][q]
        #pragma unroll
        for (int j = 0; j < 4; j++) {
            float4 wv4 = make_float4(w[0][j], w[1][j], w[2][j], w[3][j]);
            *(float4*)&WS[(c0 + j)*SMS + r0] = wv4;
        }
        __syncthreads();

        // acc += W @ V
        #pragma unroll 16
        for (int kj = 0; kj < 64; kj++) {
            float4 aw = *(const float4*)&WS[kj*SMS + r0];
            float4 bv = *(const float4*)&Vs[kj*SMS + c0];
            float af[4] = {aw.x, aw.y, aw.z, aw.w};
            float bf[4] = {bv.x, bv.y, bv.z, bv.w};
            #pragma unroll
            for (int i = 0; i < 4; i++)
                #pragma unroll
                for (int j = 0; j < 4; j++)
                    acc[i][j] += af[i] * bf[j];
        }
    }

    // epilogue: y[b][t][h*64 + d] = acc / l
    const int b = bh >> 4, h = bh & 15;
    #pragma unroll
    for (int i = 0; i < 4; i++) {
        float inv = __fdividef(1.f, lrow[i]);
        int t = qt * 64 + r0 + i;
        float4 o = make_float4(acc[i][0]*inv, acc[i][1]*inv, acc[i][2]*inv, acc[i][3]*inv);
        *(float4*)(g_Y + ((size_t)(b * Tt + t)) * Cc + h * 64 + c0) = o;
    }
}

// ---------------------------------------------------------------------------
extern "C" void kernel_launch(void* const* d_in, const int* in_sizes, int n_in,
                              void* d_out, int out_size)
{
    (void)in_sizes; (void)n_in; (void)out_size;
    const float* x      = (const float*)d_in[0];
    const float* W_attn = (const float*)d_in[1];
    const float* W_proj = (const float*)d_in[2];
    float* out = (float*)d_out;

    static const size_t attn_smem = 4 * 64 * SMS * sizeof(float);  // 69632 B
    cudaFuncSetAttribute(attn_kernel, cudaFuncAttributeMaxDynamicSharedMemorySize,
                         (int)attn_smem);

    float* dQ; cudaGetSymbolAddress((void**)&dQ, g_Q);
    float* dY; cudaGetSymbolAddress((void**)&dY, g_Y);
    (void)dQ;

    gemm_qkv_kernel<<<dim3(3072/128, MTOT/128), 256>>>(x, W_attn);
    attn_kernel<<<dim3(Tt/64, BH), 256, attn_smem>>>();
    gemm_proj_kernel<<<dim3(Cc/128, MTOT/128), 256>>>(dY, W_proj, out);
}

// round 4
// speedup vs baseline: 1.0322x; 1.0322x over previous
#include <cuda_runtime.h>
#include <cuda_bf16.h>
#include <math.h>

#define Bb 2
#define Tt 2048
#define Cc 1024
#define Hh 16
#define Dd 64
#define BH (Bb*Hh)      // 32
#define MTOT (Bb*Tt)    // 4096

typedef unsigned long long u64;

// ---- packed f32x2 helpers (sm_103a FFMA2 path; ptxas won't emit from C++) ----
__device__ __forceinline__ u64 ffma2(u64 a, u64 b, u64 c) {
    u64 d;
    asm("fma.rn.f32x2 %0, %1, %2, %3;" : "=l"(d) : "l"(a), "l"(b), "l"(c));
    return d;
}
__device__ __forceinline__ u64 fmul2(u64 a, u64 b) {
    u64 d;
    asm("mul.rn.f32x2 %0, %1, %2;" : "=l"(d) : "l"(a), "l"(b));
    return d;
}
__device__ __forceinline__ u64 splat2(float x) {
    u64 d; unsigned r = __float_as_uint(x);
    asm("mov.b64 %0, {%1, %1};" : "=l"(d) : "r"(r));
    return d;
}
__device__ __forceinline__ float2 unpack2(u64 v) {
    unsigned lo, hi;
    asm("mov.b64 {%0, %1}, %2;" : "=r"(lo), "=r"(hi) : "l"(v));
    return make_float2(__uint_as_float(lo), __uint_as_float(hi));
}

// Scratch (allocation-free rule: __device__ globals)
__device__ float g_Q[(size_t)BH*Tt*Dd];
__device__ float g_K[(size_t)BH*Tt*Dd];
__device__ float g_V[(size_t)BH*Tt*Dd];
__device__ float g_Y[(size_t)Bb*Tt*Cc];

// ---------------------------------------------------------------------------
// GEMM1: qkv[m][n] = sum_k X[m][k] * Wattn[n][k]; scatter into Q/K/V [B,H,T,D]
// 128x128 tile, BK=16, 256 threads, 8x8 micro-tile, FFMA2 inner loop.
// ---------------------------------------------------------------------------
__global__ __launch_bounds__(256) void gemm_qkv_kernel(
    const float* __restrict__ X, const float* __restrict__ W)
{
    __shared__ float As[16][132];
    __shared__ float Bs[16][132];
    const int bm = blockIdx.y * 128;
    const int bn = blockIdx.x * 128;
    const int tid = threadIdx.x;
    const int lr = tid >> 1;          // 0..127
    const int lc = (tid & 1) * 8;     // 0 or 8
    const int tx = tid & 15, ty = tid >> 4;
    const int r0 = ty * 8, c0 = tx * 8;

    u64 acc2[8][4] = {};   // acc2[i][j] packs (acc[i][2j], acc[i][2j+1])

    const float* xg = X + (size_t)(bm + lr) * Cc + lc;
    const float* wg = W + (size_t)(bn + lr) * Cc + lc;

    for (int k0 = 0; k0 < Cc; k0 += 16) {
        float4 xv0 = *(const float4*)(xg + k0);
        float4 xv1 = *(const float4*)(xg + k0 + 4);
        float4 wv0 = *(const float4*)(wg + k0);
        float4 wv1 = *(const float4*)(wg + k0 + 4);
        __syncthreads();
        As[lc+0][lr]=xv0.x; As[lc+1][lr]=xv0.y; As[lc+2][lr]=xv0.z; As[lc+3][lr]=xv0.w;
        As[lc+4][lr]=xv1.x; As[lc+5][lr]=xv1.y; As[lc+6][lr]=xv1.z; As[lc+7][lr]=xv1.w;
        Bs[lc+0][lr]=wv0.x; Bs[lc+1][lr]=wv0.y; Bs[lc+2][lr]=wv0.z; Bs[lc+3][lr]=wv0.w;
        Bs[lc+4][lr]=wv1.x; Bs[lc+5][lr]=wv1.y; Bs[lc+6][lr]=wv1.z; Bs[lc+7][lr]=wv1.w;
        __syncthreads();
        #pragma unroll
        for (int kk = 0; kk < 16; kk++) {
            float4 a0 = *(const float4*)&As[kk][r0];
            float4 a1 = *(const float4*)&As[kk][r0+4];
            ulonglong2 bq0 = *(const ulonglong2*)&Bs[kk][c0];
            ulonglong2 bq1 = *(const ulonglong2*)&Bs[kk][c0+4];
            u64 b2[4] = {bq0.x, bq0.y, bq1.x, bq1.y};
            float af[8] = {a0.x,a0.y,a0.z,a0.w,a1.x,a1.y,a1.z,a1.w};
            #pragma unroll
            for (int i = 0; i < 8; i++) {
                u64 ai = splat2(af[i]);
                #pragma unroll
                for (int j = 0; j < 4; j++)
                    acc2[i][j] = ffma2(ai, b2[j], acc2[i][j]);
            }
        }
    }

    #pragma unroll
    for (int i = 0; i < 8; i++) {
        int m = bm + r0 + i;
        int bb = m >> 11;         // / T
        int t  = m & 2047;
        #pragma unroll
        for (int j0 = 0; j0 < 2; j0++) {     // two float4 (= ulonglong2) stores
            int n = bn + c0 + j0 * 4;
            int which = n >> 10;              // 0=q 1=k 2=v
            int rem = n & 1023;
            int h = rem >> 6, d = rem & 63;
            float* dst = (which == 0) ? g_Q : (which == 1) ? g_K : g_V;
            size_t idx = ((size_t)(bb * Hh + h) * Tt + t) * Dd + d;
            ulonglong2 v;
            v.x = acc2[i][j0*2+0];
            v.y = acc2[i][j0*2+1];
            *(ulonglong2*)(dst + idx) = v;
        }
    }
}

// ---------------------------------------------------------------------------
// GEMM2: out[m][n] = sum_k Yin[m][k] * Wproj[n][k]  (plain row-major out)
// ---------------------------------------------------------------------------
__global__ __launch_bounds__(256) void gemm_proj_kernel(
    const float* __restrict__ Yin, const float* __restrict__ W, float* __restrict__ out)
{
    __shared__ float As[16][132];
    __shared__ float Bs[16][132];
    const int bm = blockIdx.y * 128;
    const int bn = blockIdx.x * 128;
    const int tid = threadIdx.x;
    const int lr = tid >> 1;
    const int lc = (tid & 1) * 8;
    const int tx = tid & 15, ty = tid >> 4;
    const int r0 = ty * 8, c0 = tx * 8;

    u64 acc2[8][4] = {};

    const float* xg = Yin + (size_t)(bm + lr) * Cc + lc;
    const float* wg = W   + (size_t)(bn + lr) * Cc + lc;

    for (int k0 = 0; k0 < Cc; k0 += 16) {
        float4 xv0 = *(const float4*)(xg + k0);
        float4 xv1 = *(const float4*)(xg + k0 + 4);
        float4 wv0 = *(const float4*)(wg + k0);
        float4 wv1 = *(const float4*)(wg + k0 + 4);
        __syncthreads();
        As[lc+0][lr]=xv0.x; As[lc+1][lr]=xv0.y; As[lc+2][lr]=xv0.z; As[lc+3][lr]=xv0.w;
        As[lc+4][lr]=xv1.x; As[lc+5][lr]=xv1.y; As[lc+6][lr]=xv1.z; As[lc+7][lr]=xv1.w;
        Bs[lc+0][lr]=wv0.x; Bs[lc+1][lr]=wv0.y; Bs[lc+2][lr]=wv0.z; Bs[lc+3][lr]=wv0.w;
        Bs[lc+4][lr]=wv1.x; Bs[lc+5][lr]=wv1.y; Bs[lc+6][lr]=wv1.z; Bs[lc+7][lr]=wv1.w;
        __syncthreads();
        #pragma unroll
        for (int kk = 0; kk < 16; kk++) {
            float4 a0 = *(const float4*)&As[kk][r0];
            float4 a1 = *(const float4*)&As[kk][r0+4];
            ulonglong2 bq0 = *(const ulonglong2*)&Bs[kk][c0];
            ulonglong2 bq1 = *(const ulonglong2*)&Bs[kk][c0+4];
            u64 b2[4] = {bq0.x, bq0.y, bq1.x, bq1.y};
            float af[8] = {a0.x,a0.y,a0.z,a0.w,a1.x,a1.y,a1.z,a1.w};
            #pragma unroll
            for (int i = 0; i < 8; i++) {
                u64 ai = splat2(af[i]);
                #pragma unroll
                for (int j = 0; j < 4; j++)
                    acc2[i][j] = ffma2(ai, b2[j], acc2[i][j]);
            }
        }
    }

    #pragma unroll
    for (int i = 0; i < 8; i++) {
        int m = bm + r0 + i;
        #pragma unroll
        for (int j0 = 0; j0 < 2; j0++) {
            ulonglong2 v;
            v.x = acc2[i][j0*2+0];
            v.y = acc2[i][j0*2+1];
            *(ulonglong2*)(out + (size_t)m * Cc + bn + c0 + j0*4) = v;
        }
    }
}

// ---------------------------------------------------------------------------
// Attention: sigmoid-penalty causal softmax, streaming K-tiles in DECREASING k
// order so the reverse cumsum becomes a running suffix carry + in-tile scan.
// Block = 64 queries of one (b,h). 256 threads, 4x4 micro-tiles, FFMA2 GEMMs.
// ---------------------------------------------------------------------------
#define SMS 68   // smem row stride (floats); 272B rows -> 16B aligned

__global__ __launch_bounds__(256) void attn_kernel()
{
    extern __shared__ float sm[];
    float* Qs = sm;                 // [d][q], stride SMS, Q pre-scaled by 1/8
    float* Ks = sm + 64*SMS;        // [d][k]
    float* Vs = sm + 2*64*SMS;      // [k][d]
    float* WS = sm + 3*64*SMS;      // [k][q] exp-weights

    const int qt  = blockIdx.x;     // 0..31
    const int bh  = blockIdx.y;     // 0..31
    const int tid = threadIdx.x;
    const int tx = tid & 15, ty = tid >> 4;
    const int r0 = ty * 4, c0 = tx * 4;
    const int lq = tid & 63, dblk = tid >> 6;   // loader mapping

    // Load Q tile (transposed into [d][q]), scaled by 1/sqrt(D)=0.125
    {
        const float* Qg = g_Q + ((size_t)bh * Tt + (size_t)qt * 64) * Dd;
        #pragma unroll
        for (int i = 0; i < 4; i++) {
            int d = dblk * 16 + i * 4;
            float4 v = *(const float4*)(Qg + lq * Dd + d);
            Qs[(d+0)*SMS + lq] = v.x * 0.125f;
            Qs[(d+1)*SMS + lq] = v.y * 0.125f;
            Qs[(d+2)*SMS + lq] = v.z * 0.125f;
            Qs[(d+3)*SMS + lq] = v.w * 0.125f;
        }
    }

    u64 acc2[4][2] = {};            // packed output accumulator (j pairs)
    float mrow[4], lrow[4], zcarry[4];
    #pragma unroll
    for (int i = 0; i < 4; i++) { mrow[i] = -1e30f; lrow[i] = 0.f; zcarry[i] = 0.f; }

    for (int kt = qt; kt >= 0; --kt) {
        const float* Kg = g_K + ((size_t)bh * Tt + (size_t)kt * 64) * Dd;
        const float* Vg = g_V + ((size_t)bh * Tt + (size_t)kt * 64) * Dd;
        float4 kv[4], vv[4];
        #pragma unroll
        for (int i = 0; i < 4; i++) {
            int d = dblk * 16 + i * 4;
            kv[i] = *(const float4*)(Kg + lq * Dd + d);
            vv[i] = *(const float4*)(Vg + lq * Dd + d);
        }
        __syncthreads();   // previous tile's AV reads (and Q stores on iter 0) done
        #pragma unroll
        for (int i = 0; i < 4; i++) {
            int d = dblk * 16 + i * 4;
            Ks[(d+0)*SMS + lq] = kv[i].x;
            Ks[(d+1)*SMS + lq] = kv[i].y;
            Ks[(d+2)*SMS + lq] = kv[i].z;
            Ks[(d+3)*SMS + lq] = kv[i].w;
            *(float4*)&Vs[lq*SMS + d] = vv[i];
        }
        __syncthreads();

        // P tile: p[i][j] = (q_r0+i . k_c0+j) / 8   (FFMA2 packed over j pairs)
        u64 p2[4][2] = {};
        #pragma unroll 16
        for (int dd = 0; dd < 64; dd++) {
            float4 aq = *(const float4*)&Qs[dd*SMS + r0];
            ulonglong2 bk = *(const ulonglong2*)&Ks[dd*SMS + c0];
            float af[4] = {aq.x, aq.y, aq.z, aq.w};
            #pragma unroll
            for (int i = 0; i < 4; i++) {
                u64 ai = splat2(af[i]);
                p2[i][0] = ffma2(ai, bk.x, p2[i][0]);
                p2[i][1] = ffma2(ai, bk.y, p2[i][1]);
            }
        }
        float p[4][4];
        #pragma unroll
        for (int i = 0; i < 4; i++) {
            float2 pa = unpack2(p2[i][0]);
            float2 pb = unpack2(p2[i][1]);
            p[i][0] = pa.x; p[i][1] = pa.y; p[i][2] = pb.x; p[i][3] = pb.y;
        }

        const bool diag = (kt == qt);
        float s[4][4];
        #pragma unroll
        for (int i = 0; i < 4; i++)
            #pragma unroll
            for (int j = 0; j < 4; j++) {
                bool msk = diag && ((c0 + j) > (r0 + i));
                s[i][j] = msk ? 0.f : __fdividef(1.f, 1.f + __expf(-p[i][j]));
            }

        float w[4][4];
        #pragma unroll
        for (int i = 0; i < 4; i++) {
            // in-thread suffix (inclusive) over 4 cols
            float z3 = s[i][3];
            float z2 = s[i][2] + z3;
            float z1 = s[i][1] + z2;
            float z0 = s[i][0] + z1;
            // cross-lane inclusive suffix over 16 lanes (Hillis-Steele)
            float x = z0;
            #pragma unroll
            for (int o = 1; o < 16; o <<= 1) {
                float y = __shfl_down_sync(0xffffffffu, x, o, 16);
                if (tx + o < 16) x += y;
            }
            float carry_in = x - z0;                                // exclusive
            float rowS = __shfl_sync(0xffffffffu, x, 0, 16);        // full tile row-sum of S
            float zt[4] = {z0, z1, z2, z3};

            float e[4];
            float tmax = -1e30f;
            #pragma unroll
            for (int j = 0; j < 4; j++) {
                bool msk = diag && ((c0 + j) > (r0 + i));
                e[j] = msk ? -1e30f : (p[i][j] - (zcarry[i] + carry_in + zt[j]));
                tmax = fmaxf(tmax, e[j]);
            }
            #pragma unroll
            for (int o = 1; o < 16; o <<= 1)
                tmax = fmaxf(tmax, __shfl_xor_sync(0xffffffffu, tmax, o, 16));

            float mn = fmaxf(mrow[i], tmax);
            float sc = __expf(mrow[i] - mn);
            float ws = 0.f;
            #pragma unroll
            for (int j = 0; j < 4; j++) { w[i][j] = __expf(e[j] - mn); ws += w[i][j]; }
            #pragma unroll
            for (int o = 1; o < 16; o <<= 1)
                ws += __shfl_xor_sync(0xffffffffu, ws, o, 16);

            lrow[i] = lrow[i] * sc + ws;
            mrow[i] = mn;
            u64 sc2 = splat2(sc);
            acc2[i][0] = fmul2(acc2[i][0], sc2);
            acc2[i][1] = fmul2(acc2[i][1], sc2);
            zcarry[i] += rowS;
        }

        // exp-weights -> WS[k][q]
        #pragma unroll
        for (int j = 0; j < 4; j++) {
            float4 wv4 = make_float4(w[0][j], w[1][j], w[2][j], w[3][j]);
            *(float4*)&WS[(c0 + j)*SMS + r0] = wv4;
        }
        __syncthreads();

        // acc += W @ V   (FFMA2 packed over d pairs)
        #pragma unroll 16
        for (int kj = 0; kj < 64; kj++) {
            float4 aw = *(const float4*)&WS[kj*SMS + r0];
            ulonglong2 bv = *(const ulonglong2*)&Vs[kj*SMS + c0];
            float af[4] = {aw.x, aw.y, aw.z, aw.w};
            #pragma unroll
            for (int i = 0; i < 4; i++) {
                u64 ai = splat2(af[i]);
                acc2[i][0] = ffma2(ai, bv.x, acc2[i][0]);
                acc2[i][1] = ffma2(ai, bv.y, acc2[i][1]);
            }
        }
    }

    // epilogue: y[b][t][h*64 + d] = acc / l
    const int b = bh >> 4, h = bh & 15;
    #pragma unroll
    for (int i = 0; i < 4; i++) {
        float inv = __fdividef(1.f, lrow[i]);
        u64 inv2 = splat2(inv);
        int t = qt * 64 + r0 + i;
        ulonglong2 o;
        o.x = fmul2(acc2[i][0], inv2);
        o.y = fmul2(acc2[i][1], inv2);
        *(ulonglong2*)(g_Y + ((size_t)(b * Tt + t)) * Cc + h * 64 + c0) = o;
    }
}

// ---------------------------------------------------------------------------
extern "C" void kernel_launch(void* const* d_in, const int* in_sizes, int n_in,
                              void* d_out, int out_size)
{
    (void)in_sizes; (void)n_in; (void)out_size;
    const float* x      = (const float*)d_in[0];
    const float* W_attn = (const float*)d_in[1];
    const float* W_proj = (const float*)d_in[2];
    float* out = (float*)d_out;

    static const size_t attn_smem = 4 * 64 * SMS * sizeof(float);  // 69632 B
    cudaFuncSetAttribute(attn_kernel, cudaFuncAttributeMaxDynamicSharedMemorySize,
                         (int)attn_smem);

    float* dY; cudaGetSymbolAddress((void**)&dY, g_Y);

    gemm_qkv_kernel<<<dim3(3072/128, MTOT/128), 256>>>(x, W_attn);
    attn_kernel<<<dim3(Tt/64, BH), 256, attn_smem>>>();
    gemm_proj_kernel<<<dim3(Cc/128, MTOT/128), 256>>>(dY, W_proj, out);
}

// round 6
// speedup vs baseline: 1.1722x; 1.1356x over previous
#include <cuda_runtime.h>
#include <cuda_bf16.h>
#include <math.h>
#include <cstdint>

#define Bb 2
#define Tt 2048
#define Cc 1024
#define Hh 16
#define Dd 64
#define BH (Bb*Hh)      // 32
#define MTOT (Bb*Tt)    // 4096

typedef unsigned long long u64;

// ---- packed f32x2 helpers (attention kernel) ----
__device__ __forceinline__ u64 ffma2(u64 a, u64 b, u64 c) {
    u64 d;
    asm("fma.rn.f32x2 %0, %1, %2, %3;" : "=l"(d) : "l"(a), "l"(b), "l"(c));
    return d;
}
__device__ __forceinline__ u64 fmul2(u64 a, u64 b) {
    u64 d;
    asm("mul.rn.f32x2 %0, %1, %2;" : "=l"(d) : "l"(a), "l"(b));
    return d;
}
__device__ __forceinline__ u64 splat2(float x) {
    u64 d; unsigned r = __float_as_uint(x);
    asm("mov.b64 %0, {%1, %1};" : "=l"(d) : "r"(r));
    return d;
}
__device__ __forceinline__ float2 unpack2(u64 v) {
    unsigned lo, hi;
    asm("mov.b64 {%0, %1}, %2;" : "=r"(lo), "=r"(hi) : "l"(v));
    return make_float2(__uint_as_float(lo), __uint_as_float(hi));
}

// Scratch (allocation-free rule: __device__ globals)
__device__ float g_Q[(size_t)BH*Tt*Dd];
__device__ float g_K[(size_t)BH*Tt*Dd];
__device__ float g_V[(size_t)BH*Tt*Dd];
__device__ float g_Y[(size_t)Bb*Tt*Cc];

// ===========================================================================
// 3xTF32 mma.sync GEMM: D[m][n] = sum_k A[m][k] * W[n][k]
// CTA 128x128, BK=32, 256 threads, 8 warps (warp tile 64x32), double-buffered.
// mma.sync.m16n8k8 is baseline PTX (sm_80+) -> compiles for plain sm_103.
// ===========================================================================

__device__ __forceinline__ float tf32r(float a) {
    uint32_t r; asm("cvt.rna.tf32.f32 %0, %1;" : "=r"(r) : "f"(a));
    return __uint_as_float(r);
}

__device__ __forceinline__ void mma8(float c[4],
    uint32_t a0, uint32_t a1, uint32_t a2, uint32_t a3,
    uint32_t b0, uint32_t b1)
{
    asm volatile(
        "mma.sync.aligned.m16n8k8.row.col.f32.tf32.tf32.f32 "
        "{%0,%1,%2,%3}, {%4,%5,%6,%7}, {%8,%9}, {%0,%1,%2,%3};"
        : "+f"(c[0]), "+f"(c[1]), "+f"(c[2]), "+f"(c[3])
        : "r"(a0), "r"(a1), "r"(a2), "r"(a3), "r"(b0), "r"(b1));
}

#define STR 34                 // smem row stride in floats (136B: STS.64 phase-conflict-free)
#define PIECE (128*STR)        // one 128x32(+pad) matrix piece, floats
#define STAGE (4*PIECE)        // Ahi | Alo | Bhi | Blo
#define GSMEM_BYTES (2*STAGE*4)   // 139264 B

template<bool SCATTER>
__global__ __launch_bounds__(256) void gemm_mma_kernel(
    const float* __restrict__ Ain, const float* __restrict__ Win,
    float* __restrict__ outp)
{
    extern __shared__ float sf[];
    const int tid = threadIdx.x;
    const int wid = tid >> 5, lid = tid & 31;
    const int g = lid >> 2, t4 = lid & 3;
    const int wm = wid & 1, wn = wid >> 1;          // warp tile: 64 (m) x 32 (n)
    const int bm = blockIdx.y * 128;
    const int bn = blockIdx.x * 128;

    const float* gA = Ain + (size_t)bm * Cc;
    const float* gB = Win + (size_t)bn * Cc;

    float acc[4][4][4];
    #pragma unroll
    for (int i = 0; i < 4; i++)
        #pragma unroll
        for (int j = 0; j < 4; j++)
            #pragma unroll
            for (int r = 0; r < 4; r++) acc[i][j][r] = 0.f;

    float4 ra[4], rb[4];
    int ldrow[4], ldc4[4];
    #pragma unroll
    for (int t = 0; t < 4; t++) {
        int idx = tid + t * 256;   // 0..1023
        ldrow[t] = idx >> 3;       // 0..127
        ldc4[t]  = idx & 7;        // float4 index within 32-float row
    }

    // ---- fetch chunk kc into registers ----
    auto fetch = [&](int kc) {
        #pragma unroll
        for (int t = 0; t < 4; t++) {
            const size_t off = (size_t)ldrow[t] * Cc + kc * 32 + ldc4[t] * 4;
            ra[t] = *(const float4*)(gA + off);
            rb[t] = *(const float4*)(gB + off);
        }
    };
    // ---- split + store registers into stage s ----
    auto stos = [&](int s) {
        float* base = sf + s * STAGE;
        #pragma unroll
        for (int t = 0; t < 4; t++) {
            const int o = ldrow[t] * STR + ldc4[t] * 4;
            float hx = tf32r(ra[t].x), hy = tf32r(ra[t].y);
            float hz = tf32r(ra[t].z), hw = tf32r(ra[t].w);
            *(float2*)(base + o)     = make_float2(hx, hy);
            *(float2*)(base + o + 2) = make_float2(hz, hw);
            *(float2*)(base + PIECE + o)     = make_float2(tf32r(ra[t].x - hx), tf32r(ra[t].y - hy));
            *(float2*)(base + PIECE + o + 2) = make_float2(tf32r(ra[t].z - hz), tf32r(ra[t].w - hw));
            hx = tf32r(rb[t].x); hy = tf32r(rb[t].y);
            hz = tf32r(rb[t].z); hw = tf32r(rb[t].w);
            *(float2*)(base + 2*PIECE + o)     = make_float2(hx, hy);
            *(float2*)(base + 2*PIECE + o + 2) = make_float2(hz, hw);
            *(float2*)(base + 3*PIECE + o)     = make_float2(tf32r(rb[t].x - hx), tf32r(rb[t].y - hy));
            *(float2*)(base + 3*PIECE + o + 2) = make_float2(tf32r(rb[t].z - hz), tf32r(rb[t].w - hw));
        }
    };

    fetch(0); stos(0);
    __syncthreads();

    #pragma unroll 1
    for (int kc = 0; kc < 32; kc++) {
        if (kc < 31) fetch(kc + 1);     // LDG latency hides under HMMA below

        const float* sA = sf + (kc & 1) * STAGE;
        #pragma unroll
        for (int ks = 0; ks < 4; ks++) {
            uint32_t ah[4][4], al[4][4], bh[4][2], bl[4][2];
            #pragma unroll
            for (int mt = 0; mt < 4; mt++) {
                const float* p = sA + (wm*64 + mt*16 + g) * STR + ks*8 + t4;
                ah[mt][0] = __float_as_uint(p[0]);
                ah[mt][1] = __float_as_uint(p[8*STR]);
                ah[mt][2] = __float_as_uint(p[4]);
                ah[mt][3] = __float_as_uint(p[8*STR + 4]);
                const float* q = p + PIECE;
                al[mt][0] = __float_as_uint(q[0]);
                al[mt][1] = __float_as_uint(q[8*STR]);
                al[mt][2] = __float_as_uint(q[4]);
                al[mt][3] = __float_as_uint(q[8*STR + 4]);
            }
            #pragma unroll
            for (int nt = 0; nt < 4; nt++) {
                const float* p = sA + 2*PIECE + (wn*32 + nt*8 + g) * STR + ks*8 + t4;
                bh[nt][0] = __float_as_uint(p[0]);
                bh[nt][1] = __float_as_uint(p[4]);
                const float* q = p + PIECE;
                bl[nt][0] = __float_as_uint(q[0]);
                bl[nt][1] = __float_as_uint(q[4]);
            }
            #pragma unroll
            for (int mt = 0; mt < 4; mt++)
                #pragma unroll
                for (int nt = 0; nt < 4; nt++) {
                    mma8(acc[mt][nt], ah[mt][0], ah[mt][1], ah[mt][2], ah[mt][3],
                         bh[nt][0], bh[nt][1]);
                    mma8(acc[mt][nt], ah[mt][0], ah[mt][1], ah[mt][2], ah[mt][3],
                         bl[nt][0], bl[nt][1]);
                    mma8(acc[mt][nt], al[mt][0], al[mt][1], al[mt][2], al[mt][3],
                         bh[nt][0], bh[nt][1]);
                }
        }

        if (kc < 31) stos((kc + 1) & 1);
        __syncthreads();
    }

    // ---- epilogue: c0:(g,2t4) c1:(g,2t4+1) c2:(g+8,2t4) c3:(g+8,2t4+1) ----
    #pragma unroll
    for (int mt = 0; mt < 4; mt++) {
        #pragma unroll
        for (int nt = 0; nt < 4; nt++) {
            int m0 = bm + wm*64 + mt*16 + g;
            int n  = bn + wn*32 + nt*8 + 2*t4;
            if (SCATTER) {
                int which = n >> 10;           // 0=q 1=k 2=v
                int rem = n & 1023;
                int h = rem >> 6, d = rem & 63;
                float* dst = (which == 0) ? g_Q : (which == 1) ? g_K : g_V;
                int bb0 = m0 >> 11, t0 = m0 & 2047;
                *(float2*)(dst + ((size_t)(bb0*Hh + h)*Tt + t0)*Dd + d) =
                    make_float2(acc[mt][nt][0], acc[mt][nt][1]);
                int m1 = m0 + 8;
                int bb1 = m1 >> 11, t1 = m1 & 2047;
                *(float2*)(dst + ((size_t)(bb1*Hh + h)*Tt + t1)*Dd + d) =
                    make_float2(acc[mt][nt][2], acc[mt][nt][3]);
            } else {
                *(float2*)(outp + (size_t)m0 * Cc + n) =
                    make_float2(acc[mt][nt][0], acc[mt][nt][1]);
                *(float2*)(outp + (size_t)(m0 + 8) * Cc + n) =
                    make_float2(acc[mt][nt][2], acc[mt][nt][3]);
            }
        }
    }
}

// ---------------------------------------------------------------------------
// Attention: sigmoid-penalty causal softmax (FFMA2 version, unchanged)
// ---------------------------------------------------------------------------
#define SMS 68

__global__ __launch_bounds__(256) void attn_kernel()
{
    extern __shared__ float sm[];
    float* Qs = sm;
    float* Ks = sm + 64*SMS;
    float* Vs = sm + 2*64*SMS;
    float* WS = sm + 3*64*SMS;

    const int qt  = blockIdx.x;
    const int bh  = blockIdx.y;
    const int tid = threadIdx.x;
    const int tx = tid & 15, ty = tid >> 4;
    const int r0 = ty * 4, c0 = tx * 4;
    const int lq = tid & 63, dblk = tid >> 6;

    {
        const float* Qg = g_Q + ((size_t)bh * Tt + (size_t)qt * 64) * Dd;
        #pragma unroll
        for (int i = 0; i < 4; i++) {
            int d = dblk * 16 + i * 4;
            float4 v = *(const float4*)(Qg + lq * Dd + d);
            Qs[(d+0)*SMS + lq] = v.x * 0.125f;
            Qs[(d+1)*SMS + lq] = v.y * 0.125f;
            Qs[(d+2)*SMS + lq] = v.z * 0.125f;
            Qs[(d+3)*SMS + lq] = v.w * 0.125f;
        }
    }

    u64 acc2[4][2] = {};
    float mrow[4], lrow[4], zcarry[4];
    #pragma unroll
    for (int i = 0; i < 4; i++) { mrow[i] = -1e30f; lrow[i] = 0.f; zcarry[i] = 0.f; }

    for (int kt = qt; kt >= 0; --kt) {
        const float* Kg = g_K + ((size_t)bh * Tt + (size_t)kt * 64) * Dd;
        const float* Vg = g_V + ((size_t)bh * Tt + (size_t)kt * 64) * Dd;
        float4 kv[4], vv[4];
        #pragma unroll
        for (int i = 0; i < 4; i++) {
            int d = dblk * 16 + i * 4;
            kv[i] = *(const float4*)(Kg + lq * Dd + d);
            vv[i] = *(const float4*)(Vg + lq * Dd + d);
        }
        __syncthreads();
        #pragma unroll
        for (int i = 0; i < 4; i++) {
            int d = dblk * 16 + i * 4;
            Ks[(d+0)*SMS + lq] = kv[i].x;
            Ks[(d+1)*SMS + lq] = kv[i].y;
            Ks[(d+2)*SMS + lq] = kv[i].z;
            Ks[(d+3)*SMS + lq] = kv[i].w;
            *(float4*)&Vs[lq*SMS + d] = vv[i];
        }
        __syncthreads();

        u64 p2[4][2] = {};
        #pragma unroll 16
        for (int dd = 0; dd < 64; dd++) {
            float4 aq = *(const float4*)&Qs[dd*SMS + r0];
            ulonglong2 bk = *(const ulonglong2*)&Ks[dd*SMS + c0];
            float af[4] = {aq.x, aq.y, aq.z, aq.w};
            #pragma unroll
            for (int i = 0; i < 4; i++) {
                u64 ai = splat2(af[i]);
                p2[i][0] = ffma2(ai, bk.x, p2[i][0]);
                p2[i][1] = ffma2(ai, bk.y, p2[i][1]);
            }
        }
        float p[4][4];
        #pragma unroll
        for (int i = 0; i < 4; i++) {
            float2 pa = unpack2(p2[i][0]);
            float2 pb = unpack2(p2[i][1]);
            p[i][0] = pa.x; p[i][1] = pa.y; p[i][2] = pb.x; p[i][3] = pb.y;
        }

        const bool diag = (kt == qt);
        float s[4][4];
        #pragma unroll
        for (int i = 0; i < 4; i++)
            #pragma unroll
            for (int j = 0; j < 4; j++) {
                bool msk = diag && ((c0 + j) > (r0 + i));
                s[i][j] = msk ? 0.f : __fdividef(1.f, 1.f + __expf(-p[i][j]));
            }

        float w[4][4];
        #pragma unroll
        for (int i = 0; i < 4; i++) {
            float z3 = s[i][3];
            float z2 = s[i][2] + z3;
            float z1 = s[i][1] + z2;
            float z0 = s[i][0] + z1;
            float x = z0;
            #pragma unroll
            for (int o = 1; o < 16; o <<= 1) {
                float y = __shfl_down_sync(0xffffffffu, x, o, 16);
                if (tx + o < 16) x += y;
            }
            float carry_in = x - z0;
            float rowS = __shfl_sync(0xffffffffu, x, 0, 16);
            float zt[4] = {z0, z1, z2, z3};

            float e[4];
            float tmax = -1e30f;
            #pragma unroll
            for (int j = 0; j < 4; j++) {
                bool msk = diag && ((c0 + j) > (r0 + i));
                e[j] = msk ? -1e30f : (p[i][j] - (zcarry[i] + carry_in + zt[j]));
                tmax = fmaxf(tmax, e[j]);
            }
            #pragma unroll
            for (int o = 1; o < 16; o <<= 1)
                tmax = fmaxf(tmax, __shfl_xor_sync(0xffffffffu, tmax, o, 16));

            float mn = fmaxf(mrow[i], tmax);
            float sc = __expf(mrow[i] - mn);
            float ws = 0.f;
            #pragma unroll
            for (int j = 0; j < 4; j++) { w[i][j] = __expf(e[j] - mn); ws += w[i][j]; }
            #pragma unroll
            for (int o = 1; o < 16; o <<= 1)
                ws += __shfl_xor_sync(0xffffffffu, ws, o, 16);

            lrow[i] = lrow[i] * sc + ws;
            mrow[i] = mn;
            u64 sc2 = splat2(sc);
            acc2[i][0] = fmul2(acc2[i][0], sc2);
            acc2[i][1] = fmul2(acc2[i][1], sc2);
            zcarry[i] += rowS;
        }

        #pragma unroll
        for (int j = 0; j < 4; j++) {
            float4 wv4 = make_float4(w[0][j], w[1][j], w[2][j], w[3][j]);
            *(float4*)&WS[(c0 + j)*SMS + r0] = wv4;
        }
        __syncthreads();

        #pragma unroll 16
        for (int kj = 0; kj < 64; kj++) {
            float4 aw = *(const float4*)&WS[kj*SMS + r0];
            ulonglong2 bv = *(const ulonglong2*)&Vs[kj*SMS + c0];
            float af[4] = {aw.x, aw.y, aw.z, aw.w};
            #pragma unroll
            for (int i = 0; i < 4; i++) {
                u64 ai = splat2(af[i]);
                acc2[i][0] = ffma2(ai, bv.x, acc2[i][0]);
                acc2[i][1] = ffma2(ai, bv.y, acc2[i][1]);
            }
        }
    }

    const int b = bh >> 4, h = bh & 15;
    #pragma unroll
    for (int i = 0; i < 4; i++) {
        float inv = __fdividef(1.f, lrow[i]);
        u64 inv2 = splat2(inv);
        int t = qt * 64 + r0 + i;
        ulonglong2 o;
        o.x = fmul2(acc2[i][0], inv2);
        o.y = fmul2(acc2[i][1], inv2);
        *(ulonglong2*)(g_Y + ((size_t)(b * Tt + t)) * Cc + h * 64 + c0) = o;
    }
}

// ---------------------------------------------------------------------------
extern "C" void kernel_launch(void* const* d_in, const int* in_sizes, int n_in,
                              void* d_out, int out_size)
{
    (void)in_sizes; (void)n_in; (void)out_size;
    const float* x      = (const float*)d_in[0];
    const float* W_attn = (const float*)d_in[1];
    const float* W_proj = (const float*)d_in[2];
    float* out = (float*)d_out;

    static const size_t attn_smem = 4 * 64 * SMS * sizeof(float);
    cudaFuncSetAttribute(attn_kernel, cudaFuncAttributeMaxDynamicSharedMemorySize,
                         (int)attn_smem);
    cudaFuncSetAttribute(gemm_mma_kernel<true>,
                         cudaFuncAttributeMaxDynamicSharedMemorySize, GSMEM_BYTES);
    cudaFuncSetAttribute(gemm_mma_kernel<false>,
                         cudaFuncAttributeMaxDynamicSharedMemorySize, GSMEM_BYTES);

    float* dY; cudaGetSymbolAddress((void**)&dY, g_Y);

    gemm_mma_kernel<true><<<dim3(3072/128, MTOT/128), 256, GSMEM_BYTES>>>(x, W_attn, nullptr);
    attn_kernel<<<dim3(Tt/64, BH), 256, attn_smem>>>();
    gemm_mma_kernel<false><<<dim3(Cc/128, MTOT/128), 256, GSMEM_BYTES>>>(dY, W_proj, out);
}

// round 7
// speedup vs baseline: 1.5051x; 1.2840x over previous
#include <cuda_runtime.h>
#include <cuda_bf16.h>
#include <math.h>
#include <cstdint>

#define Bb 2
#define Tt 2048
#define Cc 1024
#define Hh 16
#define Dd 64
#define BH (Bb*Hh)      // 32
#define MTOT (Bb*Tt)    // 4096

// Scratch (allocation-free rule: __device__ globals)
__device__ float g_Q[(size_t)BH*Tt*Dd];
__device__ float g_K[(size_t)BH*Tt*Dd];
__device__ float g_V[(size_t)BH*Tt*Dd];
__device__ float g_Y[(size_t)Bb*Tt*Cc];

__device__ __forceinline__ float tf32r(float a) {
    uint32_t r; asm("cvt.rna.tf32.f32 %0, %1;" : "=r"(r) : "f"(a));
    return __uint_as_float(r);
}
__device__ __forceinline__ uint32_t fas(float a) { return __float_as_uint(a); }

__device__ __forceinline__ void mma8(float c[4],
    uint32_t a0, uint32_t a1, uint32_t a2, uint32_t a3,
    uint32_t b0, uint32_t b1)
{
    asm volatile(
        "mma.sync.aligned.m16n8k8.row.col.f32.tf32.tf32.f32 "
        "{%0,%1,%2,%3}, {%4,%5,%6,%7}, {%8,%9}, {%0,%1,%2,%3};"
        : "+f"(c[0]), "+f"(c[1]), "+f"(c[2]), "+f"(c[3])
        : "r"(a0), "r"(a1), "r"(a2), "r"(a3), "r"(b0), "r"(b1));
}

// ===========================================================================
// 3xTF32 mma.sync GEMM (identical to R6 passing version)
// ===========================================================================
#define STR 34
#define PIECE (128*STR)
#define STAGE (4*PIECE)
#define GSMEM_BYTES (2*STAGE*4)

template<bool SCATTER>
__global__ __launch_bounds__(256) void gemm_mma_kernel(
    const float* __restrict__ Ain, const float* __restrict__ Win,
    float* __restrict__ outp)
{
    extern __shared__ float sf[];
    const int tid = threadIdx.x;
    const int wid = tid >> 5, lid = tid & 31;
    const int g = lid >> 2, t4 = lid & 3;
    const int wm = wid & 1, wn = wid >> 1;
    const int bm = blockIdx.y * 128;
    const int bn = blockIdx.x * 128;

    const float* gA = Ain + (size_t)bm * Cc;
    const float* gB = Win + (size_t)bn * Cc;

    float acc[4][4][4];
    #pragma unroll
    for (int i = 0; i < 4; i++)
        #pragma unroll
        for (int j = 0; j < 4; j++)
            #pragma unroll
            for (int r = 0; r < 4; r++) acc[i][j][r] = 0.f;

    float4 ra[4], rb[4];
    int ldrow[4], ldc4[4];
    #pragma unroll
    for (int t = 0; t < 4; t++) {
        int idx = tid + t * 256;
        ldrow[t] = idx >> 3;
        ldc4[t]  = idx & 7;
    }

    auto fetch = [&](int kc) {
        #pragma unroll
        for (int t = 0; t < 4; t++) {
            const size_t off = (size_t)ldrow[t] * Cc + kc * 32 + ldc4[t] * 4;
            ra[t] = *(const float4*)(gA + off);
            rb[t] = *(const float4*)(gB + off);
        }
    };
    auto stos = [&](int s) {
        float* base = sf + s * STAGE;
        #pragma unroll
        for (int t = 0; t < 4; t++) {
            const int o = ldrow[t] * STR + ldc4[t] * 4;
            float hx = tf32r(ra[t].x), hy = tf32r(ra[t].y);
            float hz = tf32r(ra[t].z), hw = tf32r(ra[t].w);
            *(float2*)(base + o)     = make_float2(hx, hy);
            *(float2*)(base + o + 2) = make_float2(hz, hw);
            *(float2*)(base + PIECE + o)     = make_float2(tf32r(ra[t].x - hx), tf32r(ra[t].y - hy));
            *(float2*)(base + PIECE + o + 2) = make_float2(tf32r(ra[t].z - hz), tf32r(ra[t].w - hw));
            hx = tf32r(rb[t].x); hy = tf32r(rb[t].y);
            hz = tf32r(rb[t].z); hw = tf32r(rb[t].w);
            *(float2*)(base + 2*PIECE + o)     = make_float2(hx, hy);
            *(float2*)(base + 2*PIECE + o + 2) = make_float2(hz, hw);
            *(float2*)(base + 3*PIECE + o)     = make_float2(tf32r(rb[t].x - hx), tf32r(rb[t].y - hy));
            *(float2*)(base + 3*PIECE + o + 2) = make_float2(tf32r(rb[t].z - hz), tf32r(rb[t].w - hw));
        }
    };

    fetch(0); stos(0);
    __syncthreads();

    #pragma unroll 1
    for (int kc = 0; kc < 32; kc++) {
        if (kc < 31) fetch(kc + 1);

        const float* sA = sf + (kc & 1) * STAGE;
        #pragma unroll
        for (int ks = 0; ks < 4; ks++) {
            uint32_t ah[4][4], al[4][4], bh[4][2], bl[4][2];
            #pragma unroll
            for (int mt = 0; mt < 4; mt++) {
                const float* p = sA + (wm*64 + mt*16 + g) * STR + ks*8 + t4;
                ah[mt][0] = fas(p[0]);
                ah[mt][1] = fas(p[8*STR]);
                ah[mt][2] = fas(p[4]);
                ah[mt][3] = fas(p[8*STR + 4]);
                const float* q = p + PIECE;
                al[mt][0] = fas(q[0]);
                al[mt][1] = fas(q[8*STR]);
                al[mt][2] = fas(q[4]);
                al[mt][3] = fas(q[8*STR + 4]);
            }
            #pragma unroll
            for (int nt = 0; nt < 4; nt++) {
                const float* p = sA + 2*PIECE + (wn*32 + nt*8 + g) * STR + ks*8 + t4;
                bh[nt][0] = fas(p[0]);
                bh[nt][1] = fas(p[4]);
                const float* q = p + PIECE;
                bl[nt][0] = fas(q[0]);
                bl[nt][1] = fas(q[4]);
            }
            #pragma unroll
            for (int mt = 0; mt < 4; mt++)
                #pragma unroll
                for (int nt = 0; nt < 4; nt++) {
                    mma8(acc[mt][nt], ah[mt][0], ah[mt][1], ah[mt][2], ah[mt][3],
                         bh[nt][0], bh[nt][1]);
                    mma8(acc[mt][nt], ah[mt][0], ah[mt][1], ah[mt][2], ah[mt][3],
                         bl[nt][0], bl[nt][1]);
                    mma8(acc[mt][nt], al[mt][0], al[mt][1], al[mt][2], al[mt][3],
                         bh[nt][0], bh[nt][1]);
                }
        }

        if (kc < 31) stos((kc + 1) & 1);
        __syncthreads();
    }

    #pragma unroll
    for (int mt = 0; mt < 4; mt++) {
        #pragma unroll
        for (int nt = 0; nt < 4; nt++) {
            int m0 = bm + wm*64 + mt*16 + g;
            int n  = bn + wn*32 + nt*8 + 2*t4;
            if (SCATTER) {
                int which = n >> 10;
                int rem = n & 1023;
                int h = rem >> 6, d = rem & 63;
                float* dst = (which == 0) ? g_Q : (which == 1) ? g_K : g_V;
                int bb0 = m0 >> 11, t0 = m0 & 2047;
                *(float2*)(dst + ((size_t)(bb0*Hh + h)*Tt + t0)*Dd + d) =
                    make_float2(acc[mt][nt][0], acc[mt][nt][1]);
                int m1 = m0 + 8;
                int bb1 = m1 >> 11, t1 = m1 & 2047;
                *(float2*)(dst + ((size_t)(bb1*Hh + h)*Tt + t1)*Dd + d) =
                    make_float2(acc[mt][nt][2], acc[mt][nt][3]);
            } else {
                *(float2*)(outp + (size_t)m0 * Cc + n) =
                    make_float2(acc[mt][nt][0], acc[mt][nt][1]);
                *(float2*)(outp + (size_t)(m0 + 8) * Cc + n) =
                    make_float2(acc[mt][nt][2], acc[mt][nt][3]);
            }
        }
    }
}

// ===========================================================================
// Attention via mma.sync: block = 64 q-rows (4 warps x m16), k-tiles of 64
// streamed in DECREASING k order (suffix carry). QK = 3xTF32, AV = tf32.
// No running max: e = P - Z <= P ~ N(0,1), exp cannot overflow; diagonal
// guarantees l > 0. l reduced once at epilogue.
// ===========================================================================
#define ASTRQ 132      // interleaved hi/lo rows: 64 d-pairs + pad
#define ASTRV 72
#define ASTRW 68
#define AQS 0
#define AKS (64*ASTRQ)            // 8448
#define AVS (2*64*ASTRQ)          // 16896
#define AWS (2*64*ASTRQ + 64*ASTRV)  // 21504
#define ATTN_SMEM_FLOATS (AWS + 4*16*ASTRW)   // 25856
#define ATTN_SMEM_BYTES (ATTN_SMEM_FLOATS*4)  // 103424

__global__ __launch_bounds__(128) void attn_mma_kernel()
{
    extern __shared__ float sa[];
    const int tid  = threadIdx.x;
    const int warp = tid >> 5, lane = tid & 31;
    const int g = lane >> 2, t4 = lane & 3;
    const int qt = blockIdx.x, bh = blockIdx.y;

    float* Qs = sa + AQS;
    float* Ks = sa + AKS;
    float* Vs = sa + AVS;
    float* Ws = sa + AWS + warp * (16 * ASTRW);

    const int rowA = warp * 16 + g;        // local q-row (0..63) for frag row g

    // ---- load Q tile: scale 1/8, split hi/lo (tf32), interleave ----
    {
        const float* Qg = g_Q + ((size_t)bh * Tt + (size_t)qt * 64) * Dd;
        #pragma unroll
        for (int i = 0; i < 8; i++) {
            int idx = tid + i * 128;
            int row = idx >> 4, d4 = idx & 15;
            float4 v = *(const float4*)(Qg + row * 64 + d4 * 4);
            v.x *= 0.125f; v.y *= 0.125f; v.z *= 0.125f; v.w *= 0.125f;
            float hx = tf32r(v.x), hy = tf32r(v.y), hz = tf32r(v.z), hw = tf32r(v.w);
            *(float4*)(Qs + row*ASTRQ + 8*d4) =
                make_float4(hx, tf32r(v.x - hx), hy, tf32r(v.y - hy));
            *(float4*)(Qs + row*ASTRQ + 8*d4 + 4) =
                make_float4(hz, tf32r(v.z - hz), hw, tf32r(v.w - hw));
        }
    }

    float accO[8][4];
    #pragma unroll
    for (int nt = 0; nt < 8; nt++)
        #pragma unroll
        for (int c = 0; c < 4; c++) accO[nt][c] = 0.f;
    float lpart[2] = {0.f, 0.f};
    float zcarry[2] = {0.f, 0.f};

    #pragma unroll 1
    for (int kt = qt; kt >= 0; --kt) {
        // ---- load K (split hi/lo interleaved) and V (tf32-rounded) ----
        {
            const float* Kg = g_K + ((size_t)bh * Tt + (size_t)kt * 64) * Dd;
            const float* Vg = g_V + ((size_t)bh * Tt + (size_t)kt * 64) * Dd;
            #pragma unroll
            for (int i = 0; i < 8; i++) {
                int idx = tid + i * 128;
                int row = idx >> 4, d4 = idx & 15;
                float4 kv = *(const float4*)(Kg + row * 64 + d4 * 4);
                float4 vv = *(const float4*)(Vg + row * 64 + d4 * 4);
                float hx = tf32r(kv.x), hy = tf32r(kv.y), hz = tf32r(kv.z), hw = tf32r(kv.w);
                *(float4*)(Ks + row*ASTRQ + 8*d4) =
                    make_float4(hx, tf32r(kv.x - hx), hy, tf32r(kv.y - hy));
                *(float4*)(Ks + row*ASTRQ + 8*d4 + 4) =
                    make_float4(hz, tf32r(kv.z - hz), hw, tf32r(kv.w - hw));
                *(float4*)(Vs + row*ASTRV + 4*d4) =
                    make_float4(tf32r(vv.x), tf32r(vv.y), tf32r(vv.z), tf32r(vv.w));
            }
        }
        __syncthreads();

        // ---- QK: P = Qs @ Ks^T (3xTF32), accP C-frags ----
        float accP[8][4];
        #pragma unroll
        for (int nt = 0; nt < 8; nt++)
            #pragma unroll
            for (int c = 0; c < 4; c++) accP[nt][c] = 0.f;

        #pragma unroll
        for (int ks = 0; ks < 8; ks++) {
            const float* qp = Qs + rowA*ASTRQ + 2*(ks*8 + t4);
            float2 q00 = *(const float2*)(qp);
            float2 q10 = *(const float2*)(qp + 8*ASTRQ);
            float2 q01 = *(const float2*)(qp + 8);
            float2 q11 = *(const float2*)(qp + 8*ASTRQ + 8);
            uint32_t ah0 = fas(q00.x), ah1 = fas(q10.x), ah2 = fas(q01.x), ah3 = fas(q11.x);
            uint32_t al0 = fas(q00.y), al1 = fas(q10.y), al2 = fas(q01.y), al3 = fas(q11.y);
            #pragma unroll
            for (int nt = 0; nt < 8; nt++) {
                const float* kp = Ks + (nt*8 + g)*ASTRQ + 2*(ks*8 + t4);
                float2 k0 = *(const float2*)(kp);
                float2 k1 = *(const float2*)(kp + 8);
                uint32_t bh0 = fas(k0.x), bh1 = fas(k1.x);
                mma8(accP[nt], ah0, ah1, ah2, ah3, bh0, bh1);
                mma8(accP[nt], ah0, ah1, ah2, ah3, fas(k0.y), fas(k1.y));
                mma8(accP[nt], al0, al1, al2, al3, bh0, bh1);
            }
        }

        // ---- softmax with sigmoid suffix-cumsum penalty ----
        const bool diagt = (kt == qt);
        float s[8][4];
        #pragma unroll
        for (int nt = 0; nt < 8; nt++) {
            #pragma unroll
            for (int c = 0; c < 4; c++) {
                int row = rowA + (c >> 1) * 8;
                int col = nt*8 + 2*t4 + (c & 1);
                float pv = accP[nt][c];
                if (diagt && col > row) pv = -1e30f;
                accP[nt][c] = pv;
                float t = __expf(-pv);
                s[nt][c] = __fdividef(1.f, 1.f + t);   // sigmoid; 0 when masked
            }
        }

        float w[8][4];
        #pragma unroll
        for (int half = 0; half < 2; half++) {
            float pairs[8], incl[8], tot[8];
            #pragma unroll
            for (int nt = 0; nt < 8; nt++) {
                float x = s[nt][half*2] + s[nt][half*2+1];
                pairs[nt] = x;
                float y = __shfl_down_sync(0xffffffffu, x, 1, 4);
                if (t4 < 3) x += y;
                y = __shfl_down_sync(0xffffffffu, x, 2, 4);
                if (t4 < 2) x += y;
                incl[nt] = x;                                   // suffix-incl of pairs
                tot[nt]  = __shfl_sync(0xffffffffu, x, 0, 4);   // tile row sum
            }
            float after = 0.f;
            float zc = zcarry[half];
            float lp = 0.f;
            #pragma unroll
            for (int nt = 7; nt >= 0; nt--) {
                float zbase = zc + after + (incl[nt] - pairs[nt]);
                float z1 = s[nt][half*2+1] + zbase;
                float z0 = s[nt][half*2]   + z1;
                float w0 = __expf(accP[nt][half*2]   - z0);
                float w1 = __expf(accP[nt][half*2+1] - z1);
                lp += w0 + w1;
                w[nt][half*2]   = w0;
                w[nt][half*2+1] = w1;
                after += tot[nt];
            }
            lpart[half] += lp;
            zcarry[half] = zc + after;
        }

        // ---- W C-frags -> per-warp smem (tf32-rounded), then AV mma ----
        #pragma unroll
        for (int nt = 0; nt < 8; nt++) {
            *(float2*)(Ws + g*ASTRW + nt*8 + 2*t4) =
                make_float2(tf32r(w[nt][0]), tf32r(w[nt][1]));
            *(float2*)(Ws + (g+8)*ASTRW + nt*8 + 2*t4) =
                make_float2(tf32r(w[nt][2]), tf32r(w[nt][3]));
        }
        __syncwarp();

        #pragma unroll
        for (int ks = 0; ks < 8; ks++) {
            uint32_t a0 = fas(Ws[g*ASTRW + ks*8 + t4]);
            uint32_t a1 = fas(Ws[(g+8)*ASTRW + ks*8 + t4]);
            uint32_t a2 = fas(Ws[g*ASTRW + ks*8 + t4 + 4]);
            uint32_t a3 = fas(Ws[(g+8)*ASTRW + ks*8 + t4 + 4]);
            #pragma unroll
            for (int nt = 0; nt < 8; nt++) {
                uint32_t b0 = fas(Vs[(ks*8 + t4)*ASTRV + nt*8 + g]);
                uint32_t b1 = fas(Vs[(ks*8 + t4 + 4)*ASTRV + nt*8 + g]);
                mma8(accO[nt], a0, a1, a2, a3, b0, b1);
            }
        }
        __syncthreads();   // next iteration may overwrite Ks/Vs
    }

    // ---- epilogue: reduce l across quad, normalize, store ----
    float l0 = lpart[0];
    l0 += __shfl_xor_sync(0xffffffffu, l0, 1, 4);
    l0 += __shfl_xor_sync(0xffffffffu, l0, 2, 4);
    float l1 = lpart[1];
    l1 += __shfl_xor_sync(0xffffffffu, l1, 1, 4);
    l1 += __shfl_xor_sync(0xffffffffu, l1, 2, 4);
    float inv0 = __fdividef(1.f, l0);
    float inv1 = __fdividef(1.f, l1);

    const int b = bh >> 4, h = bh & 15;
    const int t0 = qt*64 + rowA;
    #pragma unroll
    for (int nt = 0; nt < 8; nt++) {
        int d = nt*8 + 2*t4;
        *(float2*)(g_Y + ((size_t)(b*Tt + t0))*Cc + h*64 + d) =
            make_float2(accO[nt][0]*inv0, accO[nt][1]*inv0);
        *(float2*)(g_Y + ((size_t)(b*Tt + t0 + 8))*Cc + h*64 + d) =
            make_float2(accO[nt][2]*inv1, accO[nt][3]*inv1);
    }
}

// ---------------------------------------------------------------------------
extern "C" void kernel_launch(void* const* d_in, const int* in_sizes, int n_in,
                              void* d_out, int out_size)
{
    (void)in_sizes; (void)n_in; (void)out_size;
    const float* x      = (const float*)d_in[0];
    const float* W_attn = (const float*)d_in[1];
    const float* W_proj = (const float*)d_in[2];
    float* out = (float*)d_out;

    cudaFuncSetAttribute(attn_mma_kernel,
                         cudaFuncAttributeMaxDynamicSharedMemorySize, ATTN_SMEM_BYTES);
    cudaFuncSetAttribute(gemm_mma_kernel<true>,
                         cudaFuncAttributeMaxDynamicSharedMemorySize, GSMEM_BYTES);
    cudaFuncSetAttribute(gemm_mma_kernel<false>,
                         cudaFuncAttributeMaxDynamicSharedMemorySize, GSMEM_BYTES);

    float* dY; cudaGetSymbolAddress((void**)&dY, g_Y);

    gemm_mma_kernel<true><<<dim3(3072/128, MTOT/128), 256, GSMEM_BYTES>>>(x, W_attn, nullptr);
    attn_mma_kernel<<<dim3(Tt/64, BH), 128, ATTN_SMEM_BYTES>>>();
    gemm_mma_kernel<false><<<dim3(Cc/128, MTOT/128), 256, GSMEM_BYTES>>>(dY, W_proj, out);
}

// round 8
// speedup vs baseline: 1.6969x; 1.1275x over previous
#include <cuda_runtime.h>
#include <cuda_bf16.h>
#include <math.h>
#include <cstdint>

#define Bb 2
#define Tt 2048
#define Cc 1024
#define Hh 16
#define Dd 64
#define BH (Bb*Hh)      // 32
#define MTOT (Bb*Tt)    // 4096

// Scratch (allocation-free rule: __device__ globals)
__device__ float g_Q[(size_t)BH*Tt*Dd];
__device__ float g_K[(size_t)BH*Tt*Dd];
__device__ float g_V[(size_t)BH*Tt*Dd];
__device__ float g_Y[(size_t)Bb*Tt*Cc];

__device__ __forceinline__ float tf32r(float a) {
    uint32_t r; asm("cvt.rna.tf32.f32 %0, %1;" : "=r"(r) : "f"(a));
    return __uint_as_float(r);
}
__device__ __forceinline__ uint32_t fas(float a) { return __float_as_uint(a); }

__device__ __forceinline__ void mma8(float c[4],
    uint32_t a0, uint32_t a1, uint32_t a2, uint32_t a3,
    uint32_t b0, uint32_t b1)
{
    asm volatile(
        "mma.sync.aligned.m16n8k8.row.col.f32.tf32.tf32.f32 "
        "{%0,%1,%2,%3}, {%4,%5,%6,%7}, {%8,%9}, {%0,%1,%2,%3};"
        : "+f"(c[0]), "+f"(c[1]), "+f"(c[2]), "+f"(c[3])
        : "r"(a0), "r"(a1), "r"(a2), "r"(a3), "r"(b0), "r"(b1));
}

__device__ __forceinline__ void cpasync16(uint32_t dst, const void* src) {
    asm volatile("cp.async.cg.shared.global [%0], [%1], 16;" :: "r"(dst), "l"(src));
}
#define CP_COMMIT() asm volatile("cp.async.commit_group;" ::: "memory")
#define CP_WAIT0()  asm volatile("cp.async.wait_group 0;" ::: "memory")

// ===========================================================================
// 3xTF32 mma.sync GEMM: raw fp32 smem (split at consume), cp.async
// double-buffered, 2 CTAs/SM. D[m][n] = sum_k A[m][k] * W[n][k].
// ===========================================================================
#define GSTR 36
#define GPIECE (128*GSTR)          // 4608 floats
#define GSTAGE (2*GPIECE)          // A then B
#define GSMEM_BYTES (2*GSTAGE*4)   // 73728

template<bool SCATTER>
__global__ __launch_bounds__(256, 2) void gemm_mma_kernel(
    const float* __restrict__ Ain, const float* __restrict__ Win,
    float* __restrict__ outp)
{
    extern __shared__ float sf[];
    const uint32_t sbase = (uint32_t)__cvta_generic_to_shared(sf);
    const int tid = threadIdx.x;
    const int wid = tid >> 5, lid = tid & 31;
    const int g = lid >> 2, t4 = lid & 3;
    const int wm = wid & 1, wn = wid >> 1;   // warp tile 64(m) x 32(n)
    const int bm = blockIdx.y * 128;
    const int bn = blockIdx.x * 128;

    const float* gA = Ain + (size_t)bm * Cc;
    const float* gB = Win + (size_t)bn * Cc;

    float acc[4][4][4];
    #pragma unroll
    for (int i = 0; i < 4; i++)
        #pragma unroll
        for (int j = 0; j < 4; j++)
            #pragma unroll
            for (int r = 0; r < 4; r++) acc[i][j][r] = 0.f;

    auto load_chunk = [&](int kc, int s) {
        uint32_t base = sbase + (uint32_t)(s * GSTAGE) * 4u;
        #pragma unroll
        for (int t = 0; t < 4; t++) {
            int idx = tid + t * 256;            // 0..1023
            int row = idx >> 3, c4 = idx & 7;
            uint32_t doff = base + (uint32_t)(row * GSTR + c4 * 4) * 4u;
            const size_t goff = (size_t)row * Cc + kc * 32 + c4 * 4;
            cpasync16(doff, gA + goff);
            cpasync16(doff + GPIECE * 4u, gB + goff);
        }
        CP_COMMIT();
    };

    load_chunk(0, 0);
    CP_WAIT0();
    __syncthreads();

    #pragma unroll 1
    for (int kc = 0; kc < 32; kc++) {
        if (kc < 31) load_chunk(kc + 1, (kc + 1) & 1);

        const float* sA = sf + (kc & 1) * GSTAGE;
        const float* sB = sA + GPIECE;
        #pragma unroll
        for (int ks = 0; ks < 4; ks++) {
            uint32_t ah[4][4], al[4][4];
            #pragma unroll
            for (int mt = 0; mt < 4; mt++) {
                const float* p = sA + (wm*64 + mt*16 + g) * GSTR + ks*8 + t4;
                float x0 = p[0], x1 = p[8*GSTR], x2 = p[4], x3 = p[8*GSTR + 4];
                float h0 = tf32r(x0), h1 = tf32r(x1), h2 = tf32r(x2), h3 = tf32r(x3);
                ah[mt][0] = fas(h0); ah[mt][1] = fas(h1);
                ah[mt][2] = fas(h2); ah[mt][3] = fas(h3);
                al[mt][0] = fas(x0 - h0); al[mt][1] = fas(x1 - h1);
                al[mt][2] = fas(x2 - h2); al[mt][3] = fas(x3 - h3);
            }
            #pragma unroll
            for (int nt = 0; nt < 4; nt++) {
                const float* p = sB + (wn*32 + nt*8 + g) * GSTR + ks*8 + t4;
                float y0 = p[0], y1 = p[4];
                float h0 = tf32r(y0), h1 = tf32r(y1);
                uint32_t bh0 = fas(h0), bh1 = fas(h1);
                uint32_t bl0 = fas(y0 - h0), bl1 = fas(y1 - h1);
                #pragma unroll
                for (int mt = 0; mt < 4; mt++) {
                    mma8(acc[mt][nt], ah[mt][0], ah[mt][1], ah[mt][2], ah[mt][3], bh0, bh1);
                    mma8(acc[mt][nt], ah[mt][0], ah[mt][1], ah[mt][2], ah[mt][3], bl0, bl1);
                    mma8(acc[mt][nt], al[mt][0], al[mt][1], al[mt][2], al[mt][3], bh0, bh1);
                }
            }
        }

        if (kc < 31) CP_WAIT0();
        __syncthreads();
    }

    #pragma unroll
    for (int mt = 0; mt < 4; mt++) {
        #pragma unroll
        for (int nt = 0; nt < 4; nt++) {
            int m0 = bm + wm*64 + mt*16 + g;
            int n  = bn + wn*32 + nt*8 + 2*t4;
            if (SCATTER) {
                int which = n >> 10;
                int rem = n & 1023;
                int h = rem >> 6, d = rem & 63;
                float* dst = (which == 0) ? g_Q : (which == 1) ? g_K : g_V;
                int bb0 = m0 >> 11, t0 = m0 & 2047;
                *(float2*)(dst + ((size_t)(bb0*Hh + h)*Tt + t0)*Dd + d) =
                    make_float2(acc[mt][nt][0], acc[mt][nt][1]);
                int m1 = m0 + 8;
                int bb1 = m1 >> 11, t1 = m1 & 2047;
                *(float2*)(dst + ((size_t)(bb1*Hh + h)*Tt + t1)*Dd + d) =
                    make_float2(acc[mt][nt][2], acc[mt][nt][3]);
            } else {
                *(float2*)(outp + (size_t)m0 * Cc + n) =
                    make_float2(acc[mt][nt][0], acc[mt][nt][1]);
                *(float2*)(outp + (size_t)(m0 + 8) * Cc + n) =
                    make_float2(acc[mt][nt][2], acc[mt][nt][3]);
            }
        }
    }
}

// ===========================================================================
// Attention: raw-fp32 smem, cp.async double-buffered K/V, split at consume.
// Block = 64 q-rows (4 warps), k-tiles of 64 streamed in DECREASING k order.
// ===========================================================================
#define ASTRQ 68
#define ASTRV 72
#define AKSZ (64*ASTRQ)            // 4352 (K stage piece)
#define AVSZ (64*ASTRV)            // 4608
#define ASTAGE (AKSZ + AVSZ)       // 8960
#define AQOFF 0
#define AST0  (64*ASTRQ)           // 4352 (after Q)
#define AWOFF (AST0 + 2*ASTAGE)    // 22272
#define ATTN_FLOATS (AWOFF + 4*16*ASTRQ)   // 26624
#define ATTN_SMEM_BYTES (ATTN_FLOATS*4)    // 106496

__global__ __launch_bounds__(128) void attn_mma_kernel()
{
    extern __shared__ float sa[];
    const uint32_t sbase = (uint32_t)__cvta_generic_to_shared(sa);
    const int tid  = threadIdx.x;
    const int warp = tid >> 5, lane = tid & 31;
    const int g = lane >> 2, t4 = lane & 3;
    const int qt = blockIdx.x, bh = blockIdx.y;

    float* Qs = sa + AQOFF;
    float* Ws = sa + AWOFF + warp * (16 * ASTRQ);
    const int rowA = warp * 16 + g;

    // ---- load Q tile raw (scaled by 1/8) ----
    {
        const float* Qg = g_Q + ((size_t)bh * Tt + (size_t)qt * 64) * Dd;
        #pragma unroll
        for (int i = 0; i < 8; i++) {
            int idx = tid + i * 128;
            int row = idx >> 4, d4 = idx & 15;
            float4 v = *(const float4*)(Qg + row * 64 + d4 * 4);
            v.x *= 0.125f; v.y *= 0.125f; v.z *= 0.125f; v.w *= 0.125f;
            *(float4*)(Qs + row*ASTRQ + d4*4) = v;
        }
    }

    auto prefetch = [&](int kt, int s) {
        const float* Kg = g_K + ((size_t)bh * Tt + (size_t)kt * 64) * Dd;
        const float* Vg = g_V + ((size_t)bh * Tt + (size_t)kt * 64) * Dd;
        uint32_t kb = sbase + (uint32_t)(AST0 + s * ASTAGE) * 4u;
        uint32_t vb = kb + (uint32_t)AKSZ * 4u;
        #pragma unroll
        for (int t = 0; t < 8; t++) {
            int idx = tid + t * 128;
            int row = idx >> 4, c4 = idx & 15;
            cpasync16(kb + (uint32_t)(row*ASTRQ + c4*4)*4u, Kg + row*64 + c4*4);
            cpasync16(vb + (uint32_t)(row*ASTRV + c4*4)*4u, Vg + row*64 + c4*4);
        }
        CP_COMMIT();
    };

    float accO[8][4];
    #pragma unroll
    for (int nt = 0; nt < 8; nt++)
        #pragma unroll
        for (int c = 0; c < 4; c++) accO[nt][c] = 0.f;
    float lpart[2] = {0.f, 0.f};
    float zcarry[2] = {0.f, 0.f};

    prefetch(qt, 0);
    CP_WAIT0();
    __syncthreads();

    int par = 0;
    #pragma unroll 1
    for (int kt = qt; kt >= 0; --kt) {
        if (kt > 0) prefetch(kt - 1, par ^ 1);

        const float* Ks = sa + AST0 + par * ASTAGE;
        const float* Vs = Ks + AKSZ;

        // ---- QK: P = Qs @ Ks^T (3xTF32, split at consume) ----
        float accP[8][4];
        #pragma unroll
        for (int nt = 0; nt < 8; nt++)
            #pragma unroll
            for (int c = 0; c < 4; c++) accP[nt][c] = 0.f;

        #pragma unroll
        for (int ks = 0; ks < 8; ks++) {
            const float* qp = Qs + rowA*ASTRQ + ks*8 + t4;
            float x0 = qp[0], x1 = qp[8*ASTRQ], x2 = qp[4], x3 = qp[8*ASTRQ + 4];
            float h0 = tf32r(x0), h1 = tf32r(x1), h2 = tf32r(x2), h3 = tf32r(x3);
            uint32_t ah0 = fas(h0), ah1 = fas(h1), ah2 = fas(h2), ah3 = fas(h3);
            uint32_t al0 = fas(x0 - h0), al1 = fas(x1 - h1);
            uint32_t al2 = fas(x2 - h2), al3 = fas(x3 - h3);
            #pragma unroll
            for (int nt = 0; nt < 8; nt++) {
                const float* kp = Ks + (nt*8 + g)*ASTRQ + ks*8 + t4;
                float k0 = kp[0], k1 = kp[4];
                float kh0 = tf32r(k0), kh1 = tf32r(k1);
                uint32_t bh0 = fas(kh0), bh1 = fas(kh1);
                mma8(accP[nt], ah0, ah1, ah2, ah3, bh0, bh1);
                mma8(accP[nt], ah0, ah1, ah2, ah3, fas(k0 - kh0), fas(k1 - kh1));
                mma8(accP[nt], al0, al1, al2, al3, bh0, bh1);
            }
        }

        // ---- softmax with sigmoid suffix-cumsum penalty ----
        const bool diagt = (kt == qt);
        float s[8][4];
        #pragma unroll
        for (int nt = 0; nt < 8; nt++) {
            #pragma unroll
            for (int c = 0; c < 4; c++) {
                int row = rowA + (c >> 1) * 8;
                int col = nt*8 + 2*t4 + (c & 1);
                float pv = accP[nt][c];
                if (diagt && col > row) pv = -1e30f;
                accP[nt][c] = pv;
                float t = __expf(-pv);
                s[nt][c] = __fdividef(1.f, 1.f + t);
            }
        }

        float w[8][4];
        #pragma unroll
        for (int half = 0; half < 2; half++) {
            float pairs[8], incl[8], tot[8];
            #pragma unroll
            for (int nt = 0; nt < 8; nt++) {
                float x = s[nt][half*2] + s[nt][half*2+1];
                pairs[nt] = x;
                float y = __shfl_down_sync(0xffffffffu, x, 1, 4);
                if (t4 < 3) x += y;
                y = __shfl_down_sync(0xffffffffu, x, 2, 4);
                if (t4 < 2) x += y;
                incl[nt] = x;
                tot[nt]  = __shfl_sync(0xffffffffu, x, 0, 4);
            }
            float after = 0.f;
            float zc = zcarry[half];
            float lp = 0.f;
            #pragma unroll
            for (int nt = 7; nt >= 0; nt--) {
                float zbase = zc + after + (incl[nt] - pairs[nt]);
                float z1 = s[nt][half*2+1] + zbase;
                float z0 = s[nt][half*2]   + z1;
                float w0 = __expf(accP[nt][half*2]   - z0);
                float w1 = __expf(accP[nt][half*2+1] - z1);
                lp += w0 + w1;
                w[nt][half*2]   = w0;
                w[nt][half*2+1] = w1;
                after += tot[nt];
            }
            lpart[half] += lp;
            zcarry[half] = zc + after;
        }

        // ---- W C-frags -> per-warp smem (tf32-rounded), then AV mma ----
        #pragma unroll
        for (int nt = 0; nt < 8; nt++) {
            *(float2*)(Ws + g*ASTRQ + nt*8 + 2*t4) =
                make_float2(tf32r(w[nt][0]), tf32r(w[nt][1]));
            *(float2*)(Ws + (g+8)*ASTRQ + nt*8 + 2*t4) =
                make_float2(tf32r(w[nt][2]), tf32r(w[nt][3]));
        }
        __syncwarp();

        #pragma unroll
        for (int ks = 0; ks < 8; ks++) {
            uint32_t a0 = fas(Ws[g*ASTRQ + ks*8 + t4]);
            uint32_t a1 = fas(Ws[(g+8)*ASTRQ + ks*8 + t4]);
            uint32_t a2 = fas(Ws[g*ASTRQ + ks*8 + t4 + 4]);
            uint32_t a3 = fas(Ws[(g+8)*ASTRQ + ks*8 + t4 + 4]);
            #pragma unroll
            for (int nt = 0; nt < 8; nt++) {
                float v0 = Vs[(ks*8 + t4)*ASTRV + nt*8 + g];
                float v1 = Vs[(ks*8 + t4 + 4)*ASTRV + nt*8 + g];
                mma8(accO[nt], a0, a1, a2, a3, fas(tf32r(v0)), fas(tf32r(v1)));
            }
        }

        if (kt > 0) CP_WAIT0();
        __syncthreads();
        par ^= 1;
    }

    // ---- epilogue ----
    float l0 = lpart[0];
    l0 += __shfl_xor_sync(0xffffffffu, l0, 1, 4);
    l0 += __shfl_xor_sync(0xffffffffu, l0, 2, 4);
    float l1 = lpart[1];
    l1 += __shfl_xor_sync(0xffffffffu, l1, 1, 4);
    l1 += __shfl_xor_sync(0xffffffffu, l1, 2, 4);
    float inv0 = __fdividef(1.f, l0);
    float inv1 = __fdividef(1.f, l1);

    const int b = bh >> 4, h = bh & 15;
    const int t0 = qt*64 + rowA;
    #pragma unroll
    for (int nt = 0; nt < 8; nt++) {
        int d = nt*8 + 2*t4;
        *(float2*)(g_Y + ((size_t)(b*Tt + t0))*Cc + h*64 + d) =
            make_float2(accO[nt][0]*inv0, accO[nt][1]*inv0);
        *(float2*)(g_Y + ((size_t)(b*Tt + t0 + 8))*Cc + h*64 + d) =
            make_float2(accO[nt][2]*inv1, accO[nt][3]*inv1);
    }
}

// ---------------------------------------------------------------------------
extern "C" void kernel_launch(void* const* d_in, const int* in_sizes, int n_in,
                              void* d_out, int out_size)
{
    (void)in_sizes; (void)n_in; (void)out_size;
    const float* x      = (const float*)d_in[0];
    const float* W_attn = (const float*)d_in[1];
    const float* W_proj = (const float*)d_in[2];
    float* out = (float*)d_out;

    cudaFuncSetAttribute(attn_mma_kernel,
                         cudaFuncAttributeMaxDynamicSharedMemorySize, ATTN_SMEM_BYTES);
    cudaFuncSetAttribute(gemm_mma_kernel<true>,
                         cudaFuncAttributeMaxDynamicSharedMemorySize, GSMEM_BYTES);
    cudaFuncSetAttribute(gemm_mma_kernel<false>,
                         cudaFuncAttributeMaxDynamicSharedMemorySize, GSMEM_BYTES);

    float* dY; cudaGetSymbolAddress((void**)&dY, g_Y);

    gemm_mma_kernel<true><<<dim3(3072/128, MTOT/128), 256, GSMEM_BYTES>>>(x, W_attn, nullptr);
    attn_mma_kernel<<<dim3(Tt/64, BH), 128, ATTN_SMEM_BYTES>>>();
    gemm_mma_kernel<false><<<dim3(Cc/128, MTOT/128), 256, GSMEM_BYTES>>>(dY, W_proj, out);
}

// round 9
// speedup vs baseline: 2.2660x; 1.3354x over previous
#include <cuda_runtime.h>
#include <cuda_bf16.h>
#include <math.h>
#include <cstdint>

#define Bb 2
#define Tt 2048
#define Cc 1024
#define Hh 16
#define Dd 64
#define BH (Bb*Hh)      // 32
#define MTOT (Bb*Tt)    // 4096

// Scratch (allocation-free rule: __device__ globals)
__device__ float g_Q[(size_t)BH*Tt*Dd];
__device__ float g_K[(size_t)BH*Tt*Dd];
__device__ float g_V[(size_t)BH*Tt*Dd];
__device__ float g_Y[(size_t)Bb*Tt*Cc];

__device__ __forceinline__ float tf32r(float a) {
    uint32_t r; asm("cvt.rna.tf32.f32 %0, %1;" : "=r"(r) : "f"(a));
    return __uint_as_float(r);
}
__device__ __forceinline__ uint32_t fas(float a) { return __float_as_uint(a); }

// pack (e0, e1) -> bf16x2 (lo half = e0)
__device__ __forceinline__ uint32_t pack_bf(float e0, float e1) {
    uint32_t r;
    asm("cvt.rn.bf16x2.f32 %0, %1, %2;" : "=r"(r) : "f"(e1), "f"(e0));
    return r;
}
// split float2 -> bf16x2 hi + bf16x2 lo (3-term scheme)
__device__ __forceinline__ void bsplit2(float2 x, uint32_t& h, uint32_t& l) {
    h = pack_bf(x.x, x.y);
    float h0 = __uint_as_float(h << 16);
    float h1 = __uint_as_float(h & 0xffff0000u);
    l = pack_bf(x.x - h0, x.y - h1);
}

// tf32 m16n8k8 (AV path)
__device__ __forceinline__ void mma8(float c[4],
    uint32_t a0, uint32_t a1, uint32_t a2, uint32_t a3,
    uint32_t b0, uint32_t b1)
{
    asm volatile(
        "mma.sync.aligned.m16n8k8.row.col.f32.tf32.tf32.f32 "
        "{%0,%1,%2,%3}, {%4,%5,%6,%7}, {%8,%9}, {%0,%1,%2,%3};"
        : "+f"(c[0]), "+f"(c[1]), "+f"(c[2]), "+f"(c[3])
        : "r"(a0), "r"(a1), "r"(a2), "r"(a3), "r"(b0), "r"(b1));
}
// bf16 m16n8k16
__device__ __forceinline__ void mma16(float c[4],
    uint32_t a0, uint32_t a1, uint32_t a2, uint32_t a3,
    uint32_t b0, uint32_t b1)
{
    asm volatile(
        "mma.sync.aligned.m16n8k16.row.col.f32.bf16.bf16.f32 "
        "{%0,%1,%2,%3}, {%4,%5,%6,%7}, {%8,%9}, {%0,%1,%2,%3};"
        : "+f"(c[0]), "+f"(c[1]), "+f"(c[2]), "+f"(c[3])
        : "r"(a0), "r"(a1), "r"(a2), "r"(a3), "r"(b0), "r"(b1));
}

__device__ __forceinline__ void cpasync16(uint32_t dst, const void* src) {
    asm volatile("cp.async.cg.shared.global [%0], [%1], 16;" :: "r"(dst), "l"(src));
}
#define CP_COMMIT() asm volatile("cp.async.commit_group;" ::: "memory")
#define CP_WAIT0()  asm volatile("cp.async.wait_group 0;" ::: "memory")

// ===========================================================================
// 3x-bf16 mma.sync GEMM: raw fp32 smem (split to bf16 at consume), cp.async
// double-buffered, 2 CTAs/SM. D[m][n] = sum_k A[m][k] * W[n][k].
// ===========================================================================
#define GSTR 36
#define GPIECE (128*GSTR)          // 4608 floats
#define GSTAGE (2*GPIECE)          // A then B
#define GSMEM_BYTES (2*GSTAGE*4)   // 73728

template<bool SCATTER>
__global__ __launch_bounds__(256, 2) void gemm_mma_kernel(
    const float* __restrict__ Ain, const float* __restrict__ Win,
    float* __restrict__ outp)
{
    extern __shared__ float sf[];
    const uint32_t sbase = (uint32_t)__cvta_generic_to_shared(sf);
    const int tid = threadIdx.x;
    const int wid = tid >> 5, lid = tid & 31;
    const int g = lid >> 2, t4 = lid & 3;
    const int wm = wid & 1, wn = wid >> 1;   // warp tile 64(m) x 32(n)
    const int bm = blockIdx.y * 128;
    const int bn = blockIdx.x * 128;

    const float* gA = Ain + (size_t)bm * Cc;
    const float* gB = Win + (size_t)bn * Cc;

    float acc[4][4][4];
    #pragma unroll
    for (int i = 0; i < 4; i++)
        #pragma unroll
        for (int j = 0; j < 4; j++)
            #pragma unroll
            for (int r = 0; r < 4; r++) acc[i][j][r] = 0.f;

    auto load_chunk = [&](int kc, int s) {
        uint32_t base = sbase + (uint32_t)(s * GSTAGE) * 4u;
        #pragma unroll
        for (int t = 0; t < 4; t++) {
            int idx = tid + t * 256;            // 0..1023
            int row = idx >> 3, c4 = idx & 7;
            uint32_t doff = base + (uint32_t)(row * GSTR + c4 * 4) * 4u;
            const size_t goff = (size_t)row * Cc + kc * 32 + c4 * 4;
            cpasync16(doff, gA + goff);
            cpasync16(doff + GPIECE * 4u, gB + goff);
        }
        CP_COMMIT();
    };

    load_chunk(0, 0);
    CP_WAIT0();
    __syncthreads();

    #pragma unroll 1
    for (int kc = 0; kc < 32; kc++) {
        if (kc < 31) load_chunk(kc + 1, (kc + 1) & 1);

        const float* sA = sf + (kc & 1) * GSTAGE;
        const float* sB = sA + GPIECE;
        #pragma unroll
        for (int kh = 0; kh < 2; kh++) {       // two k16 halves of the 32-chunk
            uint32_t ah[4][4], al[4][4];
            #pragma unroll
            for (int mt = 0; mt < 4; mt++) {
                const float* p = sA + (wm*64 + mt*16 + g) * GSTR + kh*16 + 2*t4;
                bsplit2(*(const float2*)(p),              ah[mt][0], al[mt][0]); // (g,   2t4)
                bsplit2(*(const float2*)(p + 8*GSTR),     ah[mt][1], al[mt][1]); // (g+8, 2t4)
                bsplit2(*(const float2*)(p + 8),          ah[mt][2], al[mt][2]); // (g,   2t4+8)
                bsplit2(*(const float2*)(p + 8*GSTR + 8), ah[mt][3], al[mt][3]); // (g+8, 2t4+8)
            }
            #pragma unroll
            for (int nt = 0; nt < 4; nt++) {
                const float* p = sB + (wn*32 + nt*8 + g) * GSTR + kh*16 + 2*t4;
                uint32_t bh0, bl0, bh1, bl1;
                bsplit2(*(const float2*)(p),     bh0, bl0);   // (n=g, k=2t4)
                bsplit2(*(const float2*)(p + 8), bh1, bl1);   // (n=g, k=2t4+8)
                #pragma unroll
                for (int mt = 0; mt < 4; mt++) {
                    mma16(acc[mt][nt], ah[mt][0], ah[mt][1], ah[mt][2], ah[mt][3], bh0, bh1);
                    mma16(acc[mt][nt], ah[mt][0], ah[mt][1], ah[mt][2], ah[mt][3], bl0, bl1);
                    mma16(acc[mt][nt], al[mt][0], al[mt][1], al[mt][2], al[mt][3], bh0, bh1);
                }
            }
        }

        if (kc < 31) CP_WAIT0();
        __syncthreads();
    }

    #pragma unroll
    for (int mt = 0; mt < 4; mt++) {
        #pragma unroll
        for (int nt = 0; nt < 4; nt++) {
            int m0 = bm + wm*64 + mt*16 + g;
            int n  = bn + wn*32 + nt*8 + 2*t4;
            if (SCATTER) {
                int which = n >> 10;
                int rem = n & 1023;
                int h = rem >> 6, d = rem & 63;
                float* dst = (which == 0) ? g_Q : (which == 1) ? g_K : g_V;
                int bb0 = m0 >> 11, t0 = m0 & 2047;
                *(float2*)(dst + ((size_t)(bb0*Hh + h)*Tt + t0)*Dd + d) =
                    make_float2(acc[mt][nt][0], acc[mt][nt][1]);
                int m1 = m0 + 8;
                int bb1 = m1 >> 11, t1 = m1 & 2047;
                *(float2*)(dst + ((size_t)(bb1*Hh + h)*Tt + t1)*Dd + d) =
                    make_float2(acc[mt][nt][2], acc[mt][nt][3]);
            } else {
                *(float2*)(outp + (size_t)m0 * Cc + n) =
                    make_float2(acc[mt][nt][0], acc[mt][nt][1]);
                *(float2*)(outp + (size_t)(m0 + 8) * Cc + n) =
                    make_float2(acc[mt][nt][2], acc[mt][nt][3]);
            }
        }
    }
}

// ===========================================================================
// Attention: raw-fp32 smem, cp.async double-buffered K/V.
// QK = 3x-bf16 m16n8k16 (split at consume); AV = single-pass tf32 m16n8k8.
// Block = 64 q-rows (4 warps), k-tiles of 64 streamed in DECREASING k order.
// ===========================================================================
#define ASTRQ 68
#define ASTRV 72
#define AKSZ (64*ASTRQ)            // 4352 (K stage piece)
#define AVSZ (64*ASTRV)            // 4608
#define ASTAGE (AKSZ + AVSZ)       // 8960
#define AQOFF 0
#define AST0  (64*ASTRQ)           // 4352 (after Q)
#define AWOFF (AST0 + 2*ASTAGE)    // 22272
#define ATTN_FLOATS (AWOFF + 4*16*ASTRQ)   // 26624
#define ATTN_SMEM_BYTES (ATTN_FLOATS*4)    // 106496

__global__ __launch_bounds__(128) void attn_mma_kernel()
{
    extern __shared__ float sa[];
    const uint32_t sbase = (uint32_t)__cvta_generic_to_shared(sa);
    const int tid  = threadIdx.x;
    const int warp = tid >> 5, lane = tid & 31;
    const int g = lane >> 2, t4 = lane & 3;
    const int qt = blockIdx.x, bh = blockIdx.y;

    float* Qs = sa + AQOFF;
    float* Ws = sa + AWOFF + warp * (16 * ASTRQ);
    const int rowA = warp * 16 + g;

    // ---- load Q tile raw (scaled by 1/8) ----
    {
        const float* Qg = g_Q + ((size_t)bh * Tt + (size_t)qt * 64) * Dd;
        #pragma unroll
        for (int i = 0; i < 8; i++) {
            int idx = tid + i * 128;
            int row = idx >> 4, d4 = idx & 15;
            float4 v = *(const float4*)(Qg + row * 64 + d4 * 4);
            v.x *= 0.125f; v.y *= 0.125f; v.z *= 0.125f; v.w *= 0.125f;
            *(float4*)(Qs + row*ASTRQ + d4*4) = v;
        }
    }

    auto prefetch = [&](int kt, int s) {
        const float* Kg = g_K + ((size_t)bh * Tt + (size_t)kt * 64) * Dd;
        const float* Vg = g_V + ((size_t)bh * Tt + (size_t)kt * 64) * Dd;
        uint32_t kb = sbase + (uint32_t)(AST0 + s * ASTAGE) * 4u;
        uint32_t vb = kb + (uint32_t)AKSZ * 4u;
        #pragma unroll
        for (int t = 0; t < 8; t++) {
            int idx = tid + t * 128;
            int row = idx >> 4, c4 = idx & 15;
            cpasync16(kb + (uint32_t)(row*ASTRQ + c4*4)*4u, Kg + row*64 + c4*4);
            cpasync16(vb + (uint32_t)(row*ASTRV + c4*4)*4u, Vg + row*64 + c4*4);
        }
        CP_COMMIT();
    };

    float accO[8][4];
    #pragma unroll
    for (int nt = 0; nt < 8; nt++)
        #pragma unroll
        for (int c = 0; c < 4; c++) accO[nt][c] = 0.f;
    float lpart[2] = {0.f, 0.f};
    float zcarry[2] = {0.f, 0.f};

    prefetch(qt, 0);
    CP_WAIT0();
    __syncthreads();

    int par = 0;
    #pragma unroll 1
    for (int kt = qt; kt >= 0; --kt) {
        if (kt > 0) prefetch(kt - 1, par ^ 1);

        const float* Ks = sa + AST0 + par * ASTAGE;
        const float* Vs = Ks + AKSZ;

        // ---- QK: P = Qs @ Ks^T (3x-bf16 m16n8k16, split at consume) ----
        float accP[8][4];
        #pragma unroll
        for (int nt = 0; nt < 8; nt++)
            #pragma unroll
            for (int c = 0; c < 4; c++) accP[nt][c] = 0.f;

        #pragma unroll
        for (int kh = 0; kh < 4; kh++) {       // 4 k16 steps over d=64
            const float* qp = Qs + rowA*ASTRQ + kh*16 + 2*t4;
            uint32_t ah0, al0, ah1, al1, ah2, al2, ah3, al3;
            bsplit2(*(const float2*)(qp),               ah0, al0); // (rowA,   2t4)
            bsplit2(*(const float2*)(qp + 8*ASTRQ),     ah1, al1); // (rowA+8, 2t4)
            bsplit2(*(const float2*)(qp + 8),           ah2, al2); // (rowA,   2t4+8)
            bsplit2(*(const float2*)(qp + 8*ASTRQ + 8), ah3, al3); // (rowA+8, 2t4+8)
            #pragma unroll
            for (int nt = 0; nt < 8; nt++) {
                const float* kp = Ks + (nt*8 + g)*ASTRQ + kh*16 + 2*t4;
                uint32_t bh0, bl0, bh1, bl1;
                bsplit2(*(const float2*)(kp),     bh0, bl0);
                bsplit2(*(const float2*)(kp + 8), bh1, bl1);
                mma16(accP[nt], ah0, ah1, ah2, ah3, bh0, bh1);
                mma16(accP[nt], ah0, ah1, ah2, ah3, bl0, bl1);
                mma16(accP[nt], al0, al1, al2, al3, bh0, bh1);
            }
        }

        // ---- softmax with sigmoid suffix-cumsum penalty ----
        const bool diagt = (kt == qt);
        float s[8][4];
        #pragma unroll
        for (int nt = 0; nt < 8; nt++) {
            #pragma unroll
            for (int c = 0; c < 4; c++) {
                int row = rowA + (c >> 1) * 8;
                int col = nt*8 + 2*t4 + (c & 1);
                float pv = accP[nt][c];
                if (diagt && col > row) pv = -1e30f;
                accP[nt][c] = pv;
                float t = __expf(-pv);
                s[nt][c] = __fdividef(1.f, 1.f + t);
            }
        }

        float w[8][4];
        #pragma unroll
        for (int half = 0; half < 2; half++) {
            float pairs[8], incl[8], tot[8];
            #pragma unroll
            for (int nt = 0; nt < 8; nt++) {
                float x = s[nt][half*2] + s[nt][half*2+1];
                pairs[nt] = x;
                float y = __shfl_down_sync(0xffffffffu, x, 1, 4);
                if (t4 < 3) x += y;
                y = __shfl_down_sync(0xffffffffu, x, 2, 4);
                if (t4 < 2) x += y;
                incl[nt] = x;
                tot[nt]  = __shfl_sync(0xffffffffu, x, 0, 4);
            }
            float after = 0.f;
            float zc = zcarry[half];
            float lp = 0.f;
            #pragma unroll
            for (int nt = 7; nt >= 0; nt--) {
                float zbase = zc + after + (incl[nt] - pairs[nt]);
                float z1 = s[nt][half*2+1] + zbase;
                float z0 = s[nt][half*2]   + z1;
                float w0 = __expf(accP[nt][half*2]   - z0);
                float w1 = __expf(accP[nt][half*2+1] - z1);
                lp += w0 + w1;
                w[nt][half*2]   = w0;
                w[nt][half*2+1] = w1;
                after += tot[nt];
            }
            lpart[half] += lp;
            zcarry[half] = zc + after;
        }

        // ---- W C-frags -> per-warp smem (tf32-rounded), then AV mma (tf32) ----
        #pragma unroll
        for (int nt = 0; nt < 8; nt++) {
            *(float2*)(Ws + g*ASTRQ + nt*8 + 2*t4) =
                make_float2(tf32r(w[nt][0]), tf32r(w[nt][1]));
            *(float2*)(Ws + (g+8)*ASTRQ + nt*8 + 2*t4) =
                make_float2(tf32r(w[nt][2]), tf32r(w[nt][3]));
        }
        __syncwarp();

        #pragma unroll
        for (int ks = 0; ks < 8; ks++) {
            uint32_t a0 = fas(Ws[g*ASTRQ + ks*8 + t4]);
            uint32_t a1 = fas(Ws[(g+8)*ASTRQ + ks*8 + t4]);
            uint32_t a2 = fas(Ws[g*ASTRQ + ks*8 + t4 + 4]);
            uint32_t a3 = fas(Ws[(g+8)*ASTRQ + ks*8 + t4 + 4]);
            #pragma unroll
            for (int nt = 0; nt < 8; nt++) {
                float v0 = Vs[(ks*8 + t4)*ASTRV + nt*8 + g];
                float v1 = Vs[(ks*8 + t4 + 4)*ASTRV + nt*8 + g];
                mma8(accO[nt], a0, a1, a2, a3, fas(tf32r(v0)), fas(tf32r(v1)));
            }
        }

        if (kt > 0) CP_WAIT0();
        __syncthreads();
        par ^= 1;
    }

    // ---- epilogue ----
    float l0 = lpart[0];
    l0 += __shfl_xor_sync(0xffffffffu, l0, 1, 4);
    l0 += __shfl_xor_sync(0xffffffffu, l0, 2, 4);
    float l1 = lpart[1];
    l1 += __shfl_xor_sync(0xffffffffu, l1, 1, 4);
    l1 += __shfl_xor_sync(0xffffffffu, l1, 2, 4);
    float inv0 = __fdividef(1.f, l0);
    float inv1 = __fdividef(1.f, l1);

    const int b = bh >> 4, h = bh & 15;
    const int t0 = qt*64 + rowA;
    #pragma unroll
    for (int nt = 0; nt < 8; nt++) {
        int d = nt*8 + 2*t4;
        *(float2*)(g_Y + ((size_t)(b*Tt + t0))*Cc + h*64 + d) =
            make_float2(accO[nt][0]*inv0, accO[nt][1]*inv0);
        *(float2*)(g_Y + ((size_t)(b*Tt + t0 + 8))*Cc + h*64 + d) =
            make_float2(accO[nt][2]*inv1, accO[nt][3]*inv1);
    }
}

// ---------------------------------------------------------------------------
extern "C" void kernel_launch(void* const* d_in, const int* in_sizes, int n_in,
                              void* d_out, int out_size)
{
    (void)in_sizes; (void)n_in; (void)out_size;
    const float* x      = (const float*)d_in[0];
    const float* W_attn = (const float*)d_in[1];
    const float* W_proj = (const float*)d_in[2];
    float* out = (float*)d_out;

    cudaFuncSetAttribute(attn_mma_kernel,
                         cudaFuncAttributeMaxDynamicSharedMemorySize, ATTN_SMEM_BYTES);
    cudaFuncSetAttribute(gemm_mma_kernel<true>,
                         cudaFuncAttributeMaxDynamicSharedMemorySize, GSMEM_BYTES);
    cudaFuncSetAttribute(gemm_mma_kernel<false>,
                         cudaFuncAttributeMaxDynamicSharedMemorySize, GSMEM_BYTES);

    float* dY; cudaGetSymbolAddress((void**)&dY, g_Y);

    gemm_mma_kernel<true><<<dim3(3072/128, MTOT/128), 256, GSMEM_BYTES>>>(x, W_attn, nullptr);
    attn_mma_kernel<<<dim3(Tt/64, BH), 128, ATTN_SMEM_BYTES>>>();
    gemm_mma_kernel<false><<<dim3(Cc/128, MTOT/128), 256, GSMEM_BYTES>>>(dY, W_proj, out);
}

// round 11
// speedup vs baseline: 2.7112x; 1.1964x over previous
#include <cuda_runtime.h>
#include <cuda_bf16.h>
#include <math.h>
#include <cstdint>

#define Bb 2
#define Tt 2048
#define Cc 1024
#define Hh 16
#define Dd 64
#define BH (Bb*Hh)      // 32
#define MTOT (Bb*Tt)    // 4096

// ---- global scratch (allocation-free rule) ----
__device__ __nv_bfloat16 g_Xhi[(size_t)MTOT*Cc],  g_Xlo[(size_t)MTOT*Cc];
__device__ __nv_bfloat16 g_WAhi[(size_t)3*Cc*Cc], g_WAlo[(size_t)3*Cc*Cc];
__device__ __nv_bfloat16 g_WPhi[(size_t)Cc*Cc],   g_WPlo[(size_t)Cc*Cc];
__device__ __nv_bfloat16 g_Qhi[(size_t)BH*Tt*Dd], g_Qlo[(size_t)BH*Tt*Dd];
__device__ __nv_bfloat16 g_Khi[(size_t)BH*Tt*Dd], g_Klo[(size_t)BH*Tt*Dd];
__device__ float         g_V  [(size_t)BH*Tt*Dd];
__device__ __nv_bfloat16 g_Yhi[(size_t)MTOT*Cc],  g_Ylo[(size_t)MTOT*Cc];

__device__ __forceinline__ float tf32r(float a) {
    uint32_t r; asm("cvt.rna.tf32.f32 %0, %1;" : "=r"(r) : "f"(a));
    return __uint_as_float(r);
}
__device__ __forceinline__ uint32_t fas(float a) { return __float_as_uint(a); }

// pack (e0, e1) -> bf16x2 (lo half = e0)
__device__ __forceinline__ uint32_t pack_bf(float e0, float e1) {
    uint32_t r;
    asm("cvt.rn.bf16x2.f32 %0, %1, %2;" : "=r"(r) : "f"(e1), "f"(e0));
    return r;
}
__device__ __forceinline__ void bsplit2(float2 x, uint32_t& h, uint32_t& l) {
    h = pack_bf(x.x, x.y);
    float h0 = __uint_as_float(h << 16);
    float h1 = __uint_as_float(h & 0xffff0000u);
    l = pack_bf(x.x - h0, x.y - h1);
}

__device__ __forceinline__ void mma8(float c[4],
    uint32_t a0, uint32_t a1, uint32_t a2, uint32_t a3,
    uint32_t b0, uint32_t b1)
{
    asm volatile(
        "mma.sync.aligned.m16n8k8.row.col.f32.tf32.tf32.f32 "
        "{%0,%1,%2,%3}, {%4,%5,%6,%7}, {%8,%9}, {%0,%1,%2,%3};"
        : "+f"(c[0]), "+f"(c[1]), "+f"(c[2]), "+f"(c[3])
        : "r"(a0), "r"(a1), "r"(a2), "r"(a3), "r"(b0), "r"(b1));
}
__device__ __forceinline__ void mma16(float c[4],
    uint32_t a0, uint32_t a1, uint32_t a2, uint32_t a3,
    uint32_t b0, uint32_t b1)
{
    asm volatile(
        "mma.sync.aligned.m16n8k16.row.col.f32.bf16.bf16.f32 "
        "{%0,%1,%2,%3}, {%4,%5,%6,%7}, {%8,%9}, {%0,%1,%2,%3};"
        : "+f"(c[0]), "+f"(c[1]), "+f"(c[2]), "+f"(c[3])
        : "r"(a0), "r"(a1), "r"(a2), "r"(a3), "r"(b0), "r"(b1));
}

__device__ __forceinline__ void cpasync16(uint32_t dst, const void* src) {
    asm volatile("cp.async.cg.shared.global [%0], [%1], 16;" :: "r"(dst), "l"(src));
}
#define CP_COMMIT() asm volatile("cp.async.commit_group;" ::: "memory")
#define CP_WAIT0()  asm volatile("cp.async.wait_group 0;" ::: "memory")

// ===========================================================================
// split_kernel: fp32 -> bf16 hi/lo pair (vectorized by float4)
// ===========================================================================
__global__ __launch_bounds__(256) void split_kernel(
    const float4* __restrict__ src, uint32_t* __restrict__ hi,
    uint32_t* __restrict__ lo, int n4)
{
    int i = blockIdx.x * 256 + threadIdx.x;
    if (i >= n4) return;
    float4 v = src[i];
    uint32_t h0, l0, h1, l1;
    bsplit2(make_float2(v.x, v.y), h0, l0);
    bsplit2(make_float2(v.z, v.w), h1, l1);
    hi[2*i] = h0; hi[2*i+1] = h1;
    lo[2*i] = l0; lo[2*i+1] = l1;
}

// ===========================================================================
// 3x-bf16 GEMM, pre-split bf16 hi/lo inputs, zero consume-side conversion.
// CTA 128x128, BK=32, 8 warps, double-buffered cp.async, 2 CTAs/SM.
// ===========================================================================
#define GSTRB 40                    // bf16 row stride (80 B) - conflict-free
#define GPIECE_B (128*GSTRB*2)      // piece bytes = 10240
#define GSTAGE_B (4*GPIECE_B)       // Ahi|Alo|Bhi|Blo = 40960
#define GSMEM_BYTES (2*GSTAGE_B)    // 81920

template<bool SCATTER>
__global__ __launch_bounds__(256, 2) void gemm_bf_kernel(
    const __nv_bfloat16* __restrict__ Ahi, const __nv_bfloat16* __restrict__ Alo,
    const __nv_bfloat16* __restrict__ Bhi, const __nv_bfloat16* __restrict__ Blo,
    float* __restrict__ outp)
{
    extern __shared__ char smc[];
    const uint32_t sbase = (uint32_t)__cvta_generic_to_shared(smc);
    const int tid = threadIdx.x;
    const int wid = tid >> 5, lid = tid & 31;
    const int g = lid >> 2, t4 = lid & 3;
    const int wm = wid & 1, wn = wid >> 1;     // warp tile 64(m) x 32(n)
    const int bm = blockIdx.y * 128;
    const int bn = blockIdx.x * 128;

    const __nv_bfloat16* gp[4] = {
        Ahi + (size_t)bm * Cc, Alo + (size_t)bm * Cc,
        Bhi + (size_t)bn * Cc, Blo + (size_t)bn * Cc };

    float acc[4][4][4];
    #pragma unroll
    for (int i = 0; i < 4; i++)
        #pragma unroll
        for (int j = 0; j < 4; j++)
            #pragma unroll
            for (int r = 0; r < 4; r++) acc[i][j][r] = 0.f;

    auto load_chunk = [&](int kc, int s) {
        uint32_t base = sbase + (uint32_t)(s * GSTAGE_B);
        #pragma unroll
        for (int t = 0; t < 8; t++) {
            int idx = tid + t * 256;           // 0..2047
            int piece = idx >> 9;
            int rem = idx & 511;
            int row = rem >> 2, q16 = rem & 3; // 16B unit = 8 bf16
            cpasync16(base + (uint32_t)(piece * GPIECE_B + row * (GSTRB*2) + q16 * 16),
                      gp[piece] + (size_t)row * Cc + kc * 32 + q16 * 8);
        }
        CP_COMMIT();
    };

    load_chunk(0, 0);
    CP_WAIT0();
    __syncthreads();

    #pragma unroll 1
    for (int kc = 0; kc < 32; kc++) {
        if (kc < 31) load_chunk(kc + 1, (kc + 1) & 1);

        const char* sAh = smc + (kc & 1) * GSTAGE_B;
        const char* sAl = sAh + GPIECE_B;
        const char* sBh = sAh + 2 * GPIECE_B;
        const char* sBl = sAh + 3 * GPIECE_B;
        #pragma unroll
        for (int kh = 0; kh < 2; kh++) {
            const int kb = kh * 32 + 4 * t4;   // byte offset of this thread's k-pair
            uint32_t ah[4][4], al[4][4];
            #pragma unroll
            for (int mt = 0; mt < 4; mt++) {
                const int rb = (wm*64 + mt*16 + g) * (GSTRB*2) + kb;
                ah[mt][0] = *(const uint32_t*)(sAh + rb);
                ah[mt][1] = *(const uint32_t*)(sAh + rb + 8*(GSTRB*2));
                ah[mt][2] = *(const uint32_t*)(sAh + rb + 16);
                ah[mt][3] = *(const uint32_t*)(sAh + rb + 8*(GSTRB*2) + 16);
                al[mt][0] = *(const uint32_t*)(sAl + rb);
                al[mt][1] = *(const uint32_t*)(sAl + rb + 8*(GSTRB*2));
                al[mt][2] = *(const uint32_t*)(sAl + rb + 16);
                al[mt][3] = *(const uint32_t*)(sAl + rb + 8*(GSTRB*2) + 16);
            }
            #pragma unroll
            for (int nt = 0; nt < 4; nt++) {
                const int rb = (wn*32 + nt*8 + g) * (GSTRB*2) + kb;
                uint32_t bh0 = *(const uint32_t*)(sBh + rb);
                uint32_t bh1 = *(const uint32_t*)(sBh + rb + 16);
                uint32_t bl0 = *(const uint32_t*)(sBl + rb);
                uint32_t bl1 = *(const uint32_t*)(sBl + rb + 16);
                #pragma unroll
                for (int mt = 0; mt < 4; mt++) {
                    mma16(acc[mt][nt], ah[mt][0], ah[mt][1], ah[mt][2], ah[mt][3], bh0, bh1);
                    mma16(acc[mt][nt], ah[mt][0], ah[mt][1], ah[mt][2], ah[mt][3], bl0, bl1);
                    mma16(acc[mt][nt], al[mt][0], al[mt][1], al[mt][2], al[mt][3], bh0, bh1);
                }
            }
        }

        if (kc < 31) CP_WAIT0();
        __syncthreads();
    }

    #pragma unroll
    for (int mt = 0; mt < 4; mt++) {
        #pragma unroll
        for (int nt = 0; nt < 4; nt++) {
            int m0 = bm + wm*64 + mt*16 + g;
            int n  = bn + wn*32 + nt*8 + 2*t4;
            if (SCATTER) {
                int which = n >> 10;            // 0=q 1=k 2=v
                int rem = n & 1023;
                int h = rem >> 6, d = rem & 63;
                int bb0 = m0 >> 11, t0 = m0 & 2047;
                int m1 = m0 + 8;
                int bb1 = m1 >> 11, t1 = m1 & 2047;
                size_t i0 = ((size_t)(bb0*Hh + h)*Tt + t0)*Dd + d;
                size_t i1 = ((size_t)(bb1*Hh + h)*Tt + t1)*Dd + d;
                if (which == 2) {
                    *(float2*)(g_V + i0) = make_float2(acc[mt][nt][0], acc[mt][nt][1]);
                    *(float2*)(g_V + i1) = make_float2(acc[mt][nt][2], acc[mt][nt][3]);
                } else {
                    float sc = (which == 0) ? 0.125f : 1.0f;
                    __nv_bfloat16* dh = (which == 0) ? g_Qhi : g_Khi;
                    __nv_bfloat16* dl = (which == 0) ? g_Qlo : g_Klo;
                    uint32_t hh, ll;
                    bsplit2(make_float2(acc[mt][nt][0]*sc, acc[mt][nt][1]*sc), hh, ll);
                    *(uint32_t*)(dh + i0) = hh; *(uint32_t*)(dl + i0) = ll;
                    bsplit2(make_float2(acc[mt][nt][2]*sc, acc[mt][nt][3]*sc), hh, ll);
                    *(uint32_t*)(dh + i1) = hh; *(uint32_t*)(dl + i1) = ll;
                }
            } else {
                *(float2*)(outp + (size_t)m0 * Cc + n) =
                    make_float2(acc[mt][nt][0], acc[mt][nt][1]);
                *(float2*)(outp + (size_t)(m0 + 8) * Cc + n) =
                    make_float2(acc[mt][nt][2], acc[mt][nt][3]);
            }
        }
    }
}

// ===========================================================================
// Attention: pre-split bf16 Q/K (hi/lo), fp32 V. QK = 3x-bf16 mma16 with bare
// LDS fragment loads; AV = single-pass tf32. k-tiles DECREASING (suffix scan).
// ===========================================================================
#define QKSTR 144                   // Q/K bf16 piece row stride in bytes
#define AQHI 0
#define AQLO 9216
#define AST0 18432
#define AKPC 9216                   // one K piece (64*144)
#define AVOFF (2*AKPC)              // V offset inside stage = 18432
#define ASTG (2*AKPC + 64*288)      // stage = 36864
#define AWOFFB (AST0 + 2*ASTG)      // 92160
#define ATTN_SMEM_BYTES (AWOFFB + 4*16*68*4)   // 109568
#define ASTRW 68

__global__ __launch_bounds__(128) void attn_mma_kernel()
{
    extern __shared__ char smc[];
    const uint32_t sbase = (uint32_t)__cvta_generic_to_shared(smc);
    const int tid  = threadIdx.x;
    const int warp = tid >> 5, lane = tid & 31;
    const int g = lane >> 2, t4 = lane & 3;
    const int qt = blockIdx.x, bh = blockIdx.y;

    float* Ws = (float*)(smc + AWOFFB) + warp * (16 * ASTRW);
    const int rowA = warp * 16 + g;
    const size_t qbase = ((size_t)bh * Tt + (size_t)qt * 64) * Dd;

    // ---- Q tile: cp.async bf16 hi/lo (already scaled by 1/8) ----
    {
        #pragma unroll
        for (int t = 0; t < 8; t++) {
            int idx = tid + t * 128;           // 0..1023
            int piece = idx >> 9;
            int rem = idx & 511;
            int row = rem >> 3, q16 = rem & 7;
            const __nv_bfloat16* src = (piece ? g_Qlo : g_Qhi) + qbase + row*64 + q16*8;
            cpasync16(sbase + (uint32_t)((piece ? AQLO : AQHI) + row*QKSTR + q16*16), src);
        }
        CP_COMMIT();
    }

    auto prefetch = [&](int kt, int s) {
        const size_t kbase = ((size_t)bh * Tt + (size_t)kt * 64) * Dd;
        uint32_t base = sbase + (uint32_t)(AST0 + s * ASTG);
        #pragma unroll
        for (int t = 0; t < 8; t++) {          // K hi/lo
            int idx = tid + t * 128;
            int piece = idx >> 9;
            int rem = idx & 511;
            int row = rem >> 3, q16 = rem & 7;
            const __nv_bfloat16* src = (piece ? g_Klo : g_Khi) + kbase + row*64 + q16*8;
            cpasync16(base + (uint32_t)(piece*AKPC + row*QKSTR + q16*16), src);
        }
        #pragma unroll
        for (int t = 0; t < 8; t++) {          // V fp32
            int idx = tid + t * 128;
            int row = idx >> 4, q16 = idx & 15;
            cpasync16(base + (uint32_t)(AVOFF + row*288 + q16*16),
                      g_V + kbase + row*64 + q16*4);
        }
        CP_COMMIT();
    };

    float accO[8][4];
    #pragma unroll
    for (int nt = 0; nt < 8; nt++)
        #pragma unroll
        for (int c = 0; c < 4; c++) accO[nt][c] = 0.f;
    float lpart[2] = {0.f, 0.f};
    float zcarry[2] = {0.f, 0.f};

    prefetch(qt, 0);
    CP_WAIT0();
    __syncthreads();

    int par = 0;
    #pragma unroll 1
    for (int kt = qt; kt >= 0; --kt) {
        if (kt > 0) prefetch(kt - 1, par ^ 1);

        const char* Kh = smc + AST0 + par * ASTG;
        const char* Kl = Kh + AKPC;
        const float* Vs = (const float*)(Kh + AVOFF);

        // ---- QK: 3x-bf16 m16n8k16, bare LDS fragments ----
        float accP[8][4];
        #pragma unroll
        for (int nt = 0; nt < 8; nt++)
            #pragma unroll
            for (int c = 0; c < 4; c++) accP[nt][c] = 0.f;

        #pragma unroll
        for (int kh = 0; kh < 4; kh++) {
            const int kb = kh * 32 + 4 * t4;
            const int rb = rowA * QKSTR + kb;
            uint32_t ah0 = *(const uint32_t*)(smc + AQHI + rb);
            uint32_t ah1 = *(const uint32_t*)(smc + AQHI + rb + 8*QKSTR);
            uint32_t ah2 = *(const uint32_t*)(smc + AQHI + rb + 16);
            uint32_t ah3 = *(const uint32_t*)(smc + AQHI + rb + 8*QKSTR + 16);
            uint32_t al0 = *(const uint32_t*)(smc + AQLO + rb);
            uint32_t al1 = *(const uint32_t*)(smc + AQLO + rb + 8*QKSTR);
            uint32_t al2 = *(const uint32_t*)(smc + AQLO + rb + 16);
            uint32_t al3 = *(const uint32_t*)(smc + AQLO + rb + 8*QKSTR + 16);
            #pragma unroll
            for (int nt = 0; nt < 8; nt++) {
                const int nb = (nt*8 + g) * QKSTR + kb;
                uint32_t bh0 = *(const uint32_t*)(Kh + nb);
                uint32_t bh1 = *(const uint32_t*)(Kh + nb + 16);
                uint32_t bl0 = *(const uint32_t*)(Kl + nb);
                uint32_t bl1 = *(const uint32_t*)(Kl + nb + 16);
                mma16(accP[nt], ah0, ah1, ah2, ah3, bh0, bh1);
                mma16(accP[nt], ah0, ah1, ah2, ah3, bl0, bl1);
                mma16(accP[nt], al0, al1, al2, al3, bh0, bh1);
            }
        }

        // ---- softmax with sigmoid suffix-cumsum penalty ----
        const bool diagt = (kt == qt);
        float s[8][4];
        #pragma unroll
        for (int nt = 0; nt < 8; nt++) {
            #pragma unroll
            for (int c = 0; c < 4; c++) {
                int row = rowA + (c >> 1) * 8;
                int col = nt*8 + 2*t4 + (c & 1);
                float pv = accP[nt][c];
                if (diagt && col > row) pv = -1e30f;
                accP[nt][c] = pv;
                float t = __expf(-pv);
                s[nt][c] = __fdividef(1.f, 1.f + t);
            }
        }

        float w[8][4];
        #pragma unroll
        for (int half = 0; half < 2; half++) {
            float pairs[8], incl[8], tot[8];
            #pragma unroll
            for (int nt = 0; nt < 8; nt++) {
                float x = s[nt][half*2] + s[nt][half*2+1];
                pairs[nt] = x;
                float y = __shfl_down_sync(0xffffffffu, x, 1, 4);
                if (t4 < 3) x += y;
                y = __shfl_down_sync(0xffffffffu, x, 2, 4);
                if (t4 < 2) x += y;
                incl[nt] = x;
                tot[nt]  = __shfl_sync(0xffffffffu, x, 0, 4);
            }
            float after = 0.f;
            float zc = zcarry[half];
            float lp = 0.f;
            #pragma unroll
            for (int nt = 7; nt >= 0; nt--) {
                float zbase = zc + after + (incl[nt] - pairs[nt]);
                float z1 = s[nt][half*2+1] + zbase;
                float z0 = s[nt][half*2]   + z1;
                float w0 = __expf(accP[nt][half*2]   - z0);
                float w1 = __expf(accP[nt][half*2+1] - z1);
                lp += w0 + w1;
                w[nt][half*2]   = w0;
                w[nt][half*2+1] = w1;
                after += tot[nt];
            }
            lpart[half] += lp;
            zcarry[half] = zc + after;
        }

        // ---- W -> per-warp smem (tf32), AV mma (tf32) ----
        #pragma unroll
        for (int nt = 0; nt < 8; nt++) {
            *(float2*)(Ws + g*ASTRW + nt*8 + 2*t4) =
                make_float2(tf32r(w[nt][0]), tf32r(w[nt][1]));
            *(float2*)(Ws + (g+8)*ASTRW + nt*8 + 2*t4) =
                make_float2(tf32r(w[nt][2]), tf32r(w[nt][3]));
        }
        __syncwarp();

        #pragma unroll
        for (int ks = 0; ks < 8; ks++) {
            uint32_t a0 = fas(Ws[g*ASTRW + ks*8 + t4]);
            uint32_t a1 = fas(Ws[(g+8)*ASTRW + ks*8 + t4]);
            uint32_t a2 = fas(Ws[g*ASTRW + ks*8 + t4 + 4]);
            uint32_t a3 = fas(Ws[(g+8)*ASTRW + ks*8 + t4 + 4]);
            #pragma unroll
            for (int nt = 0; nt < 8; nt++) {
                float v0 = Vs[(ks*8 + t4)*72 + nt*8 + g];
                float v1 = Vs[(ks*8 + t4 + 4)*72 + nt*8 + g];
                mma8(accO[nt], a0, a1, a2, a3, fas(tf32r(v0)), fas(tf32r(v1)));
            }
        }

        if (kt > 0) CP_WAIT0();
        __syncthreads();
        par ^= 1;
    }

    // ---- epilogue: reduce l, normalize, split to bf16 hi/lo Y ----
    float l0 = lpart[0];
    l0 += __shfl_xor_sync(0xffffffffu, l0, 1, 4);
    l0 += __shfl_xor_sync(0xffffffffu, l0, 2, 4);
    float l1 = lpart[1];
    l1 += __shfl_xor_sync(0xffffffffu, l1, 1, 4);
    l1 += __shfl_xor_sync(0xffffffffu, l1, 2, 4);
    float inv0 = __fdividef(1.f, l0);
    float inv1 = __fdividef(1.f, l1);

    const int b = bh >> 4, h = bh & 15;
    const int t0 = qt*64 + rowA;
    #pragma unroll
    for (int nt = 0; nt < 8; nt++) {
        int d = nt*8 + 2*t4;
        size_t i0 = ((size_t)(b*Tt + t0))*Cc + h*64 + d;
        size_t i1 = ((size_t)(b*Tt + t0 + 8))*Cc + h*64 + d;
        uint32_t hh, ll;
        bsplit2(make_float2(accO[nt][0]*inv0, accO[nt][1]*inv0), hh, ll);
        *(uint32_t*)(g_Yhi + i0) = hh; *(uint32_t*)(g_Ylo + i0) = ll;
        bsplit2(make_float2(accO[nt][2]*inv1, accO[nt][3]*inv1), hh, ll);
        *(uint32_t*)(g_Yhi + i1) = hh; *(uint32_t*)(g_Ylo + i1) = ll;
    }
}

// ---------------------------------------------------------------------------
extern "C" void kernel_launch(void* const* d_in, const int* in_sizes, int n_in,
                              void* d_out, int out_size)
{
    (void)in_sizes; (void)n_in; (void)out_size;
    const float* x      = (const float*)d_in[0];
    const float* W_attn = (const float*)d_in[1];
    const float* W_proj = (const float*)d_in[2];
    float* out = (float*)d_out;

    cudaFuncSetAttribute(attn_mma_kernel,
                         cudaFuncAttributeMaxDynamicSharedMemorySize, ATTN_SMEM_BYTES);
    cudaFuncSetAttribute(gemm_bf_kernel<true>,
                         cudaFuncAttributeMaxDynamicSharedMemorySize, GSMEM_BYTES);
    cudaFuncSetAttribute(gemm_bf_kernel<false>,
                         cudaFuncAttributeMaxDynamicSharedMemorySize, GSMEM_BYTES);

    __nv_bfloat16 *xh, *xl, *wah, *wal, *wph, *wpl, *yh, *yl;
    cudaGetSymbolAddress((void**)&xh,  g_Xhi);  cudaGetSymbolAddress((void**)&xl,  g_Xlo);
    cudaGetSymbolAddress((void**)&wah, g_WAhi); cudaGetSymbolAddress((void**)&wal, g_WAlo);
    cudaGetSymbolAddress((void**)&wph, g_WPhi); cudaGetSymbolAddress((void**)&wpl, g_WPlo);
    cudaGetSymbolAddress((void**)&yh,  g_Yhi);  cudaGetSymbolAddress((void**)&yl,  g_Ylo);

    const int nX  = MTOT*Cc/4, nWA = 3*Cc*Cc/4, nWP = Cc*Cc/4;
    split_kernel<<<(nX  + 255)/256, 256>>>((const float4*)x,      (uint32_t*)xh,  (uint32_t*)xl,  nX);
    split_kernel<<<(nWA + 255)/256, 256>>>((const float4*)W_attn, (uint32_t*)wah, (uint32_t*)wal, nWA);
    split_kernel<<<(nWP + 255)/256, 256>>>((const float4*)W_proj, (uint32_t*)wph, (uint32_t*)wpl, nWP);

    gemm_bf_kernel<true><<<dim3(3072/128, MTOT/128), 256, GSMEM_BYTES>>>(
        xh, xl, wah, wal, nullptr);
    attn_mma_kernel<<<dim3(Tt/64, BH), 128, ATTN_SMEM_BYTES>>>();
    gemm_bf_kernel<false><<<dim3(Cc/128, MTOT/128), 256, GSMEM_BYTES>>>(
        yh, yl, wph, wpl, out);
}

// round 14
// speedup vs baseline: 2.9338x; 1.0821x over previous
#include <cuda_runtime.h>
#include <cuda_bf16.h>
#include <math.h>
#include <cstdint>

#define Bb 2
#define Tt 2048
#define Cc 1024
#define Hh 16
#define Dd 64
#define BH (Bb*Hh)      // 32
#define MTOT (Bb*Tt)    // 4096

// ---- global scratch (allocation-free rule) ----
__device__ __nv_bfloat16 g_Xhi[(size_t)MTOT*Cc],  g_Xlo[(size_t)MTOT*Cc];
__device__ __nv_bfloat16 g_WAhi[(size_t)3*Cc*Cc], g_WAlo[(size_t)3*Cc*Cc];
__device__ __nv_bfloat16 g_WPhi[(size_t)Cc*Cc],   g_WPlo[(size_t)Cc*Cc];
__device__ __nv_bfloat16 g_Qhi[(size_t)BH*Tt*Dd], g_Qlo[(size_t)BH*Tt*Dd];
__device__ __nv_bfloat16 g_Khi[(size_t)BH*Tt*Dd], g_Klo[(size_t)BH*Tt*Dd];
__device__ float         g_V  [(size_t)BH*Tt*Dd];
__device__ __nv_bfloat16 g_Yhi[(size_t)MTOT*Cc],  g_Ylo[(size_t)MTOT*Cc];

__device__ __forceinline__ float tf32r(float a) {
    uint32_t r; asm("cvt.rna.tf32.f32 %0, %1;" : "=r"(r) : "f"(a));
    return __uint_as_float(r);
}
__device__ __forceinline__ uint32_t fas(float a) { return __float_as_uint(a); }

// pack (e0, e1) -> bf16x2 (lo half = e0)
__device__ __forceinline__ uint32_t pack_bf(float e0, float e1) {
    uint32_t r;
    asm("cvt.rn.bf16x2.f32 %0, %1, %2;" : "=r"(r) : "f"(e1), "f"(e0));
    return r;
}
__device__ __forceinline__ void bsplit2(float2 x, uint32_t& h, uint32_t& l) {
    h = pack_bf(x.x, x.y);
    float h0 = __uint_as_float(h << 16);
    float h1 = __uint_as_float(h & 0xffff0000u);
    l = pack_bf(x.x - h0, x.y - h1);
}

__device__ __forceinline__ void mma8(float c[4],
    uint32_t a0, uint32_t a1, uint32_t a2, uint32_t a3,
    uint32_t b0, uint32_t b1)
{
    asm volatile(
        "mma.sync.aligned.m16n8k8.row.col.f32.tf32.tf32.f32 "
        "{%0,%1,%2,%3}, {%4,%5,%6,%7}, {%8,%9}, {%0,%1,%2,%3};"
        : "+f"(c[0]), "+f"(c[1]), "+f"(c[2]), "+f"(c[3])
        : "r"(a0), "r"(a1), "r"(a2), "r"(a3), "r"(b0), "r"(b1));
}
__device__ __forceinline__ void mma16(float c[4],
    uint32_t a0, uint32_t a1, uint32_t a2, uint32_t a3,
    uint32_t b0, uint32_t b1)
{
    asm volatile(
        "mma.sync.aligned.m16n8k16.row.col.f32.bf16.bf16.f32 "
        "{%0,%1,%2,%3}, {%4,%5,%6,%7}, {%8,%9}, {%0,%1,%2,%3};"
        : "+f"(c[0]), "+f"(c[1]), "+f"(c[2]), "+f"(c[3])
        : "r"(a0), "r"(a1), "r"(a2), "r"(a3), "r"(b0), "r"(b1));
}

__device__ __forceinline__ void cpasync16(uint32_t dst, const void* src) {
    asm volatile("cp.async.cg.shared.global [%0], [%1], 16;" :: "r"(dst), "l"(src));
}
#define CP_COMMIT() asm volatile("cp.async.commit_group;" ::: "memory")
#define CP_WAIT0()  asm volatile("cp.async.wait_group 0;" ::: "memory")
#define CP_WAIT1()  asm volatile("cp.async.wait_group 1;" ::: "memory")

// ===========================================================================
// split_kernel: fp32 -> bf16 hi/lo pair (vectorized by float4)
// ===========================================================================
__global__ __launch_bounds__(256) void split_kernel(
    const float4* __restrict__ src, uint32_t* __restrict__ hi,
    uint32_t* __restrict__ lo, int n4)
{
    int i = blockIdx.x * 256 + threadIdx.x;
    if (i >= n4) return;
    float4 v = src[i];
    uint32_t h0, l0, h1, l1;
    bsplit2(make_float2(v.x, v.y), h0, l0);
    bsplit2(make_float2(v.z, v.w), h1, l1);
    hi[2*i] = h0; hi[2*i+1] = h1;
    lo[2*i] = l0; lo[2*i+1] = l1;
}

// ===========================================================================
// 3x-bf16 GEMM: pre-split bf16 hi/lo inputs, 3-stage cp.async ring
// (prefetch distance 2, wait_group 1), XOR-swizzled 64B rows (no padding,
// 16B-aligned cp.async dsts, conflict-free LDS), 2 CTAs/SM.
// ===========================================================================
#define GROWB 64                    // bytes per piece row (32 bf16, NO pad)
#define GPIECE_B (128*GROWB)        // piece bytes = 8192
#define GSTAGE_B (4*GPIECE_B)       // Ahi|Alo|Bhi|Blo = 32768
#define GSMEM_BYTES (3*GSTAGE_B)    // 98304

// swizzled byte offset of logical byte lb (0..63) within piece row `row`
__device__ __forceinline__ int gswz(int row, int lb) {
    return row * GROWB + ((((lb >> 4) ^ (row >> 1)) & 3) << 4) + (lb & 15);
}

template<bool SCATTER>
__global__ __launch_bounds__(256, 2) void gemm_bf_kernel(
    const __nv_bfloat16* __restrict__ Ahi, const __nv_bfloat16* __restrict__ Alo,
    const __nv_bfloat16* __restrict__ Bhi, const __nv_bfloat16* __restrict__ Blo,
    float* __restrict__ outp)
{
    extern __shared__ char smc[];
    const uint32_t sbase = (uint32_t)__cvta_generic_to_shared(smc);
    const int tid = threadIdx.x;
    const int wid = tid >> 5, lid = tid & 31;
    const int g = lid >> 2, t4 = lid & 3;
    const int wm = wid & 1, wn = wid >> 1;     // warp tile 64(m) x 32(n)
    const int bm = blockIdx.y * 128;
    const int bn = blockIdx.x * 128;

    const __nv_bfloat16* gp[4] = {
        Ahi + (size_t)bm * Cc, Alo + (size_t)bm * Cc,
        Bhi + (size_t)bn * Cc, Blo + (size_t)bn * Cc };

    float acc[4][4][4];
    #pragma unroll
    for (int i = 0; i < 4; i++)
        #pragma unroll
        for (int j = 0; j < 4; j++)
            #pragma unroll
            for (int r = 0; r < 4; r++) acc[i][j][r] = 0.f;

    auto load_chunk = [&](int kc, int s) {
        uint32_t base = sbase + (uint32_t)(s * GSTAGE_B);
        #pragma unroll
        for (int t = 0; t < 8; t++) {
            int idx = tid + t * 256;           // 0..2047
            int piece = idx >> 9;
            int rem = idx & 511;
            int row = rem >> 2, c = rem & 3;   // 16B chunk index 0..3
            cpasync16(base + (uint32_t)(piece * GPIECE_B + gswz(row, c << 4)),
                      gp[piece] + (size_t)row * Cc + kc * 32 + c * 8);
        }
        CP_COMMIT();
    };

    load_chunk(0, 0);
    load_chunk(1, 1);

    #pragma unroll 1
    for (int kc = 0; kc < 32; kc++) {
        if (kc < 31) CP_WAIT1(); else CP_WAIT0();   // load(kc) landed
        __syncthreads();
        if (kc + 2 < 32) load_chunk(kc + 2, (kc + 2) % 3);

        const char* sAh = smc + (kc % 3) * GSTAGE_B;
        const char* sAl = sAh + GPIECE_B;
        const char* sBh = sAh + 2 * GPIECE_B;
        const char* sBl = sAh + 3 * GPIECE_B;
        #pragma unroll
        for (int kh = 0; kh < 2; kh++) {
            const int lb0 = kh * 32 + 4 * t4;  // logical byte of this thread's k-pair
            uint32_t ah[4][4], al[4][4];
            #pragma unroll
            for (int mt = 0; mt < 4; mt++) {
                const int r0 = wm*64 + mt*16 + g;
                ah[mt][0] = *(const uint32_t*)(sAh + gswz(r0,     lb0));
                ah[mt][1] = *(const uint32_t*)(sAh + gswz(r0 + 8, lb0));
                ah[mt][2] = *(const uint32_t*)(sAh + gswz(r0,     lb0 + 16));
                ah[mt][3] = *(const uint32_t*)(sAh + gswz(r0 + 8, lb0 + 16));
                al[mt][0] = *(const uint32_t*)(sAl + gswz(r0,     lb0));
                al[mt][1] = *(const uint32_t*)(sAl + gswz(r0 + 8, lb0));
                al[mt][2] = *(const uint32_t*)(sAl + gswz(r0,     lb0 + 16));
                al[mt][3] = *(const uint32_t*)(sAl + gswz(r0 + 8, lb0 + 16));
            }
            #pragma unroll
            for (int nt = 0; nt < 4; nt++) {
                const int r0 = wn*32 + nt*8 + g;
                uint32_t bh0 = *(const uint32_t*)(sBh + gswz(r0, lb0));
                uint32_t bh1 = *(const uint32_t*)(sBh + gswz(r0, lb0 + 16));
                uint32_t bl0 = *(const uint32_t*)(sBl + gswz(r0, lb0));
                uint32_t bl1 = *(const uint32_t*)(sBl + gswz(r0, lb0 + 16));
                #pragma unroll
                for (int mt = 0; mt < 4; mt++) {
                    mma16(acc[mt][nt], ah[mt][0], ah[mt][1], ah[mt][2], ah[mt][3], bh0, bh1);
                    mma16(acc[mt][nt], ah[mt][0], ah[mt][1], ah[mt][2], ah[mt][3], bl0, bl1);
                    mma16(acc[mt][nt], al[mt][0], al[mt][1], al[mt][2], al[mt][3], bh0, bh1);
                }
            }
        }
    }

    #pragma unroll
    for (int mt = 0; mt < 4; mt++) {
        #pragma unroll
        for (int nt = 0; nt < 4; nt++) {
            int m0 = bm + wm*64 + mt*16 + g;
            int n  = bn + wn*32 + nt*8 + 2*t4;
            if (SCATTER) {
                int which = n >> 10;            // 0=q 1=k 2=v
                int rem = n & 1023;
                int h = rem >> 6, d = rem & 63;
                int bb0 = m0 >> 11, t0 = m0 & 2047;
                int m1 = m0 + 8;
                int bb1 = m1 >> 11, t1 = m1 & 2047;
                size_t i0 = ((size_t)(bb0*Hh + h)*Tt + t0)*Dd + d;
                size_t i1 = ((size_t)(bb1*Hh + h)*Tt + t1)*Dd + d;
                if (which == 2) {
                    *(float2*)(g_V + i0) = make_float2(acc[mt][nt][0], acc[mt][nt][1]);
                    *(float2*)(g_V + i1) = make_float2(acc[mt][nt][2], acc[mt][nt][3]);
                } else {
                    float sc = (which == 0) ? 0.125f : 1.0f;
                    __nv_bfloat16* dh = (which == 0) ? g_Qhi : g_Khi;
                    __nv_bfloat16* dl = (which == 0) ? g_Qlo : g_Klo;
                    uint32_t hh, ll;
                    bsplit2(make_float2(acc[mt][nt][0]*sc, acc[mt][nt][1]*sc), hh, ll);
                    *(uint32_t*)(dh + i0) = hh; *(uint32_t*)(dl + i0) = ll;
                    bsplit2(make_float2(acc[mt][nt][2]*sc, acc[mt][nt][3]*sc), hh, ll);
                    *(uint32_t*)(dh + i1) = hh; *(uint32_t*)(dl + i1) = ll;
                }
            } else {
                *(float2*)(outp + (size_t)m0 * Cc + n) =
                    make_float2(acc[mt][nt][0], acc[mt][nt][1]);
                *(float2*)(outp + (size_t)(m0 + 8) * Cc + n) =
                    make_float2(acc[mt][nt][2], acc[mt][nt][3]);
            }
        }
    }
}

// ===========================================================================
// Attention: pre-split bf16 Q/K (hi/lo), fp32 V. QK = 3x-bf16 mma16 with bare
// LDS fragment loads; AV = single-pass tf32. k-tiles DECREASING (suffix scan).
// (byte-identical to the R11 passing version)
// ===========================================================================
#define QKSTR 144                   // Q/K bf16 piece row stride in bytes
#define AQHI 0
#define AQLO 9216
#define AST0 18432
#define AKPC 9216                   // one K piece (64*144)
#define AVOFF (2*AKPC)              // V offset inside stage = 18432
#define ASTG (2*AKPC + 64*288)      // stage = 36864
#define AWOFFB (AST0 + 2*ASTG)      // 92160
#define ATTN_SMEM_BYTES (AWOFFB + 4*16*68*4)   // 109568
#define ASTRW 68

__global__ __launch_bounds__(128) void attn_mma_kernel()
{
    extern __shared__ char smc[];
    const uint32_t sbase = (uint32_t)__cvta_generic_to_shared(smc);
    const int tid  = threadIdx.x;
    const int warp = tid >> 5, lane = tid & 31;
    const int g = lane >> 2, t4 = lane & 3;
    const int qt = blockIdx.x, bh = blockIdx.y;

    float* Ws = (float*)(smc + AWOFFB) + warp * (16 * ASTRW);
    const int rowA = warp * 16 + g;
    const size_t qbase = ((size_t)bh * Tt + (size_t)qt * 64) * Dd;

    // ---- Q tile: cp.async bf16 hi/lo (already scaled by 1/8) ----
    {
        #pragma unroll
        for (int t = 0; t < 8; t++) {
            int idx = tid + t * 128;           // 0..1023
            int piece = idx >> 9;
            int rem = idx & 511;
            int row = rem >> 3, q16 = rem & 7;
            const __nv_bfloat16* src = (piece ? g_Qlo : g_Qhi) + qbase + row*64 + q16*8;
            cpasync16(sbase + (uint32_t)((piece ? AQLO : AQHI) + row*QKSTR + q16*16), src);
        }
        CP_COMMIT();
    }

    auto prefetch = [&](int kt, int s) {
        const size_t kbase = ((size_t)bh * Tt + (size_t)kt * 64) * Dd;
        uint32_t base = sbase + (uint32_t)(AST0 + s * ASTG);
        #pragma unroll
        for (int t = 0; t < 8; t++) {          // K hi/lo
            int idx = tid + t * 128;
            int piece = idx >> 9;
            int rem = idx & 511;
            int row = rem >> 3, q16 = rem & 7;
            const __nv_bfloat16* src = (piece ? g_Klo : g_Khi) + kbase + row*64 + q16*8;
            cpasync16(base + (uint32_t)(piece*AKPC + row*QKSTR + q16*16), src);
        }
        #pragma unroll
        for (int t = 0; t < 8; t++) {          // V fp32
            int idx = tid + t * 128;
            int row = idx >> 4, q16 = idx & 15;
            cpasync16(base + (uint32_t)(AVOFF + row*288 + q16*16),
                      g_V + kbase + row*64 + q16*4);
        }
        CP_COMMIT();
    };

    float accO[8][4];
    #pragma unroll
    for (int nt = 0; nt < 8; nt++)
        #pragma unroll
        for (int c = 0; c < 4; c++) accO[nt][c] = 0.f;
    float lpart[2] = {0.f, 0.f};
    float zcarry[2] = {0.f, 0.f};

    prefetch(qt, 0);
    CP_WAIT0();
    __syncthreads();

    int par = 0;
    #pragma unroll 1
    for (int kt = qt; kt >= 0; --kt) {
        if (kt > 0) prefetch(kt - 1, par ^ 1);

        const char* Kh = smc + AST0 + par * ASTG;
        const char* Kl = Kh + AKPC;
        const float* Vs = (const float*)(Kh + AVOFF);

        // ---- QK: 3x-bf16 m16n8k16, bare LDS fragments ----
        float accP[8][4];
        #pragma unroll
        for (int nt = 0; nt < 8; nt++)
            #pragma unroll
            for (int c = 0; c < 4; c++) accP[nt][c] = 0.f;

        #pragma unroll
        for (int kh = 0; kh < 4; kh++) {
            const int kb = kh * 32 + 4 * t4;
            const int rb = rowA * QKSTR + kb;
            uint32_t ah0 = *(const uint32_t*)(smc + AQHI + rb);
            uint32_t ah1 = *(const uint32_t*)(smc + AQHI + rb + 8*QKSTR);
            uint32_t ah2 = *(const uint32_t*)(smc + AQHI + rb + 16);
            uint32_t ah3 = *(const uint32_t*)(smc + AQHI + rb + 8*QKSTR + 16);
            uint32_t al0 = *(const uint32_t*)(smc + AQLO + rb);
            uint32_t al1 = *(const uint32_t*)(smc + AQLO + rb + 8*QKSTR);
            uint32_t al2 = *(const uint32_t*)(smc + AQLO + rb + 16);
            uint32_t al3 = *(const uint32_t*)(smc + AQLO + rb + 8*QKSTR + 16);
            #pragma unroll
            for (int nt = 0; nt < 8; nt++) {
                const int nb = (nt*8 + g) * QKSTR + kb;
                uint32_t bh0 = *(const uint32_t*)(Kh + nb);
                uint32_t bh1 = *(const uint32_t*)(Kh + nb + 16);
                uint32_t bl0 = *(const uint32_t*)(Kl + nb);
                uint32_t bl1 = *(const uint32_t*)(Kl + nb + 16);
                mma16(accP[nt], ah0, ah1, ah2, ah3, bh0, bh1);
                mma16(accP[nt], ah0, ah1, ah2, ah3, bl0, bl1);
                mma16(accP[nt], al0, al1, al2, al3, bh0, bh1);
            }
        }

        // ---- softmax with sigmoid suffix-cumsum penalty ----
        const bool diagt = (kt == qt);
        float s[8][4];
        #pragma unroll
        for (int nt = 0; nt < 8; nt++) {
            #pragma unroll
            for (int c = 0; c < 4; c++) {
                int row = rowA + (c >> 1) * 8;
                int col = nt*8 + 2*t4 + (c & 1);
                float pv = accP[nt][c];
                if (diagt && col > row) pv = -1e30f;
                accP[nt][c] = pv;
                float t = __expf(-pv);
                s[nt][c] = __fdividef(1.f, 1.f + t);
            }
        }

        float w[8][4];
        #pragma unroll
        for (int half = 0; half < 2; half++) {
            float pairs[8], incl[8], tot[8];
            #pragma unroll
            for (int nt = 0; nt < 8; nt++) {
                float x = s[nt][half*2] + s[nt][half*2+1];
                pairs[nt] = x;
                float y = __shfl_down_sync(0xffffffffu, x, 1, 4);
                if (t4 < 3) x += y;
                y = __shfl_down_sync(0xffffffffu, x, 2, 4);
                if (t4 < 2) x += y;
                incl[nt] = x;
                tot[nt]  = __shfl_sync(0xffffffffu, x, 0, 4);
            }
            float after = 0.f;
            float zc = zcarry[half];
            float lp = 0.f;
            #pragma unroll
            for (int nt = 7; nt >= 0; nt--) {
                float zbase = zc + after + (incl[nt] - pairs[nt]);
                float z1 = s[nt][half*2+1] + zbase;
                float z0 = s[nt][half*2]   + z1;
                float w0 = __expf(accP[nt][half*2]   - z0);
                float w1 = __expf(accP[nt][half*2+1] - z1);
                lp += w0 + w1;
                w[nt][half*2]   = w0;
                w[nt][half*2+1] = w1;
                after += tot[nt];
            }
            lpart[half] += lp;
            zcarry[half] = zc + after;
        }

        // ---- W -> per-warp smem (tf32), AV mma (tf32) ----
        #pragma unroll
        for (int nt = 0; nt < 8; nt++) {
            *(float2*)(Ws + g*ASTRW + nt*8 + 2*t4) =
                make_float2(tf32r(w[nt][0]), tf32r(w[nt][1]));
            *(float2*)(Ws + (g+8)*ASTRW + nt*8 + 2*t4) =
                make_float2(tf32r(w[nt][2]), tf32r(w[nt][3]));
        }
        __syncwarp();

        #pragma unroll
        for (int ks = 0; ks < 8; ks++) {
            uint32_t a0 = fas(Ws[g*ASTRW + ks*8 + t4]);
            uint32_t a1 = fas(Ws[(g+8)*ASTRW + ks*8 + t4]);
            uint32_t a2 = fas(Ws[g*ASTRW + ks*8 + t4 + 4]);
            uint32_t a3 = fas(Ws[(g+8)*ASTRW + ks*8 + t4 + 4]);
            #pragma unroll
            for (int nt = 0; nt < 8; nt++) {
                float v0 = Vs[(ks*8 + t4)*72 + nt*8 + g];
                float v1 = Vs[(ks*8 + t4 + 4)*72 + nt*8 + g];
                mma8(accO[nt], a0, a1, a2, a3, fas(tf32r(v0)), fas(tf32r(v1)));
            }
        }

        if (kt > 0) CP_WAIT0();
        __syncthreads();
        par ^= 1;
    }

    // ---- epilogue: reduce l, normalize, split to bf16 hi/lo Y ----
    float l0 = lpart[0];
    l0 += __shfl_xor_sync(0xffffffffu, l0, 1, 4);
    l0 += __shfl_xor_sync(0xffffffffu, l0, 2, 4);
    float l1 = lpart[1];
    l1 += __shfl_xor_sync(0xffffffffu, l1, 1, 4);
    l1 += __shfl_xor_sync(0xffffffffu, l1, 2, 4);
    float inv0 = __fdividef(1.f, l0);
    float inv1 = __fdividef(1.f, l1);

    const int b = bh >> 4, h = bh & 15;
    const int t0 = qt*64 + rowA;
    #pragma unroll
    for (int nt = 0; nt < 8; nt++) {
        int d = nt*8 + 2*t4;
        size_t i0 = ((size_t)(b*Tt + t0))*Cc + h*64 + d;
        size_t i1 = ((size_t)(b*Tt + t0 + 8))*Cc + h*64 + d;
        uint32_t hh, ll;
        bsplit2(make_float2(accO[nt][0]*inv0, accO[nt][1]*inv0), hh, ll);
        *(uint32_t*)(g_Yhi + i0) = hh; *(uint32_t*)(g_Ylo + i0) = ll;
        bsplit2(make_float2(accO[nt][2]*inv1, accO[nt][3]*inv1), hh, ll);
        *(uint32_t*)(g_Yhi + i1) = hh; *(uint32_t*)(g_Ylo + i1) = ll;
    }
}

// ---------------------------------------------------------------------------
extern "C" void kernel_launch(void* const* d_in, const int* in_sizes, int n_in,
                              void* d_out, int out_size)
{
    (void)in_sizes; (void)n_in; (void)out_size;
    const float* x      = (const float*)d_in[0];
    const float* W_attn = (const float*)d_in[1];
    const float* W_proj = (const float*)d_in[2];
    float* out = (float*)d_out;

    cudaFuncSetAttribute(attn_mma_kernel,
                         cudaFuncAttributeMaxDynamicSharedMemorySize, ATTN_SMEM_BYTES);
    cudaFuncSetAttribute(gemm_bf_kernel<true>,
                         cudaFuncAttributeMaxDynamicSharedMemorySize, GSMEM_BYTES);
    cudaFuncSetAttribute(gemm_bf_kernel<false>,
                         cudaFuncAttributeMaxDynamicSharedMemorySize, GSMEM_BYTES);

    __nv_bfloat16 *xh, *xl, *wah, *wal, *wph, *wpl, *yh, *yl;
    cudaGetSymbolAddress((void**)&xh,  g_Xhi);  cudaGetSymbolAddress((void**)&xl,  g_Xlo);
    cudaGetSymbolAddress((void**)&wah, g_WAhi); cudaGetSymbolAddress((void**)&wal, g_WAlo);
    cudaGetSymbolAddress((void**)&wph, g_WPhi); cudaGetSymbolAddress((void**)&wpl, g_WPlo);
    cudaGetSymbolAddress((void**)&yh,  g_Yhi);  cudaGetSymbolAddress((void**)&yl,  g_Ylo);

    const int nX  = MTOT*Cc/4, nWA = 3*Cc*Cc/4, nWP = Cc*Cc/4;
    split_kernel<<<(nX  + 255)/256, 256>>>((const float4*)x,      (uint32_t*)xh,  (uint32_t*)xl,  nX);
    split_kernel<<<(nWA + 255)/256, 256>>>((const float4*)W_attn, (uint32_t*)wah, (uint32_t*)wal, nWA);
    split_kernel<<<(nWP + 255)/256, 256>>>((const float4*)W_proj, (uint32_t*)wph, (uint32_t*)wpl, nWP);

    gemm_bf_kernel<true><<<dim3(3072/128, MTOT/128), 256, GSMEM_BYTES>>>(
        xh, xl, wah, wal, nullptr);
    attn_mma_kernel<<<dim3(Tt/64, BH), 128, ATTN_SMEM_BYTES>>>();
    gemm_bf_kernel<false><<<dim3(Cc/128, MTOT/128), 256, GSMEM_BYTES>>>(
        yh, yl, wph, wpl, out);
}

// round 15
// speedup vs baseline: 2.9965x; 1.0214x over previous
#include <cuda_runtime.h>
#include <cuda_bf16.h>
#include <math.h>
#include <cstdint>

#define Bb 2
#define Tt 2048
#define Cc 1024
#define Hh 16
#define Dd 64
#define BH (Bb*Hh)      // 32
#define MTOT (Bb*Tt)    // 4096

// ---- global scratch (allocation-free rule) ----
__device__ __nv_bfloat16 g_Xhi[(size_t)MTOT*Cc],  g_Xlo[(size_t)MTOT*Cc];
__device__ __nv_bfloat16 g_WAhi[(size_t)3*Cc*Cc], g_WAlo[(size_t)3*Cc*Cc];
__device__ __nv_bfloat16 g_WPhi[(size_t)Cc*Cc],   g_WPlo[(size_t)Cc*Cc];
__device__ __nv_bfloat16 g_Qhi[(size_t)BH*Tt*Dd], g_Qlo[(size_t)BH*Tt*Dd];
__device__ __nv_bfloat16 g_Khi[(size_t)BH*Tt*Dd], g_Klo[(size_t)BH*Tt*Dd];
__device__ float         g_V  [(size_t)BH*Tt*Dd];   // stored tf32-pre-rounded
__device__ __nv_bfloat16 g_Yhi[(size_t)MTOT*Cc],  g_Ylo[(size_t)MTOT*Cc];

__device__ __forceinline__ float tf32r(float a) {
    uint32_t r; asm("cvt.rna.tf32.f32 %0, %1;" : "=r"(r) : "f"(a));
    return __uint_as_float(r);
}
__device__ __forceinline__ uint32_t fas(float a) { return __float_as_uint(a); }

// pack (e0, e1) -> bf16x2 (lo half = e0)
__device__ __forceinline__ uint32_t pack_bf(float e0, float e1) {
    uint32_t r;
    asm("cvt.rn.bf16x2.f32 %0, %1, %2;" : "=r"(r) : "f"(e1), "f"(e0));
    return r;
}
__device__ __forceinline__ void bsplit2(float2 x, uint32_t& h, uint32_t& l) {
    h = pack_bf(x.x, x.y);
    float h0 = __uint_as_float(h << 16);
    float h1 = __uint_as_float(h & 0xffff0000u);
    l = pack_bf(x.x - h0, x.y - h1);
}

__device__ __forceinline__ void mma8(float c[4],
    uint32_t a0, uint32_t a1, uint32_t a2, uint32_t a3,
    uint32_t b0, uint32_t b1)
{
    asm volatile(
        "mma.sync.aligned.m16n8k8.row.col.f32.tf32.tf32.f32 "
        "{%0,%1,%2,%3}, {%4,%5,%6,%7}, {%8,%9}, {%0,%1,%2,%3};"
        : "+f"(c[0]), "+f"(c[1]), "+f"(c[2]), "+f"(c[3])
        : "r"(a0), "r"(a1), "r"(a2), "r"(a3), "r"(b0), "r"(b1));
}
__device__ __forceinline__ void mma16(float c[4],
    uint32_t a0, uint32_t a1, uint32_t a2, uint32_t a3,
    uint32_t b0, uint32_t b1)
{
    asm volatile(
        "mma.sync.aligned.m16n8k16.row.col.f32.bf16.bf16.f32 "
        "{%0,%1,%2,%3}, {%4,%5,%6,%7}, {%8,%9}, {%0,%1,%2,%3};"
        : "+f"(c[0]), "+f"(c[1]), "+f"(c[2]), "+f"(c[3])
        : "r"(a0), "r"(a1), "r"(a2), "r"(a3), "r"(b0), "r"(b1));
}

__device__ __forceinline__ void cpasync16(uint32_t dst, const void* src) {
    asm volatile("cp.async.cg.shared.global [%0], [%1], 16;" :: "r"(dst), "l"(src));
}
#define CP_COMMIT() asm volatile("cp.async.commit_group;" ::: "memory")
#define CP_WAIT0()  asm volatile("cp.async.wait_group 0;" ::: "memory")
#define CP_WAIT1()  asm volatile("cp.async.wait_group 1;" ::: "memory")

// ===========================================================================
// split_kernel: fp32 -> bf16 hi/lo pair (vectorized by float4)
// ===========================================================================
__global__ __launch_bounds__(256) void split_kernel(
    const float4* __restrict__ src, uint32_t* __restrict__ hi,
    uint32_t* __restrict__ lo, int n4)
{
    int i = blockIdx.x * 256 + threadIdx.x;
    if (i >= n4) return;
    float4 v = src[i];
    uint32_t h0, l0, h1, l1;
    bsplit2(make_float2(v.x, v.y), h0, l0);
    bsplit2(make_float2(v.z, v.w), h1, l1);
    hi[2*i] = h0; hi[2*i+1] = h1;
    lo[2*i] = l0; lo[2*i+1] = l1;
}

// ===========================================================================
// 3x-bf16 GEMM: pre-split bf16 hi/lo inputs, 3-stage cp.async ring
// (prefetch distance 2, wait_group 1), XOR-swizzled 64B rows, 2 CTAs/SM.
// ===========================================================================
#define GROWB 64                    // bytes per piece row (32 bf16, NO pad)
#define GPIECE_B (128*GROWB)        // piece bytes = 8192
#define GSTAGE_B (4*GPIECE_B)       // Ahi|Alo|Bhi|Blo = 32768
#define GSMEM_BYTES (3*GSTAGE_B)    // 98304

// swizzled byte offset of logical byte lb (0..63) within piece row `row`
__device__ __forceinline__ int gswz(int row, int lb) {
    return row * GROWB + ((((lb >> 4) ^ (row >> 1)) & 3) << 4) + (lb & 15);
}

template<bool SCATTER>
__global__ __launch_bounds__(256, 2) void gemm_bf_kernel(
    const __nv_bfloat16* __restrict__ Ahi, const __nv_bfloat16* __restrict__ Alo,
    const __nv_bfloat16* __restrict__ Bhi, const __nv_bfloat16* __restrict__ Blo,
    float* __restrict__ outp)
{
    extern __shared__ char smc[];
    const uint32_t sbase = (uint32_t)__cvta_generic_to_shared(smc);
    const int tid = threadIdx.x;
    const int wid = tid >> 5, lid = tid & 31;
    const int g = lid >> 2, t4 = lid & 3;
    const int wm = wid & 1, wn = wid >> 1;     // warp tile 64(m) x 32(n)
    const int bm = blockIdx.y * 128;
    const int bn = blockIdx.x * 128;

    const __nv_bfloat16* gp[4] = {
        Ahi + (size_t)bm * Cc, Alo + (size_t)bm * Cc,
        Bhi + (size_t)bn * Cc, Blo + (size_t)bn * Cc };

    float acc[4][4][4];
    #pragma unroll
    for (int i = 0; i < 4; i++)
        #pragma unroll
        for (int j = 0; j < 4; j++)
            #pragma unroll
            for (int r = 0; r < 4; r++) acc[i][j][r] = 0.f;

    auto load_chunk = [&](int kc, int s) {
        uint32_t base = sbase + (uint32_t)(s * GSTAGE_B);
        #pragma unroll
        for (int t = 0; t < 8; t++) {
            int idx = tid + t * 256;           // 0..2047
            int piece = idx >> 9;
            int rem = idx & 511;
            int row = rem >> 2, c = rem & 3;   // 16B chunk index 0..3
            cpasync16(base + (uint32_t)(piece * GPIECE_B + gswz(row, c << 4)),
                      gp[piece] + (size_t)row * Cc + kc * 32 + c * 8);
        }
        CP_COMMIT();
    };

    load_chunk(0, 0);
    load_chunk(1, 1);

    #pragma unroll 1
    for (int kc = 0; kc < 32; kc++) {
        if (kc < 31) CP_WAIT1(); else CP_WAIT0();   // load(kc) landed
        __syncthreads();
        if (kc + 2 < 32) load_chunk(kc + 2, (kc + 2) % 3);

        const char* sAh = smc + (kc % 3) * GSTAGE_B;
        const char* sAl = sAh + GPIECE_B;
        const char* sBh = sAh + 2 * GPIECE_B;
        const char* sBl = sAh + 3 * GPIECE_B;
        #pragma unroll
        for (int kh = 0; kh < 2; kh++) {
            const int lb0 = kh * 32 + 4 * t4;  // logical byte of this thread's k-pair
            uint32_t ah[4][4], al[4][4];
            #pragma unroll
            for (int mt = 0; mt < 4; mt++) {
                const int r0 = wm*64 + mt*16 + g;
                ah[mt][0] = *(const uint32_t*)(sAh + gswz(r0,     lb0));
                ah[mt][1] = *(const uint32_t*)(sAh + gswz(r0 + 8, lb0));
                ah[mt][2] = *(const uint32_t*)(sAh + gswz(r0,     lb0 + 16));
                ah[mt][3] = *(const uint32_t*)(sAh + gswz(r0 + 8, lb0 + 16));
                al[mt][0] = *(const uint32_t*)(sAl + gswz(r0,     lb0));
                al[mt][1] = *(const uint32_t*)(sAl + gswz(r0 + 8, lb0));
                al[mt][2] = *(const uint32_t*)(sAl + gswz(r0,     lb0 + 16));
                al[mt][3] = *(const uint32_t*)(sAl + gswz(r0 + 8, lb0 + 16));
            }
            #pragma unroll
            for (int nt = 0; nt < 4; nt++) {
                const int r0 = wn*32 + nt*8 + g;
                uint32_t bh0 = *(const uint32_t*)(sBh + gswz(r0, lb0));
                uint32_t bh1 = *(const uint32_t*)(sBh + gswz(r0, lb0 + 16));
                uint32_t bl0 = *(const uint32_t*)(sBl + gswz(r0, lb0));
                uint32_t bl1 = *(const uint32_t*)(sBl + gswz(r0, lb0 + 16));
                #pragma unroll
                for (int mt = 0; mt < 4; mt++) {
                    mma16(acc[mt][nt], ah[mt][0], ah[mt][1], ah[mt][2], ah[mt][3], bh0, bh1);
                    mma16(acc[mt][nt], ah[mt][0], ah[mt][1], ah[mt][2], ah[mt][3], bl0, bl1);
                    mma16(acc[mt][nt], al[mt][0], al[mt][1], al[mt][2], al[mt][3], bh0, bh1);
                }
            }
        }
    }

    #pragma unroll
    for (int mt = 0; mt < 4; mt++) {
        #pragma unroll
        for (int nt = 0; nt < 4; nt++) {
            int m0 = bm + wm*64 + mt*16 + g;
            int n  = bn + wn*32 + nt*8 + 2*t4;
            if (SCATTER) {
                int which = n >> 10;            // 0=q 1=k 2=v
                int rem = n & 1023;
                int h = rem >> 6, d = rem & 63;
                int bb0 = m0 >> 11, t0 = m0 & 2047;
                int m1 = m0 + 8;
                int bb1 = m1 >> 11, t1 = m1 & 2047;
                size_t i0 = ((size_t)(bb0*Hh + h)*Tt + t0)*Dd + d;
                size_t i1 = ((size_t)(bb1*Hh + h)*Tt + t1)*Dd + d;
                if (which == 2) {
                    // V: pre-round to tf32 so the attention AV loop feeds
                    // bare LDS results into mma8 (zero consume-side cvt).
                    *(float2*)(g_V + i0) =
                        make_float2(tf32r(acc[mt][nt][0]), tf32r(acc[mt][nt][1]));
                    *(float2*)(g_V + i1) =
                        make_float2(tf32r(acc[mt][nt][2]), tf32r(acc[mt][nt][3]));
                } else {
                    float sc = (which == 0) ? 0.125f : 1.0f;
                    __nv_bfloat16* dh = (which == 0) ? g_Qhi : g_Khi;
                    __nv_bfloat16* dl = (which == 0) ? g_Qlo : g_Klo;
                    uint32_t hh, ll;
                    bsplit2(make_float2(acc[mt][nt][0]*sc, acc[mt][nt][1]*sc), hh, ll);
                    *(uint32_t*)(dh + i0) = hh; *(uint32_t*)(dl + i0) = ll;
                    bsplit2(make_float2(acc[mt][nt][2]*sc, acc[mt][nt][3]*sc), hh, ll);
                    *(uint32_t*)(dh + i1) = hh; *(uint32_t*)(dl + i1) = ll;
                }
            } else {
                *(float2*)(outp + (size_t)m0 * Cc + n) =
                    make_float2(acc[mt][nt][0], acc[mt][nt][1]);
                *(float2*)(outp + (size_t)(m0 + 8) * Cc + n) =
                    make_float2(acc[mt][nt][2], acc[mt][nt][3]);
            }
        }
    }
}

// ===========================================================================
// Attention: pre-split bf16 Q/K (hi/lo), tf32-pre-rounded fp32 V.
// QK = 3x-bf16 mma16 bare LDS; AV = single-pass tf32 (no consume-side cvt).
// k-tiles DECREASING (streaming suffix scan).
// ===========================================================================
#define QKSTR 144                   // Q/K bf16 piece row stride in bytes
#define AQHI 0
#define AQLO 9216
#define AST0 18432
#define AKPC 9216                   // one K piece (64*144)
#define AVOFF (2*AKPC)              // V offset inside stage = 18432
#define ASTG (2*AKPC + 64*288)      // stage = 36864
#define AWOFFB (AST0 + 2*ASTG)      // 92160
#define ATTN_SMEM_BYTES (AWOFFB + 4*16*68*4)   // 109568
#define ASTRW 68

__global__ __launch_bounds__(128) void attn_mma_kernel()
{
    extern __shared__ char smc[];
    const uint32_t sbase = (uint32_t)__cvta_generic_to_shared(smc);
    const int tid  = threadIdx.x;
    const int warp = tid >> 5, lane = tid & 31;
    const int g = lane >> 2, t4 = lane & 3;
    const int qt = blockIdx.x, bh = blockIdx.y;

    float* Ws = (float*)(smc + AWOFFB) + warp * (16 * ASTRW);
    const int rowA = warp * 16 + g;
    const size_t qbase = ((size_t)bh * Tt + (size_t)qt * 64) * Dd;

    // ---- Q tile: cp.async bf16 hi/lo (already scaled by 1/8) ----
    {
        #pragma unroll
        for (int t = 0; t < 8; t++) {
            int idx = tid + t * 128;           // 0..1023
            int piece = idx >> 9;
            int rem = idx & 511;
            int row = rem >> 3, q16 = rem & 7;
            const __nv_bfloat16* src = (piece ? g_Qlo : g_Qhi) + qbase + row*64 + q16*8;
            cpasync16(sbase + (uint32_t)((piece ? AQLO : AQHI) + row*QKSTR + q16*16), src);
        }
        CP_COMMIT();
    }

    auto prefetch = [&](int kt, int s) {
        const size_t kbase = ((size_t)bh * Tt + (size_t)kt * 64) * Dd;
        uint32_t base = sbase + (uint32_t)(AST0 + s * ASTG);
        #pragma unroll
        for (int t = 0; t < 8; t++) {          // K hi/lo
            int idx = tid + t * 128;
            int piece = idx >> 9;
            int rem = idx & 511;
            int row = rem >> 3, q16 = rem & 7;
            const __nv_bfloat16* src = (piece ? g_Klo : g_Khi) + kbase + row*64 + q16*8;
            cpasync16(base + (uint32_t)(piece*AKPC + row*QKSTR + q16*16), src);
        }
        #pragma unroll
        for (int t = 0; t < 8; t++) {          // V fp32 (tf32-pre-rounded)
            int idx = tid + t * 128;
            int row = idx >> 4, q16 = idx & 15;
            cpasync16(base + (uint32_t)(AVOFF + row*288 + q16*16),
                      g_V + kbase + row*64 + q16*4);
        }
        CP_COMMIT();
    };

    float accO[8][4];
    #pragma unroll
    for (int nt = 0; nt < 8; nt++)
        #pragma unroll
        for (int c = 0; c < 4; c++) accO[nt][c] = 0.f;
    float lpart[2] = {0.f, 0.f};
    float zcarry[2] = {0.f, 0.f};

    prefetch(qt, 0);
    CP_WAIT0();
    __syncthreads();

    int par = 0;
    #pragma unroll 1
    for (int kt = qt; kt >= 0; --kt) {
        if (kt > 0) prefetch(kt - 1, par ^ 1);

        const char* Kh = smc + AST0 + par * ASTG;
        const char* Kl = Kh + AKPC;
        const float* Vs = (const float*)(Kh + AVOFF);

        // ---- QK: 3x-bf16 m16n8k16, bare LDS fragments ----
        float accP[8][4];
        #pragma unroll
        for (int nt = 0; nt < 8; nt++)
            #pragma unroll
            for (int c = 0; c < 4; c++) accP[nt][c] = 0.f;

        #pragma unroll
        for (int kh = 0; kh < 4; kh++) {
            const int kb = kh * 32 + 4 * t4;
            const int rb = rowA * QKSTR + kb;
            uint32_t ah0 = *(const uint32_t*)(smc + AQHI + rb);
            uint32_t ah1 = *(const uint32_t*)(smc + AQHI + rb + 8*QKSTR);
            uint32_t ah2 = *(const uint32_t*)(smc + AQHI + rb + 16);
            uint32_t ah3 = *(const uint32_t*)(smc + AQHI + rb + 8*QKSTR + 16);
            uint32_t al0 = *(const uint32_t*)(smc + AQLO + rb);
            uint32_t al1 = *(const uint32_t*)(smc + AQLO + rb + 8*QKSTR);
            uint32_t al2 = *(const uint32_t*)(smc + AQLO + rb + 16);
            uint32_t al3 = *(const uint32_t*)(smc + AQLO + rb + 8*QKSTR + 16);
            #pragma unroll
            for (int nt = 0; nt < 8; nt++) {
                const int nb = (nt*8 + g) * QKSTR + kb;
                uint32_t bh0 = *(const uint32_t*)(Kh + nb);
                uint32_t bh1 = *(const uint32_t*)(Kh + nb + 16);
                uint32_t bl0 = *(const uint32_t*)(Kl + nb);
                uint32_t bl1 = *(const uint32_t*)(Kl + nb + 16);
                mma16(accP[nt], ah0, ah1, ah2, ah3, bh0, bh1);
                mma16(accP[nt], ah0, ah1, ah2, ah3, bl0, bl1);
                mma16(accP[nt], al0, al1, al2, al3, bh0, bh1);
            }
        }

        // ---- softmax with sigmoid suffix-cumsum penalty ----
        const bool diagt = (kt == qt);
        float s[8][4];
        #pragma unroll
        for (int nt = 0; nt < 8; nt++) {
            #pragma unroll
            for (int c = 0; c < 4; c++) {
                int row = rowA + (c >> 1) * 8;
                int col = nt*8 + 2*t4 + (c & 1);
                float pv = accP[nt][c];
                if (diagt && col > row) pv = -1e30f;
                accP[nt][c] = pv;
                float t = __expf(-pv);
                s[nt][c] = __fdividef(1.f, 1.f + t);
            }
        }

        float w[8][4];
        #pragma unroll
        for (int half = 0; half < 2; half++) {
            float pairs[8], incl[8], tot[8];
            #pragma unroll
            for (int nt = 0; nt < 8; nt++) {
                float x = s[nt][half*2] + s[nt][half*2+1];
                pairs[nt] = x;
                float y = __shfl_down_sync(0xffffffffu, x, 1, 4);
                if (t4 < 3) x += y;
                y = __shfl_down_sync(0xffffffffu, x, 2, 4);
                if (t4 < 2) x += y;
                incl[nt] = x;
                tot[nt]  = __shfl_sync(0xffffffffu, x, 0, 4);
            }
            float after = 0.f;
            float zc = zcarry[half];
            float lp = 0.f;
            #pragma unroll
            for (int nt = 7; nt >= 0; nt--) {
                float zbase = zc + after + (incl[nt] - pairs[nt]);
                float z1 = s[nt][half*2+1] + zbase;
                float z0 = s[nt][half*2]   + z1;
                float w0 = __expf(accP[nt][half*2]   - z0);
                float w1 = __expf(accP[nt][half*2+1] - z1);
                lp += w0 + w1;
                w[nt][half*2]   = w0;
                w[nt][half*2+1] = w1;
                after += tot[nt];
            }
            lpart[half] += lp;
            zcarry[half] = zc + after;
        }

        // ---- W -> per-warp smem (tf32), AV mma (tf32, bare V loads) ----
        #pragma unroll
        for (int nt = 0; nt < 8; nt++) {
            *(float2*)(Ws + g*ASTRW + nt*8 + 2*t4) =
                make_float2(tf32r(w[nt][0]), tf32r(w[nt][1]));
            *(float2*)(Ws + (g+8)*ASTRW + nt*8 + 2*t4) =
                make_float2(tf32r(w[nt][2]), tf32r(w[nt][3]));
        }
        __syncwarp();

        #pragma unroll
        for (int ks = 0; ks < 8; ks++) {
            uint32_t a0 = fas(Ws[g*ASTRW + ks*8 + t4]);
            uint32_t a1 = fas(Ws[(g+8)*ASTRW + ks*8 + t4]);
            uint32_t a2 = fas(Ws[g*ASTRW + ks*8 + t4 + 4]);
            uint32_t a3 = fas(Ws[(g+8)*ASTRW + ks*8 + t4 + 4]);
            #pragma unroll
            for (int nt = 0; nt < 8; nt++) {
                uint32_t b0 = *(const uint32_t*)&Vs[(ks*8 + t4)*72 + nt*8 + g];
                uint32_t b1 = *(const uint32_t*)&Vs[(ks*8 + t4 + 4)*72 + nt*8 + g];
                mma8(accO[nt], a0, a1, a2, a3, b0, b1);
            }
        }

        if (kt > 0) CP_WAIT0();
        __syncthreads();
        par ^= 1;
    }

    // ---- epilogue: reduce l, normalize, split to bf16 hi/lo Y ----
    float l0 = lpart[0];
    l0 += __shfl_xor_sync(0xffffffffu, l0, 1, 4);
    l0 += __shfl_xor_sync(0xffffffffu, l0, 2, 4);
    float l1 = lpart[1];
    l1 += __shfl_xor_sync(0xffffffffu, l1, 1, 4);
    l1 += __shfl_xor_sync(0xffffffffu, l1, 2, 4);
    float inv0 = __fdividef(1.f, l0);
    float inv1 = __fdividef(1.f, l1);

    const int b = bh >> 4, h = bh & 15;
    const int t0 = qt*64 + rowA;
    #pragma unroll
    for (int nt = 0; nt < 8; nt++) {
        int d = nt*8 + 2*t4;
        size_t i0 = ((size_t)(b*Tt + t0))*Cc + h*64 + d;
        size_t i1 = ((size_t)(b*Tt + t0 + 8))*Cc + h*64 + d;
        uint32_t hh, ll;
        bsplit2(make_float2(accO[nt][0]*inv0, accO[nt][1]*inv0), hh, ll);
        *(uint32_t*)(g_Yhi + i0) = hh; *(uint32_t*)(g_Ylo + i0) = ll;
        bsplit2(make_float2(accO[nt][2]*inv1, accO[nt][3]*inv1), hh, ll);
        *(uint32_t*)(g_Yhi + i1) = hh; *(uint32_t*)(g_Ylo + i1) = ll;
    }
}

// ---------------------------------------------------------------------------
extern "C" void kernel_launch(void* const* d_in, const int* in_sizes, int n_in,
                              void* d_out, int out_size)
{
    (void)in_sizes; (void)n_in; (void)out_size;
    const float* x      = (const float*)d_in[0];
    const float* W_attn = (const float*)d_in[1];
    const float* W_proj = (const float*)d_in[2];
    float* out = (float*)d_out;

    cudaFuncSetAttribute(attn_mma_kernel,
                         cudaFuncAttributeMaxDynamicSharedMemorySize, ATTN_SMEM_BYTES);
    cudaFuncSetAttribute(gemm_bf_kernel<true>,
                         cudaFuncAttributeMaxDynamicSharedMemorySize, GSMEM_BYTES);
    cudaFuncSetAttribute(gemm_bf_kernel<false>,
                         cudaFuncAttributeMaxDynamicSharedMemorySize, GSMEM_BYTES);

    __nv_bfloat16 *xh, *xl, *wah, *wal, *wph, *wpl, *yh, *yl;
    cudaGetSymbolAddress((void**)&xh,  g_Xhi);  cudaGetSymbolAddress((void**)&xl,  g_Xlo);
    cudaGetSymbolAddress((void**)&wah, g_WAhi); cudaGetSymbolAddress((void**)&wal, g_WAlo);
    cudaGetSymbolAddress((void**)&wph, g_WPhi); cudaGetSymbolAddress((void**)&wpl, g_WPlo);
    cudaGetSymbolAddress((void**)&yh,  g_Yhi);  cudaGetSymbolAddress((void**)&yl,  g_Ylo);

    const int nX  = MTOT*Cc/4, nWA = 3*Cc*Cc/4, nWP = Cc*Cc/4;
    split_kernel<<<(nX  + 255)/256, 256>>>((const float4*)x,      (uint32_t*)xh,  (uint32_t*)xl,  nX);
    split_kernel<<<(nWA + 255)/256, 256>>>((const float4*)W_attn, (uint32_t*)wah, (uint32_t*)wal, nWA);
    split_kernel<<<(nWP + 255)/256, 256>>>((const float4*)W_proj, (uint32_t*)wph, (uint32_t*)wpl, nWP);

    gemm_bf_kernel<true><<<dim3(3072/128, MTOT/128), 256, GSMEM_BYTES>>>(
        xh, xl, wah, wal, nullptr);
    attn_mma_kernel<<<dim3(Tt/64, BH), 128, ATTN_SMEM_BYTES>>>();
    gemm_bf_kernel<false><<<dim3(Cc/128, MTOT/128), 256, GSMEM_BYTES>>>(
        yh, yl, wph, wpl, out);
}

// round 16
// speedup vs baseline: 3.1068x; 1.0368x over previous
#include <cuda_runtime.h>
#include <cuda_bf16.h>
#include <math.h>
#include <cstdint>

#define Bb 2
#define Tt 2048
#define Cc 1024
#define Hh 16
#define Dd 64
#define BH (Bb*Hh)      // 32
#define MTOT (Bb*Tt)    // 4096

// ---- global scratch (allocation-free rule) ----
__device__ __nv_bfloat16 g_Xhi[(size_t)MTOT*Cc],  g_Xlo[(size_t)MTOT*Cc];
__device__ __nv_bfloat16 g_WAhi[(size_t)3*Cc*Cc], g_WAlo[(size_t)3*Cc*Cc];
__device__ __nv_bfloat16 g_WPhi[(size_t)Cc*Cc],   g_WPlo[(size_t)Cc*Cc];
__device__ __nv_bfloat16 g_Qhi[(size_t)BH*Tt*Dd], g_Qlo[(size_t)BH*Tt*Dd];
__device__ __nv_bfloat16 g_Khi[(size_t)BH*Tt*Dd], g_Klo[(size_t)BH*Tt*Dd];
__device__ float         g_V  [(size_t)BH*Tt*Dd];   // stored tf32-pre-rounded
__device__ __nv_bfloat16 g_Yhi[(size_t)MTOT*Cc],  g_Ylo[(size_t)MTOT*Cc];

__device__ __forceinline__ float tf32r(float a) {
    uint32_t r; asm("cvt.rna.tf32.f32 %0, %1;" : "=r"(r) : "f"(a));
    return __uint_as_float(r);
}
__device__ __forceinline__ uint32_t fas(float a) { return __float_as_uint(a); }

// pack (e0, e1) -> bf16x2 (lo half = e0)
__device__ __forceinline__ uint32_t pack_bf(float e0, float e1) {
    uint32_t r;
    asm("cvt.rn.bf16x2.f32 %0, %1, %2;" : "=r"(r) : "f"(e1), "f"(e0));
    return r;
}
__device__ __forceinline__ void bsplit2(float2 x, uint32_t& h, uint32_t& l) {
    h = pack_bf(x.x, x.y);
    float h0 = __uint_as_float(h << 16);
    float h1 = __uint_as_float(h & 0xffff0000u);
    l = pack_bf(x.x - h0, x.y - h1);
}

__device__ __forceinline__ void mma8(float c[4],
    uint32_t a0, uint32_t a1, uint32_t a2, uint32_t a3,
    uint32_t b0, uint32_t b1)
{
    asm volatile(
        "mma.sync.aligned.m16n8k8.row.col.f32.tf32.tf32.f32 "
        "{%0,%1,%2,%3}, {%4,%5,%6,%7}, {%8,%9}, {%0,%1,%2,%3};"
        : "+f"(c[0]), "+f"(c[1]), "+f"(c[2]), "+f"(c[3])
        : "r"(a0), "r"(a1), "r"(a2), "r"(a3), "r"(b0), "r"(b1));
}
__device__ __forceinline__ void mma16(float c[4],
    uint32_t a0, uint32_t a1, uint32_t a2, uint32_t a3,
    uint32_t b0, uint32_t b1)
{
    asm volatile(
        "mma.sync.aligned.m16n8k16.row.col.f32.bf16.bf16.f32 "
        "{%0,%1,%2,%3}, {%4,%5,%6,%7}, {%8,%9}, {%0,%1,%2,%3};"
        : "+f"(c[0]), "+f"(c[1]), "+f"(c[2]), "+f"(c[3])
        : "r"(a0), "r"(a1), "r"(a2), "r"(a3), "r"(b0), "r"(b1));
}

// ldmatrix x4: four 8x8 b16 matrices; lanes 0-7/8-15/16-23/24-31 give row addrs
__device__ __forceinline__ void ldsm4(uint32_t& r0, uint32_t& r1,
                                      uint32_t& r2, uint32_t& r3, uint32_t a)
{
    asm volatile("ldmatrix.sync.aligned.m8n8.x4.shared.b16 {%0,%1,%2,%3}, [%4];"
        : "=r"(r0), "=r"(r1), "=r"(r2), "=r"(r3) : "r"(a));
}

__device__ __forceinline__ void cpasync16(uint32_t dst, const void* src) {
    asm volatile("cp.async.cg.shared.global [%0], [%1], 16;" :: "r"(dst), "l"(src));
}
#define CP_COMMIT() asm volatile("cp.async.commit_group;" ::: "memory")
#define CP_WAIT0()  asm volatile("cp.async.wait_group 0;" ::: "memory")
#define CP_WAIT1()  asm volatile("cp.async.wait_group 1;" ::: "memory")

// ===========================================================================
// split_kernel: fp32 -> bf16 hi/lo pair (vectorized by float4)
// ===========================================================================
__global__ __launch_bounds__(256) void split_kernel(
    const float4* __restrict__ src, uint32_t* __restrict__ hi,
    uint32_t* __restrict__ lo, int n4)
{
    int i = blockIdx.x * 256 + threadIdx.x;
    if (i >= n4) return;
    float4 v = src[i];
    uint32_t h0, l0, h1, l1;
    bsplit2(make_float2(v.x, v.y), h0, l0);
    bsplit2(make_float2(v.z, v.w), h1, l1);
    hi[2*i] = h0; hi[2*i+1] = h1;
    lo[2*i] = l0; lo[2*i+1] = l1;
}

// ===========================================================================
// 3x-bf16 GEMM: pre-split bf16 hi/lo inputs, 3-stage cp.async ring
// (prefetch distance 2, wait_group 1), XOR-swizzled 64B rows, 2 CTAs/SM.
// (byte-identical to R15 passing version)
// ===========================================================================
#define GROWB 64                    // bytes per piece row (32 bf16, NO pad)
#define GPIECE_B (128*GROWB)        // piece bytes = 8192
#define GSTAGE_B (4*GPIECE_B)       // Ahi|Alo|Bhi|Blo = 32768
#define GSMEM_BYTES (3*GSTAGE_B)    // 98304

__device__ __forceinline__ int gswz(int row, int lb) {
    return row * GROWB + ((((lb >> 4) ^ (row >> 1)) & 3) << 4) + (lb & 15);
}

template<bool SCATTER>
__global__ __launch_bounds__(256, 2) void gemm_bf_kernel(
    const __nv_bfloat16* __restrict__ Ahi, const __nv_bfloat16* __restrict__ Alo,
    const __nv_bfloat16* __restrict__ Bhi, const __nv_bfloat16* __restrict__ Blo,
    float* __restrict__ outp)
{
    extern __shared__ char smc[];
    const uint32_t sbase = (uint32_t)__cvta_generic_to_shared(smc);
    const int tid = threadIdx.x;
    const int wid = tid >> 5, lid = tid & 31;
    const int g = lid >> 2, t4 = lid & 3;
    const int wm = wid & 1, wn = wid >> 1;     // warp tile 64(m) x 32(n)
    const int bm = blockIdx.y * 128;
    const int bn = blockIdx.x * 128;

    const __nv_bfloat16* gp[4] = {
        Ahi + (size_t)bm * Cc, Alo + (size_t)bm * Cc,
        Bhi + (size_t)bn * Cc, Blo + (size_t)bn * Cc };

    float acc[4][4][4];
    #pragma unroll
    for (int i = 0; i < 4; i++)
        #pragma unroll
        for (int j = 0; j < 4; j++)
            #pragma unroll
            for (int r = 0; r < 4; r++) acc[i][j][r] = 0.f;

    auto load_chunk = [&](int kc, int s) {
        uint32_t base = sbase + (uint32_t)(s * GSTAGE_B);
        #pragma unroll
        for (int t = 0; t < 8; t++) {
            int idx = tid + t * 256;           // 0..2047
            int piece = idx >> 9;
            int rem = idx & 511;
            int row = rem >> 2, c = rem & 3;   // 16B chunk index 0..3
            cpasync16(base + (uint32_t)(piece * GPIECE_B + gswz(row, c << 4)),
                      gp[piece] + (size_t)row * Cc + kc * 32 + c * 8);
        }
        CP_COMMIT();
    };

    load_chunk(0, 0);
    load_chunk(1, 1);

    #pragma unroll 1
    for (int kc = 0; kc < 32; kc++) {
        if (kc < 31) CP_WAIT1(); else CP_WAIT0();   // load(kc) landed
        __syncthreads();
        if (kc + 2 < 32) load_chunk(kc + 2, (kc + 2) % 3);

        const char* sAh = smc + (kc % 3) * GSTAGE_B;
        const char* sAl = sAh + GPIECE_B;
        const char* sBh = sAh + 2 * GPIECE_B;
        const char* sBl = sAh + 3 * GPIECE_B;
        #pragma unroll
        for (int kh = 0; kh < 2; kh++) {
            const int lb0 = kh * 32 + 4 * t4;  // logical byte of this thread's k-pair
            uint32_t ah[4][4], al[4][4];
            #pragma unroll
            for (int mt = 0; mt < 4; mt++) {
                const int r0 = wm*64 + mt*16 + g;
                ah[mt][0] = *(const uint32_t*)(sAh + gswz(r0,     lb0));
                ah[mt][1] = *(const uint32_t*)(sAh + gswz(r0 + 8, lb0));
                ah[mt][2] = *(const uint32_t*)(sAh + gswz(r0,     lb0 + 16));
                ah[mt][3] = *(const uint32_t*)(sAh + gswz(r0 + 8, lb0 + 16));
                al[mt][0] = *(const uint32_t*)(sAl + gswz(r0,     lb0));
                al[mt][1] = *(const uint32_t*)(sAl + gswz(r0 + 8, lb0));
                al[mt][2] = *(const uint32_t*)(sAl + gswz(r0,     lb0 + 16));
                al[mt][3] = *(const uint32_t*)(sAl + gswz(r0 + 8, lb0 + 16));
            }
            #pragma unroll
            for (int nt = 0; nt < 4; nt++) {
                const int r0 = wn*32 + nt*8 + g;
                uint32_t bh0 = *(const uint32_t*)(sBh + gswz(r0, lb0));
                uint32_t bh1 = *(const uint32_t*)(sBh + gswz(r0, lb0 + 16));
                uint32_t bl0 = *(const uint32_t*)(sBl + gswz(r0, lb0));
                uint32_t bl1 = *(const uint32_t*)(sBl + gswz(r0, lb0 + 16));
                #pragma unroll
                for (int mt = 0; mt < 4; mt++) {
                    mma16(acc[mt][nt], ah[mt][0], ah[mt][1], ah[mt][2], ah[mt][3], bh0, bh1);
                    mma16(acc[mt][nt], ah[mt][0], ah[mt][1], ah[mt][2], ah[mt][3], bl0, bl1);
                    mma16(acc[mt][nt], al[mt][0], al[mt][1], al[mt][2], al[mt][3], bh0, bh1);
                }
            }
        }
    }

    #pragma unroll
    for (int mt = 0; mt < 4; mt++) {
        #pragma unroll
        for (int nt = 0; nt < 4; nt++) {
            int m0 = bm + wm*64 + mt*16 + g;
            int n  = bn + wn*32 + nt*8 + 2*t4;
            if (SCATTER) {
                int which = n >> 10;            // 0=q 1=k 2=v
                int rem = n & 1023;
                int h = rem >> 6, d = rem & 63;
                int bb0 = m0 >> 11, t0 = m0 & 2047;
                int m1 = m0 + 8;
                int bb1 = m1 >> 11, t1 = m1 & 2047;
                size_t i0 = ((size_t)(bb0*Hh + h)*Tt + t0)*Dd + d;
                size_t i1 = ((size_t)(bb1*Hh + h)*Tt + t1)*Dd + d;
                if (which == 2) {
                    *(float2*)(g_V + i0) =
                        make_float2(tf32r(acc[mt][nt][0]), tf32r(acc[mt][nt][1]));
                    *(float2*)(g_V + i1) =
                        make_float2(tf32r(acc[mt][nt][2]), tf32r(acc[mt][nt][3]));
                } else {
                    float sc = (which == 0) ? 0.125f : 1.0f;
                    __nv_bfloat16* dh = (which == 0) ? g_Qhi : g_Khi;
                    __nv_bfloat16* dl = (which == 0) ? g_Qlo : g_Klo;
                    uint32_t hh, ll;
                    bsplit2(make_float2(acc[mt][nt][0]*sc, acc[mt][nt][1]*sc), hh, ll);
                    *(uint32_t*)(dh + i0) = hh; *(uint32_t*)(dl + i0) = ll;
                    bsplit2(make_float2(acc[mt][nt][2]*sc, acc[mt][nt][3]*sc), hh, ll);
                    *(uint32_t*)(dh + i1) = hh; *(uint32_t*)(dl + i1) = ll;
                }
            } else {
                *(float2*)(outp + (size_t)m0 * Cc + n) =
                    make_float2(acc[mt][nt][0], acc[mt][nt][1]);
                *(float2*)(outp + (size_t)(m0 + 8) * Cc + n) =
                    make_float2(acc[mt][nt][2], acc[mt][nt][3]);
            }
        }
    }
}

// ===========================================================================
// Attention: pre-split bf16 Q/K (hi/lo), tf32-pre-rounded fp32 V.
// QK = 3x-bf16 mma16 (Q frags hoisted to regs; K frags via ldmatrix.x4);
// AV = single-pass tf32. k-tiles DECREASING (streaming suffix scan).
// LPT: highest-qt blocks launch first.
// ===========================================================================
#define QKSTR 144                   // Q/K bf16 piece row stride in bytes (9*16)
#define AQHI 0
#define AQLO 9216
#define AST0 18432
#define AKPC 9216                   // one K piece (64*144)
#define AVOFF (2*AKPC)              // V offset inside stage = 18432
#define ASTG (2*AKPC + 64*288)      // stage = 36864
#define AWOFFB (AST0 + 2*ASTG)      // 92160
#define ATTN_SMEM_BYTES (AWOFFB + 4*16*68*4)   // 109568
#define ASTRW 68

__global__ __launch_bounds__(128) void attn_mma_kernel()
{
    extern __shared__ char smc[];
    const uint32_t sbase = (uint32_t)__cvta_generic_to_shared(smc);
    const int tid  = threadIdx.x;
    const int warp = tid >> 5, lane = tid & 31;
    const int g = lane >> 2, t4 = lane & 3;
    const int qt = (int)gridDim.x - 1 - (int)blockIdx.x;   // LPT: long blocks first
    const int bh = blockIdx.y;

    float* Ws = (float*)(smc + AWOFFB) + warp * (16 * ASTRW);
    const int rowA = warp * 16 + g;
    const size_t qbase = ((size_t)bh * Tt + (size_t)qt * 64) * Dd;

    // ldmatrix per-lane row-address offset: m = lane>>3 selects
    // (nt-sub, k-half); i = lane&7 selects row within 8.
    const int lsm_off = (((lane >> 4) & 1) * 8 + (lane & 7)) * QKSTR
                      + ((lane >> 3) & 1) * 16;

    // ---- Q tile: cp.async bf16 hi/lo (already scaled by 1/8) ----
    {
        #pragma unroll
        for (int t = 0; t < 8; t++) {
            int idx = tid + t * 128;           // 0..1023
            int piece = idx >> 9;
            int rem = idx & 511;
            int row = rem >> 3, q16 = rem & 7;
            const __nv_bfloat16* src = (piece ? g_Qlo : g_Qhi) + qbase + row*64 + q16*8;
            cpasync16(sbase + (uint32_t)((piece ? AQLO : AQHI) + row*QKSTR + q16*16), src);
        }
        CP_COMMIT();
    }

    auto prefetch = [&](int kt, int s) {
        const size_t kbase = ((size_t)bh * Tt + (size_t)kt * 64) * Dd;
        uint32_t base = sbase + (uint32_t)(AST0 + s * ASTG);
        #pragma unroll
        for (int t = 0; t < 8; t++) {          // K hi/lo
            int idx = tid + t * 128;
            int piece = idx >> 9;
            int rem = idx & 511;
            int row = rem >> 3, q16 = rem & 7;
            const __nv_bfloat16* src = (piece ? g_Klo : g_Khi) + kbase + row*64 + q16*8;
            cpasync16(base + (uint32_t)(piece*AKPC + row*QKSTR + q16*16), src);
        }
        #pragma unroll
        for (int t = 0; t < 8; t++) {          // V fp32 (tf32-pre-rounded)
            int idx = tid + t * 128;
            int row = idx >> 4, q16 = idx & 15;
            cpasync16(base + (uint32_t)(AVOFF + row*288 + q16*16),
                      g_V + kbase + row*64 + q16*4);
        }
        CP_COMMIT();
    };

    float accO[8][4];
    #pragma unroll
    for (int nt = 0; nt < 8; nt++)
        #pragma unroll
        for (int c = 0; c < 4; c++) accO[nt][c] = 0.f;
    float lpart[2] = {0.f, 0.f};
    float zcarry[2] = {0.f, 0.f};

    prefetch(qt, 0);
    CP_WAIT0();
    __syncthreads();

    // ---- hoist Q fragments to registers (constant across all kt tiles) ----
    uint32_t qfh[4][4], qfl[4][4];
    #pragma unroll
    for (int kh = 0; kh < 4; kh++) {
        const int rb = rowA * QKSTR + kh * 32 + 4 * t4;
        qfh[kh][0] = *(const uint32_t*)(smc + AQHI + rb);
        qfh[kh][1] = *(const uint32_t*)(smc + AQHI + rb + 8*QKSTR);
        qfh[kh][2] = *(const uint32_t*)(smc + AQHI + rb + 16);
        qfh[kh][3] = *(const uint32_t*)(smc + AQHI + rb + 8*QKSTR + 16);
        qfl[kh][0] = *(const uint32_t*)(smc + AQLO + rb);
        qfl[kh][1] = *(const uint32_t*)(smc + AQLO + rb + 8*QKSTR);
        qfl[kh][2] = *(const uint32_t*)(smc + AQLO + rb + 16);
        qfl[kh][3] = *(const uint32_t*)(smc + AQLO + rb + 8*QKSTR + 16);
    }

    int par = 0;
    #pragma unroll 1
    for (int kt = qt; kt >= 0; --kt) {
        if (kt > 0) prefetch(kt - 1, par ^ 1);

        const uint32_t kb_u32 = sbase + (uint32_t)(AST0 + par * ASTG);
        const float* Vs = (const float*)(smc + AST0 + par * ASTG + AVOFF);

        // ---- QK: 3x-bf16 m16n8k16; K frags via ldmatrix.x4 ----
        float accP[8][4];
        #pragma unroll
        for (int nt = 0; nt < 8; nt++)
            #pragma unroll
            for (int c = 0; c < 4; c++) accP[nt][c] = 0.f;

        #pragma unroll
        for (int kh = 0; kh < 4; kh++) {
            const uint32_t ka = kb_u32 + (uint32_t)(kh * 32 + lsm_off);
            #pragma unroll
            for (int j = 0; j < 4; j++) {      // nt pair (2j, 2j+1)
                uint32_t h0, h1, h2, h3, l0, l1, l2, l3;
                ldsm4(h0, h1, h2, h3, ka + (uint32_t)(j * (16*QKSTR)));
                ldsm4(l0, l1, l2, l3, ka + (uint32_t)(j * (16*QKSTR) + AKPC));
                mma16(accP[2*j],   qfh[kh][0], qfh[kh][1], qfh[kh][2], qfh[kh][3], h0, h1);
                mma16(accP[2*j],   qfh[kh][0], qfh[kh][1], qfh[kh][2], qfh[kh][3], l0, l1);
                mma16(accP[2*j],   qfl[kh][0], qfl[kh][1], qfl[kh][2], qfl[kh][3], h0, h1);
                mma16(accP[2*j+1], qfh[kh][0], qfh[kh][1], qfh[kh][2], qfh[kh][3], h2, h3);
                mma16(accP[2*j+1], qfh[kh][0], qfh[kh][1], qfh[kh][2], qfh[kh][3], l2, l3);
                mma16(accP[2*j+1], qfl[kh][0], qfl[kh][1], qfl[kh][2], qfl[kh][3], h2, h3);
            }
        }

        // ---- softmax with sigmoid suffix-cumsum penalty ----
        const bool diagt = (kt == qt);
        float s[8][4];
        #pragma unroll
        for (int nt = 0; nt < 8; nt++) {
            #pragma unroll
            for (int c = 0; c < 4; c++) {
                int row = rowA + (c >> 1) * 8;
                int col = nt*8 + 2*t4 + (c & 1);
                float pv = accP[nt][c];
                if (diagt && col > row) pv = -1e30f;
                accP[nt][c] = pv;
                float t = __expf(-pv);
                s[nt][c] = __fdividef(1.f, 1.f + t);
            }
        }

        float w[8][4];
        #pragma unroll
        for (int half = 0; half < 2; half++) {
            float pairs[8], incl[8], tot[8];
            #pragma unroll
            for (int nt = 0; nt < 8; nt++) {
                float x = s[nt][half*2] + s[nt][half*2+1];
                pairs[nt] = x;
                float y = __shfl_down_sync(0xffffffffu, x, 1, 4);
                if (t4 < 3) x += y;
                y = __shfl_down_sync(0xffffffffu, x, 2, 4);
                if (t4 < 2) x += y;
                incl[nt] = x;
                tot[nt]  = __shfl_sync(0xffffffffu, x, 0, 4);
            }
            float after = 0.f;
            float zc = zcarry[half];
            float lp = 0.f;
            #pragma unroll
            for (int nt = 7; nt >= 0; nt--) {
                float zbase = zc + after + (incl[nt] - pairs[nt]);
                float z1 = s[nt][half*2+1] + zbase;
                float z0 = s[nt][half*2]   + z1;
                float w0 = __expf(accP[nt][half*2]   - z0);
                float w1 = __expf(accP[nt][half*2+1] - z1);
                lp += w0 + w1;
                w[nt][half*2]   = w0;
                w[nt][half*2+1] = w1;
                after += tot[nt];
            }
            lpart[half] += lp;
            zcarry[half] = zc + after;
        }

        // ---- W -> per-warp smem (tf32), AV mma (tf32, bare V loads) ----
        #pragma unroll
        for (int nt = 0; nt < 8; nt++) {
            *(float2*)(Ws + g*ASTRW + nt*8 + 2*t4) =
                make_float2(tf32r(w[nt][0]), tf32r(w[nt][1]));
            *(float2*)(Ws + (g+8)*ASTRW + nt*8 + 2*t4) =
                make_float2(tf32r(w[nt][2]), tf32r(w[nt][3]));
        }
        __syncwarp();

        #pragma unroll
        for (int ks = 0; ks < 8; ks++) {
            uint32_t a0 = fas(Ws[g*ASTRW + ks*8 + t4]);
            uint32_t a1 = fas(Ws[(g+8)*ASTRW + ks*8 + t4]);
            uint32_t a2 = fas(Ws[g*ASTRW + ks*8 + t4 + 4]);
            uint32_t a3 = fas(Ws[(g+8)*ASTRW + ks*8 + t4 + 4]);
            #pragma unroll
            for (int nt = 0; nt < 8; nt++) {
                uint32_t b0 = *(const uint32_t*)&Vs[(ks*8 + t4)*72 + nt*8 + g];
                uint32_t b1 = *(const uint32_t*)&Vs[(ks*8 + t4 + 4)*72 + nt*8 + g];
                mma8(accO[nt], a0, a1, a2, a3, b0, b1);
            }
        }

        if (kt > 0) CP_WAIT0();
        __syncthreads();
        par ^= 1;
    }

    // ---- epilogue: reduce l, normalize, split to bf16 hi/lo Y ----
    float l0 = lpart[0];
    l0 += __shfl_xor_sync(0xffffffffu, l0, 1, 4);
    l0 += __shfl_xor_sync(0xffffffffu, l0, 2, 4);
    float l1 = lpart[1];
    l1 += __shfl_xor_sync(0xffffffffu, l1, 1, 4);
    l1 += __shfl_xor_sync(0xffffffffu, l1, 2, 4);
    float inv0 = __fdividef(1.f, l0);
    float inv1 = __fdividef(1.f, l1);

    const int b = bh >> 4, h = bh & 15;
    const int t0 = qt*64 + rowA;
    #pragma unroll
    for (int nt = 0; nt < 8; nt++) {
        int d = nt*8 + 2*t4;
        size_t i0 = ((size_t)(b*Tt + t0))*Cc + h*64 + d;
        size_t i1 = ((size_t)(b*Tt + t0 + 8))*Cc + h*64 + d;
        uint32_t hh, ll;
        bsplit2(make_float2(accO[nt][0]*inv0, accO[nt][1]*inv0), hh, ll);
        *(uint32_t*)(g_Yhi + i0) = hh; *(uint32_t*)(g_Ylo + i0) = ll;
        bsplit2(make_float2(accO[nt][2]*inv1, accO[nt][3]*inv1), hh, ll);
        *(uint32_t*)(g_Yhi + i1) = hh; *(uint32_t*)(g_Ylo + i1) = ll;
    }
}

// ---------------------------------------------------------------------------
extern "C" void kernel_launch(void* const* d_in, const int* in_sizes, int n_in,
                              void* d_out, int out_size)
{
    (void)in_sizes; (void)n_in; (void)out_size;
    const float* x      = (const float*)d_in[0];
    const float* W_attn = (const float*)d_in[1];
    const float* W_proj = (const float*)d_in[2];
    float* out = (float*)d_out;

    cudaFuncSetAttribute(attn_mma_kernel,
                         cudaFuncAttributeMaxDynamicSharedMemorySize, ATTN_SMEM_BYTES);
    cudaFuncSetAttribute(gemm_bf_kernel<true>,
                         cudaFuncAttributeMaxDynamicSharedMemorySize, GSMEM_BYTES);
    cudaFuncSetAttribute(gemm_bf_kernel<false>,
                         cudaFuncAttributeMaxDynamicSharedMemorySize, GSMEM_BYTES);

    __nv_bfloat16 *xh, *xl, *wah, *wal, *wph, *wpl, *yh, *yl;
    cudaGetSymbolAddress((void**)&xh,  g_Xhi);  cudaGetSymbolAddress((void**)&xl,  g_Xlo);
    cudaGetSymbolAddress((void**)&wah, g_WAhi); cudaGetSymbolAddress((void**)&wal, g_WAlo);
    cudaGetSymbolAddress((void**)&wph, g_WPhi); cudaGetSymbolAddress((void**)&wpl, g_WPlo);
    cudaGetSymbolAddress((void**)&yh,  g_Yhi);  cudaGetSymbolAddress((void**)&yl,  g_Ylo);

    const int nX  = MTOT*Cc/4, nWA = 3*Cc*Cc/4, nWP = Cc*Cc/4;
    split_kernel<<<(nX  + 255)/256, 256>>>((const float4*)x,      (uint32_t*)xh,  (uint32_t*)xl,  nX);
    split_kernel<<<(nWA + 255)/256, 256>>>((const float4*)W_attn, (uint32_t*)wah, (uint32_t*)wal, nWA);
    split_kernel<<<(nWP + 255)/256, 256>>>((const float4*)W_proj, (uint32_t*)wph, (uint32_t*)wpl, nWP);

    gemm_bf_kernel<true><<<dim3(3072/128, MTOT/128), 256, GSMEM_BYTES>>>(
        xh, xl, wah, wal, nullptr);
    attn_mma_kernel<<<dim3(Tt/64, BH), 128, ATTN_SMEM_BYTES>>>();
    gemm_bf_kernel<false><<<dim3(Cc/128, MTOT/128), 256, GSMEM_BYTES>>>(
        yh, yl, wph, wpl, out);
}